// round 6
// baseline (speedup 1.0000x reference)
#include <cuda_runtime.h>
#include <math.h>

#define BB 64
#define TT 101
#define TS 100
#define VV 8000
#define HH 512
#define GG 2048
#define MM (TS*BB)   // 6400
#define EPSN 1e-5f

typedef unsigned long long ull;

// ---------------- device scratch (static; no runtime allocation) -------------
__device__ float g_e[MM*HH];                     // [m][h] embedded inputs, m = t*64+b
__device__ float g_Xg1[(size_t)GG*MM];           // [t][n][b] precomputed e@Wih1^T + b1
__device__ float g_Hout[MM*HH];                  // [m][h] layer-3 bn*mask output per step
__device__ float g_logits[(size_t)MM*VV];        // [m][v]
__device__ float g_part[(size_t)3*32*GG*BB];     // [layer][slice][n][b] split-K partials
__device__ float g_h[3*HH*BB];                   // [layer][j][b]
__device__ float g_c[3*HH*BB];                   // [layer][j][b]
__device__ float g_hd[2*HH*BB];                  // [layer][j][b]

// ---------------- f32x2 helpers ----------------------------------------------
__device__ __forceinline__ ull fma2(ull a, ull b, ull c) {
    ull d;
    asm("fma.rn.f32x2 %0, %1, %2, %3;" : "=l"(d) : "l"(a), "l"(b), "l"(c));
    return d;
}
__device__ __forceinline__ ull pack2(float x, float y) {
    ull r;
    asm("mov.b64 %0, {%1, %2};" : "=l"(r) : "f"(x), "f"(y));
    return r;
}
__device__ __forceinline__ ull dup2(float x) {
    ull r;
    asm("mov.b64 %0, {%1, %1};" : "=l"(r) : "f"(x));
    return r;
}
__device__ __forceinline__ float2 unpack2(ull v) {
    float2 r;
    asm("mov.b64 {%0, %1}, %2;" : "=f"(r.x), "=f"(r.y) : "l"(v));
    return r;
}

// ---------------- init: zero states + loss slot ------------------------------
__global__ void k_init(float* out, int hasLoss) {
    int i = blockIdx.x * blockDim.x + threadIdx.x;
    if (i < 3*HH*BB) { g_h[i] = 0.f; g_c[i] = 0.f; }
    if (i == 0 && hasLoss) out[0] = 0.f;
}

// ---------------- embedding gather -------------------------------------------
__global__ void k_embed(const int* x, const float* emb) {
    int i = blockIdx.x * blockDim.x + threadIdx.x;
    if (i >= MM * (HH/4)) return;
    int m  = i / (HH/4);
    int hq = i % (HH/4);
    int t = m / BB, b = m % BB;
    int tok = x[b*TT + t];
    ((float4*)g_e)[(size_t)m*(HH/4) + hq] =
        ((const float4*)emb)[(size_t)tok*(HH/4) + hq];
}

// ---------------- big SGEMM (f32x2): 128x128 tile, pairs along m -------------
// MODE 0: g_Xg1[t][n][b] = g_e @ Wih1^T + b1, N=2048
// MODE 1: g_logits[m][v] = g_Hout @ Wd^T + bd, N=8000
template<int MODE>
__global__ void __launch_bounds__(256) k_gemm_big(const float* __restrict__ Bw,
                                                  const float* __restrict__ bias) {
    const int N = (MODE == 0) ? GG : VV;
    const float* A = (MODE == 0) ? g_e : g_Hout;
    __shared__ __align__(16) float Ast[16][132];
    __shared__ __align__(16) ull   Bst2[16][132];
    int tid = threadIdx.x;
    int mBase = blockIdx.y * 128, nBase = blockIdx.x * 128;
    int lr = tid >> 2, lc = (tid & 3) * 4;
    int m0 = (tid >> 4) * 8, n0 = (tid & 15) * 8;
    ull acc[4][8];
#pragma unroll
    for (int i = 0; i < 4; i++)
#pragma unroll
        for (int j = 0; j < 8; j++) acc[i][j] = 0ull;

    for (int kb = 0; kb < 512; kb += 16) {
        float4 av0 = *(const float4*)&A[(size_t)(mBase + lr)*512 + kb + lc];
        float4 av1 = *(const float4*)&A[(size_t)(mBase + lr + 64)*512 + kb + lc];
        int ng0 = nBase + lr, ng1 = nBase + lr + 64;
        float4 bv0 = make_float4(0.f,0.f,0.f,0.f), bv1 = make_float4(0.f,0.f,0.f,0.f);
        if (ng0 < N) bv0 = *(const float4*)&Bw[(size_t)ng0*512 + kb + lc];
        if (ng1 < N) bv1 = *(const float4*)&Bw[(size_t)ng1*512 + kb + lc];
        __syncthreads();
        Ast[lc+0][lr] = av0.x; Ast[lc+1][lr] = av0.y; Ast[lc+2][lr] = av0.z; Ast[lc+3][lr] = av0.w;
        Ast[lc+0][lr+64] = av1.x; Ast[lc+1][lr+64] = av1.y; Ast[lc+2][lr+64] = av1.z; Ast[lc+3][lr+64] = av1.w;
        Bst2[lc+0][lr] = pack2(bv0.x, bv0.x); Bst2[lc+1][lr] = pack2(bv0.y, bv0.y);
        Bst2[lc+2][lr] = pack2(bv0.z, bv0.z); Bst2[lc+3][lr] = pack2(bv0.w, bv0.w);
        Bst2[lc+0][lr+64] = pack2(bv1.x, bv1.x); Bst2[lc+1][lr+64] = pack2(bv1.y, bv1.y);
        Bst2[lc+2][lr+64] = pack2(bv1.z, bv1.z); Bst2[lc+3][lr+64] = pack2(bv1.w, bv1.w);
        __syncthreads();
#pragma unroll
        for (int kk = 0; kk < 16; kk++) {
            ull a2[4], w2[8];
#pragma unroll
            for (int i = 0; i < 4; i++) a2[i] = *(const ull*)&Ast[kk][m0 + 2*i];
#pragma unroll
            for (int j = 0; j < 8; j++) w2[j] = Bst2[kk][n0 + j];
#pragma unroll
            for (int i = 0; i < 4; i++)
#pragma unroll
                for (int j = 0; j < 8; j++) acc[i][j] = fma2(a2[i], w2[j], acc[i][j]);
        }
    }

    if (MODE == 0) {
#pragma unroll
        for (int j = 0; j < 8; j++) {
            int n = nBase + n0 + j;
            float bb = bias[n];
#pragma unroll
            for (int i = 0; i < 4; i++) {
                int m = mBase + m0 + 2*i;
                float2 v = unpack2(acc[i][j]);
                v.x += bb; v.y += bb;
                int tt = m >> 6, bc = m & 63;
                *(float2*)&g_Xg1[(size_t)tt*(GG*BB) + (size_t)n*BB + bc] = v;
            }
        }
    } else {
#pragma unroll
        for (int i = 0; i < 4; i++) {
            int m = mBase + m0 + 2*i;
#pragma unroll
            for (int j = 0; j < 8; j++) {
                int n = nBase + n0 + j;
                if (n < VV) {
                    float2 v = unpack2(acc[i][j]);
                    float bb = bias[n];
                    g_logits[(size_t)m*VV + n]     = v.x + bb;
                    g_logits[(size_t)(m+1)*VV + n] = v.y + bb;
                }
            }
        }
    }
}

// ---------------- wavefront GEMM: diagonal d = t + l --------------------------
// grid (8 n-tiles, 32 K-slices, 3 layers), block 256 = CTA tile 256n x 64b x 32k.
// Thread tile 8n x 8b (FMA-bound: 64B LDS per 64 MACs).
// Layer 0: K=512 -> 16 slices. Layers 1,2: K=1024 -> 32 slices (16 Wih + 16 Whh).
__global__ void __launch_bounds__(256) k_gemm_wave(int d,
    const float* __restrict__ Whh1,
    const float* __restrict__ Wih2, const float* __restrict__ Whh2,
    const float* __restrict__ Wih3, const float* __restrict__ Whh3)
{
    int l = blockIdx.z;
    int t = d - l;
    if (t < 0 || t >= TS) return;
    int slice = blockIdx.y;
    if (l == 0 && slice >= 16) return;

    const float* A; const float* W;
    if (l == 0) {
        A = g_h + slice*32*BB;
        W = Whh1 + slice*32;
    } else if (slice < 16) {
        A = g_hd + (l-1)*HH*BB + slice*32*BB;
        W = ((l == 1) ? Wih2 : Wih3) + slice*32;
    } else {
        A = g_h + l*HH*BB + (slice-16)*32*BB;
        W = ((l == 1) ? Whh2 : Whh3) + (slice-16)*32;
    }
    int nb = blockIdx.x * 256;
    int tid = threadIdx.x;

    __shared__ __align__(16) float Ast[32*64];    // [k][b] 8KB
    __shared__ __align__(16) float Wst[32*256];   // [k][n] 32KB

    // stage A [32k][64b]: 512 float4, 2 per thread
#pragma unroll
    for (int i = 0; i < 2; i++) {
        int idx = tid + i*256;
        int k = idx >> 4, q = (idx & 15) * 4;
        *(float4*)&Ast[k*64 + q] = *(const float4*)&A[(size_t)k*BB + q];
    }
    // stage W [32k][256n]: thread owns one n row, 8 float4 along k
    {
        const float* wp = W + (size_t)(nb + tid)*HH;
#pragma unroll
        for (int c = 0; c < 32; c += 4) {
            float4 w = *(const float4*)&wp[c];
            Wst[(c+0)*256 + tid] = w.x;
            Wst[(c+1)*256 + tid] = w.y;
            Wst[(c+2)*256 + tid] = w.z;
            Wst[(c+3)*256 + tid] = w.w;
        }
    }
    __syncthreads();

    int b0 = (tid & 7) * 8;      // 8 b (4 ull pairs)
    int n0 = (tid >> 3) * 8;     // 8 n
    ull acc[8][4];
#pragma unroll
    for (int j = 0; j < 8; j++)
#pragma unroll
        for (int i = 0; i < 4; i++) acc[j][i] = 0ull;

#pragma unroll 4
    for (int k = 0; k < 32; k++) {
        ull a2[4];
        *(ulonglong2*)&a2[0] = *(const ulonglong2*)&Ast[k*64 + b0];
        *(ulonglong2*)&a2[2] = *(const ulonglong2*)&Ast[k*64 + b0 + 4];
        float4 w0 = *(const float4*)&Wst[k*256 + n0];
        float4 w1 = *(const float4*)&Wst[k*256 + n0 + 4];
        ull wd[8];
        wd[0] = dup2(w0.x); wd[1] = dup2(w0.y); wd[2] = dup2(w0.z); wd[3] = dup2(w0.w);
        wd[4] = dup2(w1.x); wd[5] = dup2(w1.y); wd[6] = dup2(w1.z); wd[7] = dup2(w1.w);
#pragma unroll
        for (int j = 0; j < 8; j++)
#pragma unroll
            for (int i = 0; i < 4; i++)
                acc[j][i] = fma2(a2[i], wd[j], acc[j][i]);
    }

    float* P = g_part + ((size_t)(l*32 + slice)*GG + nb)*BB;
#pragma unroll
    for (int j = 0; j < 8; j++) {
        ulonglong2 v0; v0.x = acc[j][0]; v0.y = acc[j][1];
        ulonglong2 v1; v1.x = acc[j][2]; v1.y = acc[j][3];
        *(ulonglong2*)&P[(size_t)(n0 + j)*BB + b0]     = v0;
        *(ulonglong2*)&P[(size_t)(n0 + j)*BB + b0 + 4] = v1;
    }
}

// ---------------- wavefront cell: LSTM + BN(train) + locked dropout ----------
// grid (32 j-tiles, 3 layers), block 256 = 16 j x 16 b-quads (float4 along b).
// BN via width-16 shuffles only; no smem, no __syncthreads.
__global__ void __launch_bounds__(256) k_cell_wave(int d,
    const float* __restrict__ b2, const float* __restrict__ b3,
    const float* __restrict__ gm0, const float* __restrict__ bt0, const float* __restrict__ mk0,
    const float* __restrict__ gm1, const float* __restrict__ bt1, const float* __restrict__ mk1,
    const float* __restrict__ gm2, const float* __restrict__ bt2, const float* __restrict__ mk2)
{
    int l = blockIdx.y;
    int t = d - l;
    if (t < 0 || t >= TS) return;
    int tid = threadIdx.x;
    int jl = tid >> 4, bq = tid & 15;
    int j = blockIdx.x * 16 + jl;
    int b0 = bq * 4;
    const float* biasP = (l == 1) ? b2 : b3;
    const float* gmP = (l == 0) ? gm0 : (l == 1) ? gm1 : gm2;
    const float* btP = (l == 0) ? bt0 : (l == 1) ? bt1 : bt2;
    const float* mkP = (l == 0) ? mk0 : (l == 1) ? mk1 : mk2;

    float ga[4][4];   // [gate][b-elem]
#pragma unroll
    for (int g = 0; g < 4; g++) {
        int n = (g << 9) + j;
        float4 s;
        if (l == 0) {
            s = *(const float4*)&g_Xg1[(size_t)t*(GG*BB) + (size_t)n*BB + b0];
        } else {
            float bv = biasP[n];
            s = make_float4(bv, bv, bv, bv);
        }
        const float* pp = g_part + ((size_t)(l*32)*GG + n)*BB + b0;
        if (l == 0) {
#pragma unroll 8
            for (int sl = 0; sl < 16; sl++) {
                float4 v = *(const float4*)(pp + (size_t)sl*(GG*BB));
                s.x += v.x; s.y += v.y; s.z += v.z; s.w += v.w;
            }
        } else {
#pragma unroll 8
            for (int sl = 0; sl < 32; sl++) {
                float4 v = *(const float4*)(pp + (size_t)sl*(GG*BB));
                s.x += v.x; s.y += v.y; s.z += v.z; s.w += v.w;
            }
        }
        ga[g][0] = s.x; ga[g][1] = s.y; ga[g][2] = s.z; ga[g][3] = s.w;
    }

    float* hP = g_h + l*HH*BB + j*BB + b0;
    float* cP = g_c + l*HH*BB + j*BB + b0;
    float4 cprev = *(const float4*)cP;
    float cpv[4] = {cprev.x, cprev.y, cprev.z, cprev.w};
    float hh[4], ccv[4];
#pragma unroll
    for (int e = 0; e < 4; e++) {
        float iv = 1.f / (1.f + expf(-ga[0][e]));
        float fv = 1.f / (1.f + expf(-ga[1][e]));
        float gv = tanhf(ga[2][e]);
        float ov = 1.f / (1.f + expf(-ga[3][e]));
        float cc = fv * cpv[e] + iv * gv;
        ccv[e] = cc;
        hh[e] = ov * tanhf(cc);
    }
    *(float4*)cP = make_float4(ccv[0], ccv[1], ccv[2], ccv[3]);
    *(float4*)hP = make_float4(hh[0], hh[1], hh[2], hh[3]);

    // BN over batch: 16 threads x 4 elems per feature j (width-16 shuffle tree)
    float sum = hh[0] + hh[1] + hh[2] + hh[3];
    float sq  = hh[0]*hh[0] + hh[1]*hh[1] + hh[2]*hh[2] + hh[3]*hh[3];
#pragma unroll
    for (int o = 8; o; o >>= 1) {
        sum += __shfl_down_sync(0xffffffffu, sum, o, 16);
        sq  += __shfl_down_sync(0xffffffffu, sq,  o, 16);
    }
    sum = __shfl_sync(0xffffffffu, sum, 0, 16);
    sq  = __shfl_sync(0xffffffffu, sq,  0, 16);
    float mu  = sum * (1.f / BB);
    float var = sq  * (1.f / BB) - mu * mu;
    float rs  = rsqrtf(var + EPSN);
    float gmv = gmP[j], btv = btP[j];

    if (l < 2) {
        float hd[4];
#pragma unroll
        for (int e = 0; e < 4; e++)
            hd[e] = (gmv * (hh[e] - mu) * rs + btv) * mkP[(b0+e)*HH + j];
        *(float4*)&g_hd[l*HH*BB + j*BB + b0] = make_float4(hd[0], hd[1], hd[2], hd[3]);
    } else {
#pragma unroll
        for (int e = 0; e < 4; e++) {
            float hd = (gmv * (hh[e] - mu) * rs + btv) * mkP[(b0+e)*HH + j];
            g_Hout[((size_t)t*BB + b0 + e)*HH + j] = hd;
        }
    }
}

// ---------------- loss: mean NLL over 6400 rows of 8000 logits --------------
__global__ void k_loss(const int* __restrict__ x, float* out) {
    int r = blockIdx.x;            // r = t*64 + b
    int t = r >> 6, b = r & 63;
    const float* row = &g_logits[(size_t)r * VV];
    int tid = threadIdx.x;
    float m = -INFINITY, s = 0.f;
    for (int v = tid; v < VV; v += 256) {
        float xv = row[v];
        if (xv > m) { s = s * expf(m - xv) + 1.f; m = xv; }
        else s += expf(xv - m);
    }
    __shared__ float sm[256], ss[256];
    sm[tid] = m; ss[tid] = s;
    __syncthreads();
    for (int o = 128; o; o >>= 1) {
        if (tid < o) {
            float m2 = sm[tid + o], s2 = ss[tid + o];
            float mm = fmaxf(sm[tid], m2);
            ss[tid] = ss[tid] * expf(sm[tid] - mm) + s2 * expf(m2 - mm);
            sm[tid] = mm;
        }
        __syncthreads();
    }
    if (tid == 0) {
        int tgt = x[b*TT + t + 1];
        float lse = sm[0] + logf(ss[0]);
        atomicAdd(out, (lse - row[tgt]) * (1.f / MM));
    }
}

// ---------------- transpose [t*64+b][v] -> out[b][v][t] ---------------------
__global__ void k_transpose(float* __restrict__ outLogits) {
    int b = blockIdx.x;
    int v0 = blockIdx.y * 32;
    __shared__ float tile[32 * 101];
    int tid = threadIdx.x;
    for (int idx = tid; idx < 3200; idx += 256) {
        int t = idx >> 5, vi = idx & 31;
        tile[vi*101 + t] = g_logits[(size_t)(t*BB + b)*VV + v0 + vi];
    }
    __syncthreads();
    for (int idx = tid; idx < 3200; idx += 256) {
        int vi = idx / 100, t = idx - vi*100;
        outLogits[(size_t)b*VV*TS + (size_t)(v0 + vi)*TS + t] = tile[vi*101 + t];
    }
}

// ---------------- launch ------------------------------------------------------
extern "C" void kernel_launch(void* const* d_in, const int* in_sizes, int n_in,
                              void* d_out, int out_size) {
    const int*   x   = (const int*)d_in[0];
    const float* emb = (const float*)d_in[1];
    const float* Wd  = (const float*)d_in[2];
    const float* bd  = (const float*)d_in[3];
    const float* Wih[3] = {(const float*)d_in[4],  (const float*)d_in[10], (const float*)d_in[16]};
    const float* Whh[3] = {(const float*)d_in[5],  (const float*)d_in[11], (const float*)d_in[17]};
    const float* bl[3]  = {(const float*)d_in[6],  (const float*)d_in[12], (const float*)d_in[18]};
    const float* gm[3]  = {(const float*)d_in[7],  (const float*)d_in[13], (const float*)d_in[19]};
    const float* bt[3]  = {(const float*)d_in[8],  (const float*)d_in[14], (const float*)d_in[20]};
    const float* mk[3]  = {(const float*)d_in[9],  (const float*)d_in[15], (const float*)d_in[21]};

    float* out = (float*)d_out;
    int hasLoss = (out_size & 1) ? 1 : 0;   // 51,200,001 odd => loss + logits
    float* outLogits = out + hasLoss;

    k_init<<<(3*HH*BB + 255)/256, 256>>>(out, hasLoss);
    k_embed<<<(MM*(HH/4) + 255)/256, 256>>>(x, emb);
    k_gemm_big<0><<<dim3(GG/128, MM/128), 256>>>(Wih[0], bl[0]);

    // wavefront over diagonals d = t + l, d in [0, TS+2)
    for (int d = 0; d < TS + 2; d++) {
        k_gemm_wave<<<dim3(8, 32, 3), 256>>>(d, Whh[0], Wih[1], Whh[1], Wih[2], Whh[2]);
        k_cell_wave<<<dim3(32, 3), 256>>>(d, bl[1], bl[2],
                                          gm[0], bt[0], mk[0],
                                          gm[1], bt[1], mk[1],
                                          gm[2], bt[2], mk[2]);
    }

    k_gemm_big<1><<<dim3((VV + 127)/128, MM/128), 256>>>(Wd, bd);
    if (hasLoss) k_loss<<<MM, 256>>>(x, out);
    k_transpose<<<dim3(BB, VV/32), 256>>>(outLogits);
}

// round 7
// speedup vs baseline: 1.1101x; 1.1101x over previous
#include <cuda_runtime.h>
#include <math.h>

#define BB 64
#define TT 101
#define TS 100
#define VV 8000
#define HH 512
#define GG 2048
#define MM (TS*BB)   // 6400
#define EPSN 1e-5f

typedef unsigned long long ull;

// ---------------- device scratch (static; no runtime allocation) -------------
__device__ float g_e[MM*HH];                     // [m][h] embedded inputs, m = t*64+b
__device__ float g_Xg1[(size_t)GG*MM];           // [t][n][b] precomputed e@Wih1^T + b1
__device__ float g_Hout[MM*HH];                  // [m][h] layer-3 bn*mask output per step
__device__ float g_logits[(size_t)MM*VV];        // [m][v]
__device__ float g_part[(size_t)3*8*GG*BB];      // [layer][slice][n][b] split-K partials
__device__ float g_h[3*HH*BB];                   // [layer][j][b]
__device__ float g_c[3*HH*BB];                   // [layer][j][b]
__device__ float g_hd[2*HH*BB];                  // [layer][j][b]

// ---------------- f32x2 helpers ----------------------------------------------
__device__ __forceinline__ ull fma2(ull a, ull b, ull c) {
    ull d;
    asm("fma.rn.f32x2 %0, %1, %2, %3;" : "=l"(d) : "l"(a), "l"(b), "l"(c));
    return d;
}
__device__ __forceinline__ ull pack2(float x, float y) {
    ull r;
    asm("mov.b64 %0, {%1, %2};" : "=l"(r) : "f"(x), "f"(y));
    return r;
}
__device__ __forceinline__ ull dup2(float x) {
    ull r;
    asm("mov.b64 %0, {%1, %1};" : "=l"(r) : "f"(x));
    return r;
}
__device__ __forceinline__ float2 unpack2(ull v) {
    float2 r;
    asm("mov.b64 {%0, %1}, %2;" : "=f"(r.x), "=f"(r.y) : "l"(v));
    return r;
}

// ---------------- init: zero states + loss slot ------------------------------
__global__ void k_init(float* out, int hasLoss) {
    int i = blockIdx.x * blockDim.x + threadIdx.x;
    if (i < 3*HH*BB) { g_h[i] = 0.f; g_c[i] = 0.f; }
    if (i == 0 && hasLoss) out[0] = 0.f;
}

// ---------------- embedding gather -------------------------------------------
__global__ void k_embed(const int* x, const float* emb) {
    int i = blockIdx.x * blockDim.x + threadIdx.x;
    if (i >= MM * (HH/4)) return;
    int m  = i / (HH/4);
    int hq = i % (HH/4);
    int t = m / BB, b = m % BB;
    int tok = x[b*TT + t];
    ((float4*)g_e)[(size_t)m*(HH/4) + hq] =
        ((const float4*)emb)[(size_t)tok*(HH/4) + hq];
}

// ---------------- big SGEMM (f32x2): 128x128 tile, pairs along m -------------
// MODE 0: g_Xg1[t][n][b] = g_e @ Wih1^T + b1, N=2048
// MODE 1: g_logits[m][v] = g_Hout @ Wd^T + bd, N=8000
template<int MODE>
__global__ void __launch_bounds__(256) k_gemm_big(const float* __restrict__ Bw,
                                                  const float* __restrict__ bias) {
    const int N = (MODE == 0) ? GG : VV;
    const float* A = (MODE == 0) ? g_e : g_Hout;
    __shared__ __align__(16) float Ast[16][132];
    __shared__ __align__(16) ull   Bst2[16][132];
    int tid = threadIdx.x;
    int mBase = blockIdx.y * 128, nBase = blockIdx.x * 128;
    int lr = tid >> 2, lc = (tid & 3) * 4;
    int m0 = (tid >> 4) * 8, n0 = (tid & 15) * 8;
    ull acc[4][8];
#pragma unroll
    for (int i = 0; i < 4; i++)
#pragma unroll
        for (int j = 0; j < 8; j++) acc[i][j] = 0ull;

    for (int kb = 0; kb < 512; kb += 16) {
        float4 av0 = *(const float4*)&A[(size_t)(mBase + lr)*512 + kb + lc];
        float4 av1 = *(const float4*)&A[(size_t)(mBase + lr + 64)*512 + kb + lc];
        int ng0 = nBase + lr, ng1 = nBase + lr + 64;
        float4 bv0 = make_float4(0.f,0.f,0.f,0.f), bv1 = make_float4(0.f,0.f,0.f,0.f);
        if (ng0 < N) bv0 = *(const float4*)&Bw[(size_t)ng0*512 + kb + lc];
        if (ng1 < N) bv1 = *(const float4*)&Bw[(size_t)ng1*512 + kb + lc];
        __syncthreads();
        Ast[lc+0][lr] = av0.x; Ast[lc+1][lr] = av0.y; Ast[lc+2][lr] = av0.z; Ast[lc+3][lr] = av0.w;
        Ast[lc+0][lr+64] = av1.x; Ast[lc+1][lr+64] = av1.y; Ast[lc+2][lr+64] = av1.z; Ast[lc+3][lr+64] = av1.w;
        Bst2[lc+0][lr] = pack2(bv0.x, bv0.x); Bst2[lc+1][lr] = pack2(bv0.y, bv0.y);
        Bst2[lc+2][lr] = pack2(bv0.z, bv0.z); Bst2[lc+3][lr] = pack2(bv0.w, bv0.w);
        Bst2[lc+0][lr+64] = pack2(bv1.x, bv1.x); Bst2[lc+1][lr+64] = pack2(bv1.y, bv1.y);
        Bst2[lc+2][lr+64] = pack2(bv1.z, bv1.z); Bst2[lc+3][lr+64] = pack2(bv1.w, bv1.w);
        __syncthreads();
#pragma unroll
        for (int kk = 0; kk < 16; kk++) {
            ull a2[4], w2[8];
#pragma unroll
            for (int i = 0; i < 4; i++) a2[i] = *(const ull*)&Ast[kk][m0 + 2*i];
#pragma unroll
            for (int j = 0; j < 8; j++) w2[j] = Bst2[kk][n0 + j];
#pragma unroll
            for (int i = 0; i < 4; i++)
#pragma unroll
                for (int j = 0; j < 8; j++) acc[i][j] = fma2(a2[i], w2[j], acc[i][j]);
        }
    }

    if (MODE == 0) {
#pragma unroll
        for (int j = 0; j < 8; j++) {
            int n = nBase + n0 + j;
            float bb = bias[n];
#pragma unroll
            for (int i = 0; i < 4; i++) {
                int m = mBase + m0 + 2*i;
                float2 v = unpack2(acc[i][j]);
                v.x += bb; v.y += bb;
                int tt = m >> 6, bc = m & 63;
                *(float2*)&g_Xg1[(size_t)tt*(GG*BB) + (size_t)n*BB + bc] = v;
            }
        }
    } else {
#pragma unroll
        for (int i = 0; i < 4; i++) {
            int m = mBase + m0 + 2*i;
#pragma unroll
            for (int j = 0; j < 8; j++) {
                int n = nBase + n0 + j;
                if (n < VV) {
                    float2 v = unpack2(acc[i][j]);
                    float bb = bias[n];
                    g_logits[(size_t)m*VV + n]     = v.x + bb;
                    g_logits[(size_t)(m+1)*VV + n] = v.y + bb;
                }
            }
        }
    }
}

// ---------------- wavefront GEMM: diagonal d = t + l --------------------------
// grid (16 n-tiles, 8 K-slices, 3 layers), block 256.
// CTA tile 128n x 64b x 128k, k-chunked by 32 through smem. Thread tile 8n x 4b.
// Layer 0: K=512 -> slices 0..3. Layers 1,2: K=1024 -> slices 0..3 Wih, 4..7 Whh.
__global__ void __launch_bounds__(256) k_gemm_wave(int d,
    const float* __restrict__ Whh1,
    const float* __restrict__ Wih2, const float* __restrict__ Whh2,
    const float* __restrict__ Wih3, const float* __restrict__ Whh3)
{
    int l = blockIdx.z;
    int t = d - l;
    if (t < 0 || t >= TS) return;
    int slice = blockIdx.y;
    if (l == 0 && slice >= 4) return;

    const float* A; const float* W;
    if (l == 0) {
        A = g_h + slice*128*BB;
        W = Whh1 + slice*128;
    } else if (slice < 4) {
        A = g_hd + (l-1)*HH*BB + slice*128*BB;
        W = ((l == 1) ? Wih2 : Wih3) + slice*128;
    } else {
        A = g_h + l*HH*BB + (slice-4)*128*BB;
        W = ((l == 1) ? Whh2 : Whh3) + (slice-4)*128;
    }
    int nb = blockIdx.x * 128;
    int tid = threadIdx.x;

    __shared__ __align__(16) float Ast[32*64];    // [k][b] 8KB
    __shared__ __align__(16) float Wst[32*128];   // [k][n] 16KB

    int b0 = (tid & 15) * 4;     // 4 b (2 ull pairs)
    int n0 = (tid >> 4) * 8;     // 8 n
    int wn = tid & 127, wkh = (tid >> 7) * 16;   // W staging coords

    ull acc[8][2];
#pragma unroll
    for (int j = 0; j < 8; j++) { acc[j][0] = 0ull; acc[j][1] = 0ull; }

    for (int kc = 0; kc < 128; kc += 32) {
        // stage A chunk [32k][64b]: 512 float4, 2 per thread
#pragma unroll
        for (int i = 0; i < 2; i++) {
            int idx = tid + i*256;
            int k = idx >> 4, q = (idx & 15) * 4;
            *(float4*)&Ast[k*64 + q] = *(const float4*)&A[(size_t)(kc + k)*BB + q];
        }
        // stage W chunk [32k][128n]: thread owns n row, 16 k (half of chunk)
        {
            const float* wp = W + (size_t)(nb + wn)*HH + kc + wkh;
#pragma unroll
            for (int c = 0; c < 16; c += 4) {
                float4 w = *(const float4*)&wp[c];
                int k = wkh + c;
                Wst[(k+0)*128 + wn] = w.x;
                Wst[(k+1)*128 + wn] = w.y;
                Wst[(k+2)*128 + wn] = w.z;
                Wst[(k+3)*128 + wn] = w.w;
            }
        }
        __syncthreads();

#pragma unroll 4
        for (int k = 0; k < 32; k++) {
            ull a2[2];
            *(ulonglong2*)&a2[0] = *(const ulonglong2*)&Ast[k*64 + b0];
            float4 w0 = *(const float4*)&Wst[k*128 + n0];
            float4 w1 = *(const float4*)&Wst[k*128 + n0 + 4];
            ull wd[8];
            wd[0] = dup2(w0.x); wd[1] = dup2(w0.y); wd[2] = dup2(w0.z); wd[3] = dup2(w0.w);
            wd[4] = dup2(w1.x); wd[5] = dup2(w1.y); wd[6] = dup2(w1.z); wd[7] = dup2(w1.w);
#pragma unroll
            for (int j = 0; j < 8; j++) {
                acc[j][0] = fma2(a2[0], wd[j], acc[j][0]);
                acc[j][1] = fma2(a2[1], wd[j], acc[j][1]);
            }
        }
        __syncthreads();
    }

    float* P = g_part + ((size_t)(l*8 + slice)*GG + nb)*BB;
#pragma unroll
    for (int j = 0; j < 8; j++) {
        ulonglong2 v; v.x = acc[j][0]; v.y = acc[j][1];
        *(ulonglong2*)&P[(size_t)(n0 + j)*BB + b0] = v;
    }
}

// ---------------- wavefront cell: LSTM + BN(train) + locked dropout ----------
// grid (32 j-tiles, 3 layers), block 256 = 16 j x 16 b-quads (float4 along b).
// BN via width-16 shuffles only; no smem, no __syncthreads.
__global__ void __launch_bounds__(256) k_cell_wave(int d,
    const float* __restrict__ b2, const float* __restrict__ b3,
    const float* __restrict__ gm0, const float* __restrict__ bt0, const float* __restrict__ mk0,
    const float* __restrict__ gm1, const float* __restrict__ bt1, const float* __restrict__ mk1,
    const float* __restrict__ gm2, const float* __restrict__ bt2, const float* __restrict__ mk2)
{
    int l = blockIdx.y;
    int t = d - l;
    if (t < 0 || t >= TS) return;
    int tid = threadIdx.x;
    int jl = tid >> 4, bq = tid & 15;
    int j = blockIdx.x * 16 + jl;
    int b0 = bq * 4;
    const float* biasP = (l == 1) ? b2 : b3;
    const float* gmP = (l == 0) ? gm0 : (l == 1) ? gm1 : gm2;
    const float* btP = (l == 0) ? bt0 : (l == 1) ? bt1 : bt2;
    const float* mkP = (l == 0) ? mk0 : (l == 1) ? mk1 : mk2;

    float ga[4][4];   // [gate][b-elem]
#pragma unroll
    for (int g = 0; g < 4; g++) {
        int n = (g << 9) + j;
        float4 s;
        if (l == 0) {
            s = *(const float4*)&g_Xg1[(size_t)t*(GG*BB) + (size_t)n*BB + b0];
        } else {
            float bv = biasP[n];
            s = make_float4(bv, bv, bv, bv);
        }
        const float* pp = g_part + ((size_t)(l*8)*GG + n)*BB + b0;
        if (l == 0) {
#pragma unroll
            for (int sl = 0; sl < 4; sl++) {
                float4 v = *(const float4*)(pp + (size_t)sl*(GG*BB));
                s.x += v.x; s.y += v.y; s.z += v.z; s.w += v.w;
            }
        } else {
#pragma unroll
            for (int sl = 0; sl < 8; sl++) {
                float4 v = *(const float4*)(pp + (size_t)sl*(GG*BB));
                s.x += v.x; s.y += v.y; s.z += v.z; s.w += v.w;
            }
        }
        ga[g][0] = s.x; ga[g][1] = s.y; ga[g][2] = s.z; ga[g][3] = s.w;
    }

    float* hP = g_h + l*HH*BB + j*BB + b0;
    float* cP = g_c + l*HH*BB + j*BB + b0;
    float4 cprev = *(const float4*)cP;
    float cpv[4] = {cprev.x, cprev.y, cprev.z, cprev.w};
    float hh[4], ccv[4];
#pragma unroll
    for (int e = 0; e < 4; e++) {
        float iv = 1.f / (1.f + expf(-ga[0][e]));
        float fv = 1.f / (1.f + expf(-ga[1][e]));
        float gv = tanhf(ga[2][e]);
        float ov = 1.f / (1.f + expf(-ga[3][e]));
        float cc = fv * cpv[e] + iv * gv;
        ccv[e] = cc;
        hh[e] = ov * tanhf(cc);
    }
    *(float4*)cP = make_float4(ccv[0], ccv[1], ccv[2], ccv[3]);
    *(float4*)hP = make_float4(hh[0], hh[1], hh[2], hh[3]);

    // BN over batch: 16 threads x 4 elems per feature j (width-16 shuffle tree)
    float sum = hh[0] + hh[1] + hh[2] + hh[3];
    float sq  = hh[0]*hh[0] + hh[1]*hh[1] + hh[2]*hh[2] + hh[3]*hh[3];
#pragma unroll
    for (int o = 8; o; o >>= 1) {
        sum += __shfl_down_sync(0xffffffffu, sum, o, 16);
        sq  += __shfl_down_sync(0xffffffffu, sq,  o, 16);
    }
    sum = __shfl_sync(0xffffffffu, sum, 0, 16);
    sq  = __shfl_sync(0xffffffffu, sq,  0, 16);
    float mu  = sum * (1.f / BB);
    float var = sq  * (1.f / BB) - mu * mu;
    float rs  = rsqrtf(var + EPSN);
    float gmv = gmP[j], btv = btP[j];

    if (l < 2) {
        float hd[4];
#pragma unroll
        for (int e = 0; e < 4; e++)
            hd[e] = (gmv * (hh[e] - mu) * rs + btv) * mkP[(b0+e)*HH + j];
        *(float4*)&g_hd[l*HH*BB + j*BB + b0] = make_float4(hd[0], hd[1], hd[2], hd[3]);
    } else {
#pragma unroll
        for (int e = 0; e < 4; e++) {
            float hd = (gmv * (hh[e] - mu) * rs + btv) * mkP[(b0+e)*HH + j];
            g_Hout[((size_t)t*BB + b0 + e)*HH + j] = hd;
        }
    }
}

// ---------------- loss: mean NLL over 6400 rows of 8000 logits --------------
__global__ void k_loss(const int* __restrict__ x, float* out) {
    int r = blockIdx.x;            // r = t*64 + b
    int t = r >> 6, b = r & 63;
    const float* row = &g_logits[(size_t)r * VV];
    int tid = threadIdx.x;
    float m = -INFINITY, s = 0.f;
    for (int v = tid; v < VV; v += 256) {
        float xv = row[v];
        if (xv > m) { s = s * expf(m - xv) + 1.f; m = xv; }
        else s += expf(xv - m);
    }
    __shared__ float sm[256], ss[256];
    sm[tid] = m; ss[tid] = s;
    __syncthreads();
    for (int o = 128; o; o >>= 1) {
        if (tid < o) {
            float m2 = sm[tid + o], s2 = ss[tid + o];
            float mm = fmaxf(sm[tid], m2);
            ss[tid] = ss[tid] * expf(sm[tid] - mm) + s2 * expf(m2 - mm);
            sm[tid] = mm;
        }
        __syncthreads();
    }
    if (tid == 0) {
        int tgt = x[b*TT + t + 1];
        float lse = sm[0] + logf(ss[0]);
        atomicAdd(out, (lse - row[tgt]) * (1.f / MM));
    }
}

// ---------------- transpose [t*64+b][v] -> out[b][v][t] ---------------------
__global__ void k_transpose(float* __restrict__ outLogits) {
    int b = blockIdx.x;
    int v0 = blockIdx.y * 32;
    __shared__ float tile[32 * 101];
    int tid = threadIdx.x;
    for (int idx = tid; idx < 3200; idx += 256) {
        int t = idx >> 5, vi = idx & 31;
        tile[vi*101 + t] = g_logits[(size_t)(t*BB + b)*VV + v0 + vi];
    }
    __syncthreads();
    for (int idx = tid; idx < 3200; idx += 256) {
        int vi = idx / 100, t = idx - vi*100;
        outLogits[(size_t)b*VV*TS + (size_t)(v0 + vi)*TS + t] = tile[vi*101 + t];
    }
}

// ---------------- launch ------------------------------------------------------
extern "C" void kernel_launch(void* const* d_in, const int* in_sizes, int n_in,
                              void* d_out, int out_size) {
    const int*   x   = (const int*)d_in[0];
    const float* emb = (const float*)d_in[1];
    const float* Wd  = (const float*)d_in[2];
    const float* bd  = (const float*)d_in[3];
    const float* Wih[3] = {(const float*)d_in[4],  (const float*)d_in[10], (const float*)d_in[16]};
    const float* Whh[3] = {(const float*)d_in[5],  (const float*)d_in[11], (const float*)d_in[17]};
    const float* bl[3]  = {(const float*)d_in[6],  (const float*)d_in[12], (const float*)d_in[18]};
    const float* gm[3]  = {(const float*)d_in[7],  (const float*)d_in[13], (const float*)d_in[19]};
    const float* bt[3]  = {(const float*)d_in[8],  (const float*)d_in[14], (const float*)d_in[20]};
    const float* mk[3]  = {(const float*)d_in[9],  (const float*)d_in[15], (const float*)d_in[21]};

    float* out = (float*)d_out;
    int hasLoss = (out_size & 1) ? 1 : 0;   // 51,200,001 odd => loss + logits
    float* outLogits = out + hasLoss;

    k_init<<<(3*HH*BB + 255)/256, 256>>>(out, hasLoss);
    k_embed<<<(MM*(HH/4) + 255)/256, 256>>>(x, emb);
    k_gemm_big<0><<<dim3(GG/128, MM/128), 256>>>(Wih[0], bl[0]);

    // wavefront over diagonals d = t + l, d in [0, TS+2)
    for (int d = 0; d < TS + 2; d++) {
        k_gemm_wave<<<dim3(16, 8, 3), 256>>>(d, Whh[0], Wih[1], Whh[1], Wih[2], Whh[2]);
        k_cell_wave<<<dim3(32, 3), 256>>>(d, bl[1], bl[2],
                                          gm[0], bt[0], mk[0],
                                          gm[1], bt[1], mk[1],
                                          gm[2], bt[2], mk[2]);
    }

    k_gemm_big<1><<<dim3((VV + 127)/128, MM/128), 256>>>(Wd, bd);
    if (hasLoss) k_loss<<<MM, 256>>>(x, out);
    k_transpose<<<dim3(BB, VV/32), 256>>>(outLogits);
}

// round 8
// speedup vs baseline: 1.6584x; 1.4939x over previous
#include <cuda_runtime.h>
#include <math.h>

#define BB 64
#define TT 101
#define TS 100
#define VV 8000
#define HH 512
#define GG 2048
#define MM (TS*BB)   // 6400
#define EPSN 1e-5f

typedef unsigned long long ull;

// ---------------- device scratch (static; no runtime allocation) -------------
__device__ float g_e[MM*HH];                     // [m][h] embedded inputs, m = t*64+b
__device__ float g_Xg1[(size_t)GG*MM];           // [t][n][b] precomputed e@Wih1^T + b1
__device__ float g_Hout[MM*HH];                  // [m][h] layer-3 bn*mask output per step
__device__ float g_logits[(size_t)MM*VV];        // [m][v]
__device__ float g_part[(size_t)3*8*GG*BB];      // [layer][slice][n][b] split-K partials
__device__ float g_h[3*HH*BB];                   // [layer][j][b]
__device__ float g_c[3*HH*BB];                   // [layer][j][b]
__device__ float g_hd[2*HH*BB];                  // [layer][j][b]

// ---------------- f32x2 / tf32 helpers ----------------------------------------
__device__ __forceinline__ ull fma2(ull a, ull b, ull c) {
    ull d;
    asm("fma.rn.f32x2 %0, %1, %2, %3;" : "=l"(d) : "l"(a), "l"(b), "l"(c));
    return d;
}
__device__ __forceinline__ ull pack2(float x, float y) {
    ull r;
    asm("mov.b64 %0, {%1, %2};" : "=l"(r) : "f"(x), "f"(y));
    return r;
}
__device__ __forceinline__ ull dup2(float x) {
    ull r;
    asm("mov.b64 %0, {%1, %1};" : "=l"(r) : "f"(x));
    return r;
}
__device__ __forceinline__ float2 unpack2(ull v) {
    float2 r;
    asm("mov.b64 {%0, %1}, %2;" : "=f"(r.x), "=f"(r.y) : "l"(v));
    return r;
}
__device__ __forceinline__ unsigned tf32c(float x) {
    unsigned u;
    asm("cvt.rna.tf32.f32 %0, %1;" : "=r"(u) : "f"(x));
    return u;
}
__device__ __forceinline__ void mma_tf32(float* c, const unsigned* a, const unsigned* b) {
    asm("mma.sync.aligned.m16n8k8.row.col.f32.tf32.tf32.f32 "
        "{%0,%1,%2,%3}, {%4,%5,%6,%7}, {%8,%9}, {%0,%1,%2,%3};"
        : "+f"(c[0]), "+f"(c[1]), "+f"(c[2]), "+f"(c[3])
        : "r"(a[0]), "r"(a[1]), "r"(a[2]), "r"(a[3]), "r"(b[0]), "r"(b[1]));
}

// ---------------- init: zero states + loss slot ------------------------------
__global__ void k_init(float* out, int hasLoss) {
    int i = blockIdx.x * blockDim.x + threadIdx.x;
    if (i < 3*HH*BB) { g_h[i] = 0.f; g_c[i] = 0.f; }
    if (i == 0 && hasLoss) out[0] = 0.f;
}

// ---------------- embedding gather -------------------------------------------
__global__ void k_embed(const int* x, const float* emb) {
    int i = blockIdx.x * blockDim.x + threadIdx.x;
    if (i >= MM * (HH/4)) return;
    int m  = i / (HH/4);
    int hq = i % (HH/4);
    int t = m / BB, b = m % BB;
    int tok = x[b*TT + t];
    ((float4*)g_e)[(size_t)m*(HH/4) + hq] =
        ((const float4*)emb)[(size_t)tok*(HH/4) + hq];
}

// ---------------- Xg1 SGEMM (fp32 f32x2, exact): 128x128 tile ----------------
// g_Xg1[t][n][b] = g_e @ Wih1^T + b1, N=2048
__global__ void __launch_bounds__(256) k_gemm_xg1(const float* __restrict__ Bw,
                                                  const float* __restrict__ bias) {
    const float* A = g_e;
    __shared__ __align__(16) float Ast[16][132];
    __shared__ __align__(16) ull   Bst2[16][132];
    int tid = threadIdx.x;
    int mBase = blockIdx.y * 128, nBase = blockIdx.x * 128;
    int lr = tid >> 2, lc = (tid & 3) * 4;
    int m0 = (tid >> 4) * 8, n0 = (tid & 15) * 8;
    ull acc[4][8];
#pragma unroll
    for (int i = 0; i < 4; i++)
#pragma unroll
        for (int j = 0; j < 8; j++) acc[i][j] = 0ull;

    for (int kb = 0; kb < 512; kb += 16) {
        float4 av0 = *(const float4*)&A[(size_t)(mBase + lr)*512 + kb + lc];
        float4 av1 = *(const float4*)&A[(size_t)(mBase + lr + 64)*512 + kb + lc];
        float4 bv0 = *(const float4*)&Bw[(size_t)(nBase + lr)*512 + kb + lc];
        float4 bv1 = *(const float4*)&Bw[(size_t)(nBase + lr + 64)*512 + kb + lc];
        __syncthreads();
        Ast[lc+0][lr] = av0.x; Ast[lc+1][lr] = av0.y; Ast[lc+2][lr] = av0.z; Ast[lc+3][lr] = av0.w;
        Ast[lc+0][lr+64] = av1.x; Ast[lc+1][lr+64] = av1.y; Ast[lc+2][lr+64] = av1.z; Ast[lc+3][lr+64] = av1.w;
        Bst2[lc+0][lr] = pack2(bv0.x, bv0.x); Bst2[lc+1][lr] = pack2(bv0.y, bv0.y);
        Bst2[lc+2][lr] = pack2(bv0.z, bv0.z); Bst2[lc+3][lr] = pack2(bv0.w, bv0.w);
        Bst2[lc+0][lr+64] = pack2(bv1.x, bv1.x); Bst2[lc+1][lr+64] = pack2(bv1.y, bv1.y);
        Bst2[lc+2][lr+64] = pack2(bv1.z, bv1.z); Bst2[lc+3][lr+64] = pack2(bv1.w, bv1.w);
        __syncthreads();
#pragma unroll
        for (int kk = 0; kk < 16; kk++) {
            ull a2[4], w2[8];
#pragma unroll
            for (int i = 0; i < 4; i++) a2[i] = *(const ull*)&Ast[kk][m0 + 2*i];
#pragma unroll
            for (int j = 0; j < 8; j++) w2[j] = Bst2[kk][n0 + j];
#pragma unroll
            for (int i = 0; i < 4; i++)
#pragma unroll
                for (int j = 0; j < 8; j++) acc[i][j] = fma2(a2[i], w2[j], acc[i][j]);
        }
    }

#pragma unroll
    for (int j = 0; j < 8; j++) {
        int n = nBase + n0 + j;
        float bb = bias[n];
#pragma unroll
        for (int i = 0; i < 4; i++) {
            int m = mBase + m0 + 2*i;
            float2 v = unpack2(acc[i][j]);
            v.x += bb; v.y += bb;
            int tt = m >> 6, bc = m & 63;
            *(float2*)&g_Xg1[(size_t)tt*(GG*BB) + (size_t)n*BB + bc] = v;
        }
    }
}

// ---------------- decoder GEMM: TF32 tensor cores -----------------------------
// g_logits[m][v] = g_Hout[m][k] @ Wd[v][k]^T + bd.  CTA 128m x 128n, K=512.
// 8 warps (2m x 4n), warp tile 64x32 via m16n8k8 mma.
__global__ void __launch_bounds__(256) k_dec_tc(const float* __restrict__ Wd,
                                                const float* __restrict__ bd) {
    __shared__ unsigned Ast[32*136];   // [k][m], row stride 136 -> conflict-free
    __shared__ unsigned Bst[32*136];   // [k][n]
    int tid = threadIdx.x;
    int warp = tid >> 5, lane = tid & 31;
    int gid = lane >> 2, tig = lane & 3;
    int mBase = blockIdx.y * 128, nBase = blockIdx.x * 128;
    int wm = (warp >> 2) * 64, wn = (warp & 3) * 32;

    float c[4][4][4];
#pragma unroll
    for (int i = 0; i < 4; i++)
#pragma unroll
        for (int j = 0; j < 4; j++)
#pragma unroll
            for (int e = 0; e < 4; e++) c[i][j][e] = 0.f;

    int srow = tid & 127;        // staged m (or n) row
    int half = tid >> 7;         // k half: 0 or 1 (16 k each)
    int nIdx = nBase + srow;
    bool nOk = nIdx < VV;
    const float* aRow = &g_Hout[(size_t)(mBase + srow)*HH];
    const float* bRow = &Wd[(size_t)(nOk ? nIdx : 0)*HH];

    for (int kc = 0; kc < HH; kc += 32) {
        float4 av[4], bv[4];
#pragma unroll
        for (int i = 0; i < 4; i++) {
            av[i] = *(const float4*)&aRow[kc + half*16 + i*4];
            float4 b = *(const float4*)&bRow[kc + half*16 + i*4];
            if (!nOk) b = make_float4(0.f, 0.f, 0.f, 0.f);
            bv[i] = b;
        }
        __syncthreads();
#pragma unroll
        for (int i = 0; i < 4; i++) {
            int k = half*16 + i*4;
            Ast[(k+0)*136 + srow] = tf32c(av[i].x);
            Ast[(k+1)*136 + srow] = tf32c(av[i].y);
            Ast[(k+2)*136 + srow] = tf32c(av[i].z);
            Ast[(k+3)*136 + srow] = tf32c(av[i].w);
            Bst[(k+0)*136 + srow] = tf32c(bv[i].x);
            Bst[(k+1)*136 + srow] = tf32c(bv[i].y);
            Bst[(k+2)*136 + srow] = tf32c(bv[i].z);
            Bst[(k+3)*136 + srow] = tf32c(bv[i].w);
        }
        __syncthreads();
#pragma unroll
        for (int ks = 0; ks < 32; ks += 8) {
            unsigned a[4][4], b[4][2];
            int r0 = (ks + tig)*136, r1 = (ks + tig + 4)*136;
#pragma unroll
            for (int i = 0; i < 4; i++) {
                int mo = wm + i*16 + gid;
                a[i][0] = Ast[r0 + mo]; a[i][1] = Ast[r0 + mo + 8];
                a[i][2] = Ast[r1 + mo]; a[i][3] = Ast[r1 + mo + 8];
            }
#pragma unroll
            for (int j = 0; j < 4; j++) {
                int no = wn + j*8 + gid;
                b[j][0] = Bst[r0 + no];
                b[j][1] = Bst[r1 + no];
            }
#pragma unroll
            for (int i = 0; i < 4; i++)
#pragma unroll
                for (int j = 0; j < 4; j++)
                    mma_tf32(c[i][j], a[i], b[j]);
        }
    }

#pragma unroll
    for (int i = 0; i < 4; i++) {
        int r0 = mBase + wm + i*16 + gid;
#pragma unroll
        for (int j = 0; j < 4; j++) {
            int n = nBase + wn + j*8 + 2*tig;
            if (n < VV) {
                float2 bb = *(const float2*)&bd[n];
                float2 v0; v0.x = c[i][j][0] + bb.x; v0.y = c[i][j][1] + bb.y;
                float2 v1; v1.x = c[i][j][2] + bb.x; v1.y = c[i][j][3] + bb.y;
                *(float2*)&g_logits[(size_t)r0*VV + n]       = v0;
                *(float2*)&g_logits[(size_t)(r0 + 8)*VV + n] = v1;
            }
        }
    }
}

// ---------------- wavefront GEMM: diagonal d = t + l --------------------------
// grid (16 n-tiles, 8 K-slices, 3 layers), block 256.
// CTA tile 128n x 64b x 128k, k-chunked by 32 through smem. Thread tile 8n x 4b.
__global__ void __launch_bounds__(256) k_gemm_wave(int d,
    const float* __restrict__ Whh1,
    const float* __restrict__ Wih2, const float* __restrict__ Whh2,
    const float* __restrict__ Wih3, const float* __restrict__ Whh3)
{
    int l = blockIdx.z;
    int t = d - l;
    if (t < 0 || t >= TS) return;
    int slice = blockIdx.y;
    if (l == 0 && slice >= 4) return;

    const float* A; const float* W;
    if (l == 0) {
        A = g_h + slice*128*BB;
        W = Whh1 + slice*128;
    } else if (slice < 4) {
        A = g_hd + (l-1)*HH*BB + slice*128*BB;
        W = ((l == 1) ? Wih2 : Wih3) + slice*128;
    } else {
        A = g_h + l*HH*BB + (slice-4)*128*BB;
        W = ((l == 1) ? Whh2 : Whh3) + (slice-4)*128;
    }
    int nb = blockIdx.x * 128;
    int tid = threadIdx.x;

    __shared__ __align__(16) float Ast[32*64];    // [k][b] 8KB
    __shared__ __align__(16) float Wst[32*128];   // [k][n] 16KB

    int b0 = (tid & 15) * 4;
    int n0 = (tid >> 4) * 8;
    int wn = tid & 127, wkh = (tid >> 7) * 16;

    ull acc[8][2];
#pragma unroll
    for (int j = 0; j < 8; j++) { acc[j][0] = 0ull; acc[j][1] = 0ull; }

    for (int kc = 0; kc < 128; kc += 32) {
#pragma unroll
        for (int i = 0; i < 2; i++) {
            int idx = tid + i*256;
            int k = idx >> 4, q = (idx & 15) * 4;
            *(float4*)&Ast[k*64 + q] = *(const float4*)&A[(size_t)(kc + k)*BB + q];
        }
        {
            const float* wp = W + (size_t)(nb + wn)*HH + kc + wkh;
#pragma unroll
            for (int c = 0; c < 16; c += 4) {
                float4 w = *(const float4*)&wp[c];
                int k = wkh + c;
                Wst[(k+0)*128 + wn] = w.x;
                Wst[(k+1)*128 + wn] = w.y;
                Wst[(k+2)*128 + wn] = w.z;
                Wst[(k+3)*128 + wn] = w.w;
            }
        }
        __syncthreads();

#pragma unroll 4
        for (int k = 0; k < 32; k++) {
            ull a2[2];
            *(ulonglong2*)&a2[0] = *(const ulonglong2*)&Ast[k*64 + b0];
            float4 w0 = *(const float4*)&Wst[k*128 + n0];
            float4 w1 = *(const float4*)&Wst[k*128 + n0 + 4];
            ull wd[8];
            wd[0] = dup2(w0.x); wd[1] = dup2(w0.y); wd[2] = dup2(w0.z); wd[3] = dup2(w0.w);
            wd[4] = dup2(w1.x); wd[5] = dup2(w1.y); wd[6] = dup2(w1.z); wd[7] = dup2(w1.w);
#pragma unroll
            for (int j = 0; j < 8; j++) {
                acc[j][0] = fma2(a2[0], wd[j], acc[j][0]);
                acc[j][1] = fma2(a2[1], wd[j], acc[j][1]);
            }
        }
        __syncthreads();
    }

    float* P = g_part + ((size_t)(l*8 + slice)*GG + nb)*BB;
#pragma unroll
    for (int j = 0; j < 8; j++) {
        ulonglong2 v; v.x = acc[j][0]; v.y = acc[j][1];
        *(ulonglong2*)&P[(size_t)(n0 + j)*BB + b0] = v;
    }
}

// ---------------- wavefront cell: LSTM + BN(train) + locked dropout ----------
__global__ void __launch_bounds__(256) k_cell_wave(int d,
    const float* __restrict__ b2, const float* __restrict__ b3,
    const float* __restrict__ gm0, const float* __restrict__ bt0, const float* __restrict__ mk0,
    const float* __restrict__ gm1, const float* __restrict__ bt1, const float* __restrict__ mk1,
    const float* __restrict__ gm2, const float* __restrict__ bt2, const float* __restrict__ mk2)
{
    int l = blockIdx.y;
    int t = d - l;
    if (t < 0 || t >= TS) return;
    int tid = threadIdx.x;
    int jl = tid >> 4, bq = tid & 15;
    int j = blockIdx.x * 16 + jl;
    int b0 = bq * 4;
    const float* biasP = (l == 1) ? b2 : b3;
    const float* gmP = (l == 0) ? gm0 : (l == 1) ? gm1 : gm2;
    const float* btP = (l == 0) ? bt0 : (l == 1) ? bt1 : bt2;
    const float* mkP = (l == 0) ? mk0 : (l == 1) ? mk1 : mk2;

    float ga[4][4];
#pragma unroll
    for (int g = 0; g < 4; g++) {
        int n = (g << 9) + j;
        float4 s;
        if (l == 0) {
            s = *(const float4*)&g_Xg1[(size_t)t*(GG*BB) + (size_t)n*BB + b0];
        } else {
            float bv = biasP[n];
            s = make_float4(bv, bv, bv, bv);
        }
        const float* pp = g_part + ((size_t)(l*8)*GG + n)*BB + b0;
        if (l == 0) {
#pragma unroll
            for (int sl = 0; sl < 4; sl++) {
                float4 v = *(const float4*)(pp + (size_t)sl*(GG*BB));
                s.x += v.x; s.y += v.y; s.z += v.z; s.w += v.w;
            }
        } else {
#pragma unroll
            for (int sl = 0; sl < 8; sl++) {
                float4 v = *(const float4*)(pp + (size_t)sl*(GG*BB));
                s.x += v.x; s.y += v.y; s.z += v.z; s.w += v.w;
            }
        }
        ga[g][0] = s.x; ga[g][1] = s.y; ga[g][2] = s.z; ga[g][3] = s.w;
    }

    float* hP = g_h + l*HH*BB + j*BB + b0;
    float* cP = g_c + l*HH*BB + j*BB + b0;
    float4 cprev = *(const float4*)cP;
    float cpv[4] = {cprev.x, cprev.y, cprev.z, cprev.w};
    float hh[4], ccv[4];
#pragma unroll
    for (int e = 0; e < 4; e++) {
        float iv = 1.f / (1.f + expf(-ga[0][e]));
        float fv = 1.f / (1.f + expf(-ga[1][e]));
        float gv = tanhf(ga[2][e]);
        float ov = 1.f / (1.f + expf(-ga[3][e]));
        float cc = fv * cpv[e] + iv * gv;
        ccv[e] = cc;
        hh[e] = ov * tanhf(cc);
    }
    *(float4*)cP = make_float4(ccv[0], ccv[1], ccv[2], ccv[3]);
    *(float4*)hP = make_float4(hh[0], hh[1], hh[2], hh[3]);

    float sum = hh[0] + hh[1] + hh[2] + hh[3];
    float sq  = hh[0]*hh[0] + hh[1]*hh[1] + hh[2]*hh[2] + hh[3]*hh[3];
#pragma unroll
    for (int o = 8; o; o >>= 1) {
        sum += __shfl_down_sync(0xffffffffu, sum, o, 16);
        sq  += __shfl_down_sync(0xffffffffu, sq,  o, 16);
    }
    sum = __shfl_sync(0xffffffffu, sum, 0, 16);
    sq  = __shfl_sync(0xffffffffu, sq,  0, 16);
    float mu  = sum * (1.f / BB);
    float var = sq  * (1.f / BB) - mu * mu;
    float rs  = rsqrtf(var + EPSN);
    float gmv = gmP[j], btv = btP[j];

    if (l < 2) {
        float hd[4];
#pragma unroll
        for (int e = 0; e < 4; e++)
            hd[e] = (gmv * (hh[e] - mu) * rs + btv) * mkP[(b0+e)*HH + j];
        *(float4*)&g_hd[l*HH*BB + j*BB + b0] = make_float4(hd[0], hd[1], hd[2], hd[3]);
    } else {
#pragma unroll
        for (int e = 0; e < 4; e++) {
            float hd = (gmv * (hh[e] - mu) * rs + btv) * mkP[(b0+e)*HH + j];
            g_Hout[((size_t)t*BB + b0 + e)*HH + j] = hd;
        }
    }
}

// ---------------- loss: mean NLL over 6400 rows of 8000 logits --------------
__global__ void k_loss(const int* __restrict__ x, float* out) {
    int r = blockIdx.x;
    int t = r >> 6, b = r & 63;
    const float* row = &g_logits[(size_t)r * VV];
    int tid = threadIdx.x;
    float m = -INFINITY, s = 0.f;
    for (int v = tid; v < VV; v += 256) {
        float xv = row[v];
        if (xv > m) { s = s * expf(m - xv) + 1.f; m = xv; }
        else s += expf(xv - m);
    }
    __shared__ float sm[256], ss[256];
    sm[tid] = m; ss[tid] = s;
    __syncthreads();
    for (int o = 128; o; o >>= 1) {
        if (tid < o) {
            float m2 = sm[tid + o], s2 = ss[tid + o];
            float mm = fmaxf(sm[tid], m2);
            ss[tid] = ss[tid] * expf(sm[tid] - mm) + s2 * expf(m2 - mm);
            sm[tid] = mm;
        }
        __syncthreads();
    }
    if (tid == 0) {
        int tgt = x[b*TT + t + 1];
        float lse = sm[0] + logf(ss[0]);
        atomicAdd(out, (lse - row[tgt]) * (1.f / MM));
    }
}

// ---------------- transpose [t*64+b][v] -> out[b][v][t] ---------------------
__global__ void k_transpose(float* __restrict__ outLogits) {
    int b = blockIdx.x;
    int v0 = blockIdx.y * 32;
    __shared__ float tile[32 * 101];
    int tid = threadIdx.x;
    for (int idx = tid; idx < 3200; idx += 256) {
        int t = idx >> 5, vi = idx & 31;
        tile[vi*101 + t] = g_logits[(size_t)(t*BB + b)*VV + v0 + vi];
    }
    __syncthreads();
    for (int idx = tid; idx < 3200; idx += 256) {
        int vi = idx / 100, t = idx - vi*100;
        outLogits[(size_t)b*VV*TS + (size_t)(v0 + vi)*TS + t] = tile[vi*101 + t];
    }
}

// ---------------- launch ------------------------------------------------------
extern "C" void kernel_launch(void* const* d_in, const int* in_sizes, int n_in,
                              void* d_out, int out_size) {
    const int*   x   = (const int*)d_in[0];
    const float* emb = (const float*)d_in[1];
    const float* Wd  = (const float*)d_in[2];
    const float* bd  = (const float*)d_in[3];
    const float* Wih[3] = {(const float*)d_in[4],  (const float*)d_in[10], (const float*)d_in[16]};
    const float* Whh[3] = {(const float*)d_in[5],  (const float*)d_in[11], (const float*)d_in[17]};
    const float* bl[3]  = {(const float*)d_in[6],  (const float*)d_in[12], (const float*)d_in[18]};
    const float* gm[3]  = {(const float*)d_in[7],  (const float*)d_in[13], (const float*)d_in[19]};
    const float* bt[3]  = {(const float*)d_in[8],  (const float*)d_in[14], (const float*)d_in[20]};
    const float* mk[3]  = {(const float*)d_in[9],  (const float*)d_in[15], (const float*)d_in[21]};

    float* out = (float*)d_out;
    int hasLoss = (out_size & 1) ? 1 : 0;   // 51,200,001 odd => loss + logits
    float* outLogits = out + hasLoss;

    k_init<<<(3*HH*BB + 255)/256, 256>>>(out, hasLoss);
    k_embed<<<(MM*(HH/4) + 255)/256, 256>>>(x, emb);
    k_gemm_xg1<<<dim3(GG/128, MM/128), 256>>>(Wih[0], bl[0]);

    // wavefront over diagonals d = t + l, d in [0, TS+2)
    for (int d = 0; d < TS + 2; d++) {
        k_gemm_wave<<<dim3(16, 8, 3), 256>>>(d, Whh[0], Wih[1], Whh[1], Wih[2], Whh[2]);
        k_cell_wave<<<dim3(32, 3), 256>>>(d, bl[1], bl[2],
                                          gm[0], bt[0], mk[0],
                                          gm[1], bt[1], mk[1],
                                          gm[2], bt[2], mk[2]);
    }

    // decoder on tensor cores (TF32)
    k_dec_tc<<<dim3((VV + 127)/128, MM/128), 256>>>(Wd, bd);
    if (hasLoss) k_loss<<<MM, 256>>>(x, out);
    k_transpose<<<dim3(BB, VV/32), 256>>>(outLogits);
}

// round 9
// speedup vs baseline: 2.0943x; 1.2628x over previous
#include <cuda_runtime.h>
#include <cuda_bf16.h>
#include <math.h>

#define BB 64
#define TT 101
#define TS 100
#define VV 8000
#define HH 512
#define GG 2048
#define MM (TS*BB)   // 6400
#define EPSN 1e-5f

typedef unsigned long long ull;

// ---------------- device scratch (static; no runtime allocation) -------------
__device__ float g_e[MM*HH];                     // [m][h] embedded inputs, m = t*64+b
__device__ float g_Xg1[(size_t)GG*MM];           // [t][n][b] precomputed e@Wih1^T + b1
__device__ float g_Hout[MM*HH];                  // [m][h] layer-3 bn*mask output per step
__device__ float g_logits[(size_t)MM*VV];        // [m][v]
__device__ float g_part[(size_t)3*4*GG*BB];      // [layer][slice][n][b] split-K partials
__device__ float g_h[3*HH*BB];                   // [layer][j][b]
__device__ float g_c[3*HH*BB];                   // [layer][j][b]
__device__ float g_hd[2*HH*BB];                  // [layer][j][b]

// ---------------- f32x2 / tf32 / bf16 helpers ---------------------------------
__device__ __forceinline__ ull fma2(ull a, ull b, ull c) {
    ull d;
    asm("fma.rn.f32x2 %0, %1, %2, %3;" : "=l"(d) : "l"(a), "l"(b), "l"(c));
    return d;
}
__device__ __forceinline__ ull pack2(float x, float y) {
    ull r;
    asm("mov.b64 %0, {%1, %2};" : "=l"(r) : "f"(x), "f"(y));
    return r;
}
__device__ __forceinline__ float2 unpack2(ull v) {
    float2 r;
    asm("mov.b64 {%0, %1}, %2;" : "=f"(r.x), "=f"(r.y) : "l"(v));
    return r;
}
__device__ __forceinline__ unsigned tf32c(float x) {
    unsigned u;
    asm("cvt.rna.tf32.f32 %0, %1;" : "=r"(u) : "f"(x));
    return u;
}
__device__ __forceinline__ void mma_tf32(float* c, const unsigned* a, const unsigned* b) {
    asm("mma.sync.aligned.m16n8k8.row.col.f32.tf32.tf32.f32 "
        "{%0,%1,%2,%3}, {%4,%5,%6,%7}, {%8,%9}, {%0,%1,%2,%3};"
        : "+f"(c[0]), "+f"(c[1]), "+f"(c[2]), "+f"(c[3])
        : "r"(a[0]), "r"(a[1]), "r"(a[2]), "r"(a[3]), "r"(b[0]), "r"(b[1]));
}
__device__ __forceinline__ void mma_bf16(float* c, const unsigned* a, const unsigned* b) {
    asm("mma.sync.aligned.m16n8k16.row.col.f32.bf16.bf16.f32 "
        "{%0,%1,%2,%3}, {%4,%5,%6,%7}, {%8,%9}, {%0,%1,%2,%3};"
        : "+f"(c[0]), "+f"(c[1]), "+f"(c[2]), "+f"(c[3])
        : "r"(a[0]), "r"(a[1]), "r"(a[2]), "r"(a[3]), "r"(b[0]), "r"(b[1]));
}
__device__ __forceinline__ void ldsm4(unsigned* r, unsigned addr) {
    asm volatile("ldmatrix.sync.aligned.m8n8.x4.shared.b16 {%0,%1,%2,%3}, [%4];"
                 : "=r"(r[0]), "=r"(r[1]), "=r"(r[2]), "=r"(r[3]) : "r"(addr));
}
__device__ __forceinline__ void bsplit(float x, __nv_bfloat16& hi, __nv_bfloat16& lo) {
    hi = __float2bfloat16(x);
    lo = __float2bfloat16(x - __bfloat162float(hi));
}

// ---------------- init: zero states + loss slot ------------------------------
__global__ void k_init(float* out, int hasLoss) {
    int i = blockIdx.x * blockDim.x + threadIdx.x;
    if (i < 3*HH*BB) { g_h[i] = 0.f; g_c[i] = 0.f; }
    if (i == 0 && hasLoss) out[0] = 0.f;
}

// ---------------- embedding gather -------------------------------------------
__global__ void k_embed(const int* x, const float* emb) {
    int i = blockIdx.x * blockDim.x + threadIdx.x;
    if (i >= MM * (HH/4)) return;
    int m  = i / (HH/4);
    int hq = i % (HH/4);
    int t = m / BB, b = m % BB;
    int tok = x[b*TT + t];
    ((float4*)g_e)[(size_t)m*(HH/4) + hq] =
        ((const float4*)emb)[(size_t)tok*(HH/4) + hq];
}

// ---------------- Xg1 SGEMM (fp32 f32x2, exact): 128x128 tile ----------------
__global__ void __launch_bounds__(256) k_gemm_xg1(const float* __restrict__ Bw,
                                                  const float* __restrict__ bias) {
    const float* A = g_e;
    __shared__ __align__(16) float Ast[16][132];
    __shared__ __align__(16) ull   Bst2[16][132];
    int tid = threadIdx.x;
    int mBase = blockIdx.y * 128, nBase = blockIdx.x * 128;
    int lr = tid >> 2, lc = (tid & 3) * 4;
    int m0 = (tid >> 4) * 8, n0 = (tid & 15) * 8;
    ull acc[4][8];
#pragma unroll
    for (int i = 0; i < 4; i++)
#pragma unroll
        for (int j = 0; j < 8; j++) acc[i][j] = 0ull;

    for (int kb = 0; kb < 512; kb += 16) {
        float4 av0 = *(const float4*)&A[(size_t)(mBase + lr)*512 + kb + lc];
        float4 av1 = *(const float4*)&A[(size_t)(mBase + lr + 64)*512 + kb + lc];
        float4 bv0 = *(const float4*)&Bw[(size_t)(nBase + lr)*512 + kb + lc];
        float4 bv1 = *(const float4*)&Bw[(size_t)(nBase + lr + 64)*512 + kb + lc];
        __syncthreads();
        Ast[lc+0][lr] = av0.x; Ast[lc+1][lr] = av0.y; Ast[lc+2][lr] = av0.z; Ast[lc+3][lr] = av0.w;
        Ast[lc+0][lr+64] = av1.x; Ast[lc+1][lr+64] = av1.y; Ast[lc+2][lr+64] = av1.z; Ast[lc+3][lr+64] = av1.w;
        Bst2[lc+0][lr] = pack2(bv0.x, bv0.x); Bst2[lc+1][lr] = pack2(bv0.y, bv0.y);
        Bst2[lc+2][lr] = pack2(bv0.z, bv0.z); Bst2[lc+3][lr] = pack2(bv0.w, bv0.w);
        Bst2[lc+0][lr+64] = pack2(bv1.x, bv1.x); Bst2[lc+1][lr+64] = pack2(bv1.y, bv1.y);
        Bst2[lc+2][lr+64] = pack2(bv1.z, bv1.z); Bst2[lc+3][lr+64] = pack2(bv1.w, bv1.w);
        __syncthreads();
#pragma unroll
        for (int kk = 0; kk < 16; kk++) {
            ull a2[4], w2[8];
#pragma unroll
            for (int i = 0; i < 4; i++) a2[i] = *(const ull*)&Ast[kk][m0 + 2*i];
#pragma unroll
            for (int j = 0; j < 8; j++) w2[j] = Bst2[kk][n0 + j];
#pragma unroll
            for (int i = 0; i < 4; i++)
#pragma unroll
                for (int j = 0; j < 8; j++) acc[i][j] = fma2(a2[i], w2[j], acc[i][j]);
        }
    }

#pragma unroll
    for (int j = 0; j < 8; j++) {
        int n = nBase + n0 + j;
        float bb = bias[n];
#pragma unroll
        for (int i = 0; i < 4; i++) {
            int m = mBase + m0 + 2*i;
            float2 v = unpack2(acc[i][j]);
            v.x += bb; v.y += bb;
            int tt = m >> 6, bc = m & 63;
            *(float2*)&g_Xg1[(size_t)tt*(GG*BB) + (size_t)n*BB + bc] = v;
        }
    }
}

// ---------------- decoder GEMM: TF32 tensor cores -----------------------------
__global__ void __launch_bounds__(256) k_dec_tc(const float* __restrict__ Wd,
                                                const float* __restrict__ bd) {
    __shared__ unsigned Ast[32*136];
    __shared__ unsigned Bst[32*136];
    int tid = threadIdx.x;
    int warp = tid >> 5, lane = tid & 31;
    int gid = lane >> 2, tig = lane & 3;
    int mBase = blockIdx.y * 128, nBase = blockIdx.x * 128;
    int wm = (warp >> 2) * 64, wn = (warp & 3) * 32;

    float c[4][4][4];
#pragma unroll
    for (int i = 0; i < 4; i++)
#pragma unroll
        for (int j = 0; j < 4; j++)
#pragma unroll
            for (int e = 0; e < 4; e++) c[i][j][e] = 0.f;

    int srow = tid & 127;
    int half = tid >> 7;
    int nIdx = nBase + srow;
    bool nOk = nIdx < VV;
    const float* aRow = &g_Hout[(size_t)(mBase + srow)*HH];
    const float* bRow = &Wd[(size_t)(nOk ? nIdx : 0)*HH];

    for (int kc = 0; kc < HH; kc += 32) {
        float4 av[4], bv[4];
#pragma unroll
        for (int i = 0; i < 4; i++) {
            av[i] = *(const float4*)&aRow[kc + half*16 + i*4];
            float4 b = *(const float4*)&bRow[kc + half*16 + i*4];
            if (!nOk) b = make_float4(0.f, 0.f, 0.f, 0.f);
            bv[i] = b;
        }
        __syncthreads();
#pragma unroll
        for (int i = 0; i < 4; i++) {
            int k = half*16 + i*4;
            Ast[(k+0)*136 + srow] = tf32c(av[i].x);
            Ast[(k+1)*136 + srow] = tf32c(av[i].y);
            Ast[(k+2)*136 + srow] = tf32c(av[i].z);
            Ast[(k+3)*136 + srow] = tf32c(av[i].w);
            Bst[(k+0)*136 + srow] = tf32c(bv[i].x);
            Bst[(k+1)*136 + srow] = tf32c(bv[i].y);
            Bst[(k+2)*136 + srow] = tf32c(bv[i].z);
            Bst[(k+3)*136 + srow] = tf32c(bv[i].w);
        }
        __syncthreads();
#pragma unroll
        for (int ks = 0; ks < 32; ks += 8) {
            unsigned a[4][4], b[4][2];
            int r0 = (ks + tig)*136, r1 = (ks + tig + 4)*136;
#pragma unroll
            for (int i = 0; i < 4; i++) {
                int mo = wm + i*16 + gid;
                a[i][0] = Ast[r0 + mo]; a[i][1] = Ast[r0 + mo + 8];
                a[i][2] = Ast[r1 + mo]; a[i][3] = Ast[r1 + mo + 8];
            }
#pragma unroll
            for (int j = 0; j < 4; j++) {
                int no = wn + j*8 + gid;
                b[j][0] = Bst[r0 + no];
                b[j][1] = Bst[r1 + no];
            }
#pragma unroll
            for (int i = 0; i < 4; i++)
#pragma unroll
                for (int j = 0; j < 4; j++)
                    mma_tf32(c[i][j], a[i], b[j]);
        }
    }

#pragma unroll
    for (int i = 0; i < 4; i++) {
        int r0 = mBase + wm + i*16 + gid;
#pragma unroll
        for (int j = 0; j < 4; j++) {
            int n = nBase + wn + j*8 + 2*tig;
            if (n < VV) {
                float2 bb = *(const float2*)&bd[n];
                float2 v0; v0.x = c[i][j][0] + bb.x; v0.y = c[i][j][1] + bb.y;
                float2 v1; v1.x = c[i][j][2] + bb.x; v1.y = c[i][j][3] + bb.y;
                *(float2*)&g_logits[(size_t)r0*VV + n]       = v0;
                *(float2*)&g_logits[(size_t)(r0 + 8)*VV + n] = v1;
            }
        }
    }
}

// ---------------- wavefront GEMM: bf16 split-3 tensor cores -------------------
// grid (16 n-tiles, 4 K-slices, 3 layers), block 256.
// CTA tile 128n x 64b x 256k, chunked 32k through smem (bf16 hi/lo, 80B rows).
// W.h ~= Whi.hhi + Whi.hlo + Wlo.hhi  (per-product err ~2^-16, near-fp32)
// Layer 0: K=512 -> slices 0..1 (Whh1). Layers 1,2: 0..1 Wih, 2..3 Whh.
__global__ void __launch_bounds__(256) k_gemm_wave_tc(int d,
    const float* __restrict__ Whh1,
    const float* __restrict__ Wih2, const float* __restrict__ Whh2,
    const float* __restrict__ Wih3, const float* __restrict__ Whh3)
{
    int l = blockIdx.z;
    int t = d - l;
    if (t < 0 || t >= TS) return;
    int slice = blockIdx.y;
    if (l == 0 && slice >= 2) return;

    const float* A; const float* W;
    if (l == 0) {
        A = g_h + slice*256*BB;
        W = Whh1 + slice*256;
    } else if (slice < 2) {
        A = g_hd + (l-1)*HH*BB + slice*256*BB;
        W = ((l == 1) ? Wih2 : Wih3) + slice*256;
    } else {
        A = g_h + l*HH*BB + (slice-2)*256*BB;
        W = ((l == 1) ? Whh2 : Whh3) + (slice-2)*256;
    }
    int nb = blockIdx.x * 128;
    int tid = threadIdx.x;
    int lane = tid & 31, warp = tid >> 5;
    int mwarp = warp >> 1, bwarp = warp & 1;   // 4 n-warps x 2 b-warps

    // smem: rows padded to 40 bf16 (80B stride; sigma=5 odd => ldmatrix conflict-free)
    __shared__ __align__(16) __nv_bfloat16 sWhi[128*40];
    __shared__ __align__(16) __nv_bfloat16 sWlo[128*40];
    __shared__ __align__(16) __nv_bfloat16 sAhi[64*40];
    __shared__ __align__(16) __nv_bfloat16 sAlo[64*40];
    unsigned bWhi = (unsigned)__cvta_generic_to_shared(sWhi);
    unsigned bWlo = (unsigned)__cvta_generic_to_shared(sWlo);
    unsigned bAhi = (unsigned)__cvta_generic_to_shared(sAhi);
    unsigned bAlo = (unsigned)__cvta_generic_to_shared(sAlo);

    float acc[2][4][4];
#pragma unroll
    for (int mt = 0; mt < 2; mt++)
#pragma unroll
        for (int j = 0; j < 4; j++)
#pragma unroll
            for (int e = 0; e < 4; e++) acc[mt][j][e] = 0.f;

    // ldmatrix lane address components
    int aRow = mwarp*32 + (lane & 15);           // + mt*16
    int aColHalf = (lane >> 4) * 16;             // bytes
    int bSel = lane >> 3, bL = lane & 7;
    int bRowOff = (bSel >> 1) * 8 + bL;          // within j-pair
    int bColHalf = (bSel & 1) * 16;              // bytes

    for (int kc = 0; kc < 256; kc += 32) {
        // ---- stage W [128n][32k] hi/lo ----
#pragma unroll
        for (int i = 0; i < 4; i++) {
            int s = tid + i*256;
            int n = s >> 3, kq = s & 7;
            float4 w = *(const float4*)&W[(size_t)(nb + n)*HH + kc + kq*4];
            __nv_bfloat16 h0,l0,h1,l1,h2,l2,h3,l3;
            bsplit(w.x, h0, l0); bsplit(w.y, h1, l1);
            bsplit(w.z, h2, l2); bsplit(w.w, h3, l3);
            int o = n*40 + kq*4;
            *(__nv_bfloat162*)&sWhi[o]   = __nv_bfloat162(h0, h1);
            *(__nv_bfloat162*)&sWhi[o+2] = __nv_bfloat162(h2, h3);
            *(__nv_bfloat162*)&sWlo[o]   = __nv_bfloat162(l0, l1);
            *(__nv_bfloat162*)&sWlo[o+2] = __nv_bfloat162(l2, l3);
        }
        // ---- stage A transposed [64b][32k] hi/lo ----
#pragma unroll
        for (int i = 0; i < 2; i++) {
            int s = tid + i*256;
            int b = s >> 3, kq = s & 7;
            float a0 = A[(size_t)(kc + kq*4 + 0)*BB + b];
            float a1 = A[(size_t)(kc + kq*4 + 1)*BB + b];
            float a2 = A[(size_t)(kc + kq*4 + 2)*BB + b];
            float a3 = A[(size_t)(kc + kq*4 + 3)*BB + b];
            __nv_bfloat16 h0,l0,h1,l1,h2,l2,h3,l3;
            bsplit(a0, h0, l0); bsplit(a1, h1, l1);
            bsplit(a2, h2, l2); bsplit(a3, h3, l3);
            int o = b*40 + kq*4;
            *(__nv_bfloat162*)&sAhi[o]   = __nv_bfloat162(h0, h1);
            *(__nv_bfloat162*)&sAhi[o+2] = __nv_bfloat162(h2, h3);
            *(__nv_bfloat162*)&sAlo[o]   = __nv_bfloat162(l0, l1);
            *(__nv_bfloat162*)&sAlo[o+2] = __nv_bfloat162(l2, l3);
        }
        __syncthreads();

#pragma unroll
        for (int kq = 0; kq < 2; kq++) {      // two k16 steps
            unsigned wa_h[2][4], wa_l[2][4];
#pragma unroll
            for (int mt = 0; mt < 2; mt++) {
                unsigned off = (unsigned)((aRow + mt*16)*80 + kq*32 + aColHalf);
                ldsm4(wa_h[mt], bWhi + off);
                ldsm4(wa_l[mt], bWlo + off);
            }
            unsigned hb_h[4][2], hb_l[4][2];
#pragma unroll
            for (int j2 = 0; j2 < 2; j2++) {
                unsigned off = (unsigned)((bwarp*32 + j2*16 + bRowOff)*80 + kq*32 + bColHalf);
                unsigned q[4];
                ldsm4(q, bAhi + off);
                hb_h[2*j2][0] = q[0]; hb_h[2*j2][1] = q[1];
                hb_h[2*j2+1][0] = q[2]; hb_h[2*j2+1][1] = q[3];
                ldsm4(q, bAlo + off);
                hb_l[2*j2][0] = q[0]; hb_l[2*j2][1] = q[1];
                hb_l[2*j2+1][0] = q[2]; hb_l[2*j2+1][1] = q[3];
            }
#pragma unroll
            for (int mt = 0; mt < 2; mt++)
#pragma unroll
                for (int j = 0; j < 4; j++) {
                    mma_bf16(acc[mt][j], wa_h[mt], hb_h[j]);
                    mma_bf16(acc[mt][j], wa_h[mt], hb_l[j]);
                    mma_bf16(acc[mt][j], wa_l[mt], hb_h[j]);
                }
        }
        __syncthreads();
    }

    // ---- store partials [n][b] ----
    float* P = g_part + ((size_t)(l*4 + slice)*GG + nb)*BB;
    int g = lane >> 2, tg = lane & 3;
#pragma unroll
    for (int mt = 0; mt < 2; mt++) {
        int n = mwarp*32 + mt*16 + g;
#pragma unroll
        for (int j = 0; j < 4; j++) {
            int b = bwarp*32 + j*8 + 2*tg;
            float2 v0; v0.x = acc[mt][j][0]; v0.y = acc[mt][j][1];
            float2 v1; v1.x = acc[mt][j][2]; v1.y = acc[mt][j][3];
            *(float2*)&P[(size_t)n*BB + b]       = v0;
            *(float2*)&P[(size_t)(n + 8)*BB + b] = v1;
        }
    }
}

// ---------------- wavefront cell: LSTM + BN(train) + locked dropout ----------
__global__ void __launch_bounds__(256) k_cell_wave(int d,
    const float* __restrict__ b2, const float* __restrict__ b3,
    const float* __restrict__ gm0, const float* __restrict__ bt0, const float* __restrict__ mk0,
    const float* __restrict__ gm1, const float* __restrict__ bt1, const float* __restrict__ mk1,
    const float* __restrict__ gm2, const float* __restrict__ bt2, const float* __restrict__ mk2)
{
    int l = blockIdx.y;
    int t = d - l;
    if (t < 0 || t >= TS) return;
    int tid = threadIdx.x;
    int jl = tid >> 4, bq = tid & 15;
    int j = blockIdx.x * 16 + jl;
    int b0 = bq * 4;
    const float* biasP = (l == 1) ? b2 : b3;
    const float* gmP = (l == 0) ? gm0 : (l == 1) ? gm1 : gm2;
    const float* btP = (l == 0) ? bt0 : (l == 1) ? bt1 : bt2;
    const float* mkP = (l == 0) ? mk0 : (l == 1) ? mk1 : mk2;

    float ga[4][4];
#pragma unroll
    for (int g = 0; g < 4; g++) {
        int n = (g << 9) + j;
        float4 s;
        if (l == 0) {
            s = *(const float4*)&g_Xg1[(size_t)t*(GG*BB) + (size_t)n*BB + b0];
        } else {
            float bv = biasP[n];
            s = make_float4(bv, bv, bv, bv);
        }
        const float* pp = g_part + ((size_t)(l*4)*GG + n)*BB + b0;
        if (l == 0) {
#pragma unroll
            for (int sl = 0; sl < 2; sl++) {
                float4 v = *(const float4*)(pp + (size_t)sl*(GG*BB));
                s.x += v.x; s.y += v.y; s.z += v.z; s.w += v.w;
            }
        } else {
#pragma unroll
            for (int sl = 0; sl < 4; sl++) {
                float4 v = *(const float4*)(pp + (size_t)sl*(GG*BB));
                s.x += v.x; s.y += v.y; s.z += v.z; s.w += v.w;
            }
        }
        ga[g][0] = s.x; ga[g][1] = s.y; ga[g][2] = s.z; ga[g][3] = s.w;
    }

    float* hP = g_h + l*HH*BB + j*BB + b0;
    float* cP = g_c + l*HH*BB + j*BB + b0;
    float4 cprev = *(const float4*)cP;
    float cpv[4] = {cprev.x, cprev.y, cprev.z, cprev.w};
    float hh[4], ccv[4];
#pragma unroll
    for (int e = 0; e < 4; e++) {
        float iv = 1.f / (1.f + expf(-ga[0][e]));
        float fv = 1.f / (1.f + expf(-ga[1][e]));
        float gv = tanhf(ga[2][e]);
        float ov = 1.f / (1.f + expf(-ga[3][e]));
        float cc = fv * cpv[e] + iv * gv;
        ccv[e] = cc;
        hh[e] = ov * tanhf(cc);
    }
    *(float4*)cP = make_float4(ccv[0], ccv[1], ccv[2], ccv[3]);
    *(float4*)hP = make_float4(hh[0], hh[1], hh[2], hh[3]);

    float sum = hh[0] + hh[1] + hh[2] + hh[3];
    float sq  = hh[0]*hh[0] + hh[1]*hh[1] + hh[2]*hh[2] + hh[3]*hh[3];
#pragma unroll
    for (int o = 8; o; o >>= 1) {
        sum += __shfl_down_sync(0xffffffffu, sum, o, 16);
        sq  += __shfl_down_sync(0xffffffffu, sq,  o, 16);
    }
    sum = __shfl_sync(0xffffffffu, sum, 0, 16);
    sq  = __shfl_sync(0xffffffffu, sq,  0, 16);
    float mu  = sum * (1.f / BB);
    float var = sq  * (1.f / BB) - mu * mu;
    float rs  = rsqrtf(var + EPSN);
    float gmv = gmP[j], btv = btP[j];

    if (l < 2) {
        float hd[4];
#pragma unroll
        for (int e = 0; e < 4; e++)
            hd[e] = (gmv * (hh[e] - mu) * rs + btv) * mkP[(b0+e)*HH + j];
        *(float4*)&g_hd[l*HH*BB + j*BB + b0] = make_float4(hd[0], hd[1], hd[2], hd[3]);
    } else {
#pragma unroll
        for (int e = 0; e < 4; e++) {
            float hd = (gmv * (hh[e] - mu) * rs + btv) * mkP[(b0+e)*HH + j];
            g_Hout[((size_t)t*BB + b0 + e)*HH + j] = hd;
        }
    }
}

// ---------------- loss: mean NLL over 6400 rows of 8000 logits --------------
__global__ void k_loss(const int* __restrict__ x, float* out) {
    int r = blockIdx.x;
    int t = r >> 6, b = r & 63;
    const float* row = &g_logits[(size_t)r * VV];
    int tid = threadIdx.x;
    float m = -INFINITY, s = 0.f;
    for (int v = tid; v < VV; v += 256) {
        float xv = row[v];
        if (xv > m) { s = s * expf(m - xv) + 1.f; m = xv; }
        else s += expf(xv - m);
    }
    __shared__ float sm[256], ss[256];
    sm[tid] = m; ss[tid] = s;
    __syncthreads();
    for (int o = 128; o; o >>= 1) {
        if (tid < o) {
            float m2 = sm[tid + o], s2 = ss[tid + o];
            float mm = fmaxf(sm[tid], m2);
            ss[tid] = ss[tid] * expf(sm[tid] - mm) + s2 * expf(m2 - mm);
            sm[tid] = mm;
        }
        __syncthreads();
    }
    if (tid == 0) {
        int tgt = x[b*TT + t + 1];
        float lse = sm[0] + logf(ss[0]);
        atomicAdd(out, (lse - row[tgt]) * (1.f / MM));
    }
}

// ---------------- transpose [t*64+b][v] -> out[b][v][t] ---------------------
__global__ void k_transpose(float* __restrict__ outLogits) {
    int b = blockIdx.x;
    int v0 = blockIdx.y * 32;
    __shared__ float tile[32 * 101];
    int tid = threadIdx.x;
    for (int idx = tid; idx < 3200; idx += 256) {
        int t = idx >> 5, vi = idx & 31;
        tile[vi*101 + t] = g_logits[(size_t)(t*BB + b)*VV + v0 + vi];
    }
    __syncthreads();
    for (int idx = tid; idx < 3200; idx += 256) {
        int vi = idx / 100, t = idx - vi*100;
        outLogits[(size_t)b*VV*TS + (size_t)(v0 + vi)*TS + t] = tile[vi*101 + t];
    }
}

// ---------------- launch ------------------------------------------------------
extern "C" void kernel_launch(void* const* d_in, const int* in_sizes, int n_in,
                              void* d_out, int out_size) {
    const int*   x   = (const int*)d_in[0];
    const float* emb = (const float*)d_in[1];
    const float* Wd  = (const float*)d_in[2];
    const float* bd  = (const float*)d_in[3];
    const float* Wih[3] = {(const float*)d_in[4],  (const float*)d_in[10], (const float*)d_in[16]};
    const float* Whh[3] = {(const float*)d_in[5],  (const float*)d_in[11], (const float*)d_in[17]};
    const float* bl[3]  = {(const float*)d_in[6],  (const float*)d_in[12], (const float*)d_in[18]};
    const float* gm[3]  = {(const float*)d_in[7],  (const float*)d_in[13], (const float*)d_in[19]};
    const float* bt[3]  = {(const float*)d_in[8],  (const float*)d_in[14], (const float*)d_in[20]};
    const float* mk[3]  = {(const float*)d_in[9],  (const float*)d_in[15], (const float*)d_in[21]};

    float* out = (float*)d_out;
    int hasLoss = (out_size & 1) ? 1 : 0;   // 51,200,001 odd => loss + logits
    float* outLogits = out + hasLoss;

    k_init<<<(3*HH*BB + 255)/256, 256>>>(out, hasLoss);
    k_embed<<<(MM*(HH/4) + 255)/256, 256>>>(x, emb);
    k_gemm_xg1<<<dim3(GG/128, MM/128), 256>>>(Wih[0], bl[0]);

    // wavefront over diagonals d = t + l, d in [0, TS+2)
    for (int d = 0; d < TS + 2; d++) {
        k_gemm_wave_tc<<<dim3(16, 4, 3), 256>>>(d, Whh[0], Wih[1], Whh[1], Wih[2], Whh[2]);
        k_cell_wave<<<dim3(32, 3), 256>>>(d, bl[1], bl[2],
                                          gm[0], bt[0], mk[0],
                                          gm[1], bt[1], mk[1],
                                          gm[2], bt[2], mk[2]);
    }

    // decoder on tensor cores (TF32)
    k_dec_tc<<<dim3((VV + 127)/128, MM/128), 256>>>(Wd, bd);
    if (hasLoss) k_loss<<<MM, 256>>>(x, out);
    k_transpose<<<dim3(BB, VV/32), 256>>>(outLogits);
}

// round 10
// speedup vs baseline: 2.1730x; 1.0376x over previous
#include <cuda_runtime.h>
#include <cuda_bf16.h>
#include <math.h>

#define BB 64
#define TT 101
#define TS 100
#define VV 8000
#define HH 512
#define GG 2048
#define MM (TS*BB)   // 6400
#define EPSN 1e-5f

typedef unsigned long long ull;

// ---------------- device scratch (static; no runtime allocation) -------------
__device__ float g_e[MM*HH];                     // [m][h] embedded inputs
__device__ float g_Xg1[(size_t)GG*MM];           // [t][n][b] e@Wih1^T + b1
__device__ float g_Hout[MM*HH];                  // [m][h] layer-3 output
__device__ float g_logits[(size_t)MM*VV];        // [m][v]
__device__ float g_part[(size_t)3*4*GG*BB];      // [layer][slice][n][b]
__device__ float g_c[3*HH*BB];                   // [layer][j][b] cell state
// bf16 split weights: slots 0:Whh1 1:Wih2 2:Whh2 3:Wih3 4:Whh3, [slot][n][k]
__device__ __align__(16) __nv_bfloat16 g_WspHi[(size_t)5*GG*HH];
__device__ __align__(16) __nv_bfloat16 g_WspLo[(size_t)5*GG*HH];
// bf16 split activations, [layer][b][k]
__device__ __align__(16) __nv_bfloat16 g_hbfHi[3*BB*HH];
__device__ __align__(16) __nv_bfloat16 g_hbfLo[3*BB*HH];
__device__ __align__(16) __nv_bfloat16 g_hdbfHi[2*BB*HH];
__device__ __align__(16) __nv_bfloat16 g_hdbfLo[2*BB*HH];

// ---------------- helpers ------------------------------------------------------
__device__ __forceinline__ ull fma2(ull a, ull b, ull c) {
    ull d;
    asm("fma.rn.f32x2 %0, %1, %2, %3;" : "=l"(d) : "l"(a), "l"(b), "l"(c));
    return d;
}
__device__ __forceinline__ ull pack2(float x, float y) {
    ull r;
    asm("mov.b64 %0, {%1, %2};" : "=l"(r) : "f"(x), "f"(y));
    return r;
}
__device__ __forceinline__ float2 unpack2(ull v) {
    float2 r;
    asm("mov.b64 {%0, %1}, %2;" : "=f"(r.x), "=f"(r.y) : "l"(v));
    return r;
}
__device__ __forceinline__ unsigned tf32c(float x) {
    unsigned u;
    asm("cvt.rna.tf32.f32 %0, %1;" : "=r"(u) : "f"(x));
    return u;
}
__device__ __forceinline__ void mma_tf32(float* c, const unsigned* a, const unsigned* b) {
    asm("mma.sync.aligned.m16n8k8.row.col.f32.tf32.tf32.f32 "
        "{%0,%1,%2,%3}, {%4,%5,%6,%7}, {%8,%9}, {%0,%1,%2,%3};"
        : "+f"(c[0]), "+f"(c[1]), "+f"(c[2]), "+f"(c[3])
        : "r"(a[0]), "r"(a[1]), "r"(a[2]), "r"(a[3]), "r"(b[0]), "r"(b[1]));
}
__device__ __forceinline__ void mma_bf16(float* c, const unsigned* a, const unsigned* b) {
    asm("mma.sync.aligned.m16n8k16.row.col.f32.bf16.bf16.f32 "
        "{%0,%1,%2,%3}, {%4,%5,%6,%7}, {%8,%9}, {%0,%1,%2,%3};"
        : "+f"(c[0]), "+f"(c[1]), "+f"(c[2]), "+f"(c[3])
        : "r"(a[0]), "r"(a[1]), "r"(a[2]), "r"(a[3]), "r"(b[0]), "r"(b[1]));
}
__device__ __forceinline__ void ldsm4(unsigned* r, unsigned addr) {
    asm volatile("ldmatrix.sync.aligned.m8n8.x4.shared.b16 {%0,%1,%2,%3}, [%4];"
                 : "=r"(r[0]), "=r"(r[1]), "=r"(r[2]), "=r"(r[3]) : "r"(addr));
}
__device__ __forceinline__ void bsplit(float x, __nv_bfloat16& hi, __nv_bfloat16& lo) {
    hi = __float2bfloat16(x);
    lo = __float2bfloat16(x - __bfloat162float(hi));
}
__device__ __forceinline__ void cpa16(unsigned dst, const void* src) {
    asm volatile("cp.async.ca.shared.global [%0], [%1], 16;" :: "r"(dst), "l"(src));
}

// ---------------- init: zero states + loss slot ------------------------------
__global__ void k_init(float* out, int hasLoss) {
    int i = blockIdx.x * blockDim.x + threadIdx.x;
    if (i < 3*HH*BB) {
        g_c[i] = 0.f;
        g_hbfHi[i] = __float2bfloat16(0.f);
        g_hbfLo[i] = __float2bfloat16(0.f);
    }
    if (i == 0 && hasLoss) out[0] = 0.f;
}

// ---------------- weight pre-split (once) -------------------------------------
__global__ void k_wsplit(const float* __restrict__ Whh1,
                         const float* __restrict__ Wih2, const float* __restrict__ Whh2,
                         const float* __restrict__ Wih3, const float* __restrict__ Whh3) {
    int i = blockIdx.x * blockDim.x + threadIdx.x;   // float4 index
    const int PER = GG * (HH/4);
    if (i >= 5 * PER) return;
    int slot = i / PER, rem = i - slot * PER;
    const float* M = slot == 0 ? Whh1 : slot == 1 ? Wih2 : slot == 2 ? Whh2
                   : slot == 3 ? Wih3 : Whh3;
    float4 v = ((const float4*)M)[rem];
    __nv_bfloat16 h0,l0,h1,l1,h2,l2,h3,l3;
    bsplit(v.x, h0, l0); bsplit(v.y, h1, l1);
    bsplit(v.z, h2, l2); bsplit(v.w, h3, l3);
    size_t o = (size_t)slot*GG*HH + (size_t)rem*4;
    *(__nv_bfloat162*)&g_WspHi[o]   = __nv_bfloat162(h0, h1);
    *(__nv_bfloat162*)&g_WspHi[o+2] = __nv_bfloat162(h2, h3);
    *(__nv_bfloat162*)&g_WspLo[o]   = __nv_bfloat162(l0, l1);
    *(__nv_bfloat162*)&g_WspLo[o+2] = __nv_bfloat162(l2, l3);
}

// ---------------- embedding gather -------------------------------------------
__global__ void k_embed(const int* x, const float* emb) {
    int i = blockIdx.x * blockDim.x + threadIdx.x;
    if (i >= MM * (HH/4)) return;
    int m  = i / (HH/4);
    int hq = i % (HH/4);
    int t = m / BB, b = m % BB;
    int tok = x[b*TT + t];
    ((float4*)g_e)[(size_t)m*(HH/4) + hq] =
        ((const float4*)emb)[(size_t)tok*(HH/4) + hq];
}

// ---------------- Xg1 SGEMM (fp32 f32x2, exact) -------------------------------
__global__ void __launch_bounds__(256) k_gemm_xg1(const float* __restrict__ Bw,
                                                  const float* __restrict__ bias) {
    const float* A = g_e;
    __shared__ __align__(16) float Ast[16][132];
    __shared__ __align__(16) ull   Bst2[16][132];
    int tid = threadIdx.x;
    int mBase = blockIdx.y * 128, nBase = blockIdx.x * 128;
    int lr = tid >> 2, lc = (tid & 3) * 4;
    int m0 = (tid >> 4) * 8, n0 = (tid & 15) * 8;
    ull acc[4][8];
#pragma unroll
    for (int i = 0; i < 4; i++)
#pragma unroll
        for (int j = 0; j < 8; j++) acc[i][j] = 0ull;

    for (int kb = 0; kb < 512; kb += 16) {
        float4 av0 = *(const float4*)&A[(size_t)(mBase + lr)*512 + kb + lc];
        float4 av1 = *(const float4*)&A[(size_t)(mBase + lr + 64)*512 + kb + lc];
        float4 bv0 = *(const float4*)&Bw[(size_t)(nBase + lr)*512 + kb + lc];
        float4 bv1 = *(const float4*)&Bw[(size_t)(nBase + lr + 64)*512 + kb + lc];
        __syncthreads();
        Ast[lc+0][lr] = av0.x; Ast[lc+1][lr] = av0.y; Ast[lc+2][lr] = av0.z; Ast[lc+3][lr] = av0.w;
        Ast[lc+0][lr+64] = av1.x; Ast[lc+1][lr+64] = av1.y; Ast[lc+2][lr+64] = av1.z; Ast[lc+3][lr+64] = av1.w;
        Bst2[lc+0][lr] = pack2(bv0.x, bv0.x); Bst2[lc+1][lr] = pack2(bv0.y, bv0.y);
        Bst2[lc+2][lr] = pack2(bv0.z, bv0.z); Bst2[lc+3][lr] = pack2(bv0.w, bv0.w);
        Bst2[lc+0][lr+64] = pack2(bv1.x, bv1.x); Bst2[lc+1][lr+64] = pack2(bv1.y, bv1.y);
        Bst2[lc+2][lr+64] = pack2(bv1.z, bv1.z); Bst2[lc+3][lr+64] = pack2(bv1.w, bv1.w);
        __syncthreads();
#pragma unroll
        for (int kk = 0; kk < 16; kk++) {
            ull a2[4], w2[8];
#pragma unroll
            for (int i = 0; i < 4; i++) a2[i] = *(const ull*)&Ast[kk][m0 + 2*i];
#pragma unroll
            for (int j = 0; j < 8; j++) w2[j] = Bst2[kk][n0 + j];
#pragma unroll
            for (int i = 0; i < 4; i++)
#pragma unroll
                for (int j = 0; j < 8; j++) acc[i][j] = fma2(a2[i], w2[j], acc[i][j]);
        }
    }

#pragma unroll
    for (int j = 0; j < 8; j++) {
        int n = nBase + n0 + j;
        float bb = bias[n];
#pragma unroll
        for (int i = 0; i < 4; i++) {
            int m = mBase + m0 + 2*i;
            float2 v = unpack2(acc[i][j]);
            v.x += bb; v.y += bb;
            int tt = m >> 6, bc = m & 63;
            *(float2*)&g_Xg1[(size_t)tt*(GG*BB) + (size_t)n*BB + bc] = v;
        }
    }
}

// ---------------- decoder GEMM: TF32 tensor cores -----------------------------
__global__ void __launch_bounds__(256) k_dec_tc(const float* __restrict__ Wd,
                                                const float* __restrict__ bd) {
    __shared__ unsigned Ast[32*136];
    __shared__ unsigned Bst[32*136];
    int tid = threadIdx.x;
    int warp = tid >> 5, lane = tid & 31;
    int gid = lane >> 2, tig = lane & 3;
    int mBase = blockIdx.y * 128, nBase = blockIdx.x * 128;
    int wm = (warp >> 2) * 64, wn = (warp & 3) * 32;

    float c[4][4][4];
#pragma unroll
    for (int i = 0; i < 4; i++)
#pragma unroll
        for (int j = 0; j < 4; j++)
#pragma unroll
            for (int e = 0; e < 4; e++) c[i][j][e] = 0.f;

    int srow = tid & 127;
    int half = tid >> 7;
    int nIdx = nBase + srow;
    bool nOk = nIdx < VV;
    const float* aRow = &g_Hout[(size_t)(mBase + srow)*HH];
    const float* bRow = &Wd[(size_t)(nOk ? nIdx : 0)*HH];

    for (int kc = 0; kc < HH; kc += 32) {
        float4 av[4], bv[4];
#pragma unroll
        for (int i = 0; i < 4; i++) {
            av[i] = *(const float4*)&aRow[kc + half*16 + i*4];
            float4 b = *(const float4*)&bRow[kc + half*16 + i*4];
            if (!nOk) b = make_float4(0.f, 0.f, 0.f, 0.f);
            bv[i] = b;
        }
        __syncthreads();
#pragma unroll
        for (int i = 0; i < 4; i++) {
            int k = half*16 + i*4;
            Ast[(k+0)*136 + srow] = tf32c(av[i].x);
            Ast[(k+1)*136 + srow] = tf32c(av[i].y);
            Ast[(k+2)*136 + srow] = tf32c(av[i].z);
            Ast[(k+3)*136 + srow] = tf32c(av[i].w);
            Bst[(k+0)*136 + srow] = tf32c(bv[i].x);
            Bst[(k+1)*136 + srow] = tf32c(bv[i].y);
            Bst[(k+2)*136 + srow] = tf32c(bv[i].z);
            Bst[(k+3)*136 + srow] = tf32c(bv[i].w);
        }
        __syncthreads();
#pragma unroll
        for (int ks = 0; ks < 32; ks += 8) {
            unsigned a[4][4], b[4][2];
            int r0 = (ks + tig)*136, r1 = (ks + tig + 4)*136;
#pragma unroll
            for (int i = 0; i < 4; i++) {
                int mo = wm + i*16 + gid;
                a[i][0] = Ast[r0 + mo]; a[i][1] = Ast[r0 + mo + 8];
                a[i][2] = Ast[r1 + mo]; a[i][3] = Ast[r1 + mo + 8];
            }
#pragma unroll
            for (int j = 0; j < 4; j++) {
                int no = wn + j*8 + gid;
                b[j][0] = Bst[r0 + no];
                b[j][1] = Bst[r1 + no];
            }
#pragma unroll
            for (int i = 0; i < 4; i++)
#pragma unroll
                for (int j = 0; j < 4; j++)
                    mma_tf32(c[i][j], a[i], b[j]);
        }
    }

#pragma unroll
    for (int i = 0; i < 4; i++) {
        int r0 = mBase + wm + i*16 + gid;
#pragma unroll
        for (int j = 0; j < 4; j++) {
            int n = nBase + wn + j*8 + 2*tig;
            if (n < VV) {
                float2 bb = *(const float2*)&bd[n];
                float2 v0; v0.x = c[i][j][0] + bb.x; v0.y = c[i][j][1] + bb.y;
                float2 v1; v1.x = c[i][j][2] + bb.x; v1.y = c[i][j][3] + bb.y;
                *(float2*)&g_logits[(size_t)r0*VV + n]       = v0;
                *(float2*)&g_logits[(size_t)(r0 + 8)*VV + n] = v1;
            }
        }
    }
}

// ---------------- wavefront GEMM: bf16 split-3 tensor cores (cp.async staging) -
// grid (16 n-tiles, 4 K-slices, 3 layers), block 256.
// CTA tile 128n x 64b x 256k, chunked 32k. Weights + activations pre-split bf16.
// Layer 0: slices 0..1 (Whh1 k-halves). Layers 1,2: 0..1 Wih, 2..3 Whh.
__global__ void __launch_bounds__(256) k_gemm_wave_tc(int d) {
    int l = blockIdx.z;
    int t = d - l;
    if (t < 0 || t >= TS) return;
    int slice = blockIdx.y;
    if (l == 0 && slice >= 2) return;

    int wslot, kOff;
    const __nv_bfloat16 *aHi, *aLo;
    if (l == 0) {
        wslot = 0; kOff = slice * 256;
        aHi = g_hbfHi;             aLo = g_hbfLo;
    } else if (slice < 2) {
        wslot = 2*l - 1; kOff = slice * 256;
        aHi = g_hdbfHi + (l-1)*BB*HH; aLo = g_hdbfLo + (l-1)*BB*HH;
    } else {
        wslot = 2*l; kOff = (slice - 2) * 256;
        aHi = g_hbfHi + l*BB*HH;   aLo = g_hbfLo + l*BB*HH;
    }
    int nb = blockIdx.x * 128;
    const __nv_bfloat16* wHi = g_WspHi + ((size_t)wslot*GG + nb)*HH + kOff;
    const __nv_bfloat16* wLo = g_WspLo + ((size_t)wslot*GG + nb)*HH + kOff;
    aHi += kOff; aLo += kOff;

    int tid = threadIdx.x;
    int lane = tid & 31, warp = tid >> 5;
    int mwarp = warp >> 1, bwarp = warp & 1;

    __shared__ __align__(16) __nv_bfloat16 sWhi[128*40];
    __shared__ __align__(16) __nv_bfloat16 sWlo[128*40];
    __shared__ __align__(16) __nv_bfloat16 sAhi[64*40];
    __shared__ __align__(16) __nv_bfloat16 sAlo[64*40];
    unsigned bWhi = (unsigned)__cvta_generic_to_shared(sWhi);
    unsigned bWlo = (unsigned)__cvta_generic_to_shared(sWlo);
    unsigned bAhi = (unsigned)__cvta_generic_to_shared(sAhi);
    unsigned bAlo = (unsigned)__cvta_generic_to_shared(sAlo);

    float acc[2][4][4];
#pragma unroll
    for (int mt = 0; mt < 2; mt++)
#pragma unroll
        for (int j = 0; j < 4; j++)
#pragma unroll
            for (int e = 0; e < 4; e++) acc[mt][j][e] = 0.f;

    int aRow = mwarp*32 + (lane & 15);
    int aColHalf = (lane >> 4) * 16;
    int bSel = lane >> 3, bL = lane & 7;
    int bRowOff = (bSel >> 1) * 8 + bL;
    int bColHalf = (bSel & 1) * 16;

    // staging coords
    int wr0 = tid >> 1, wc0 = (tid & 1) * 2;     // W: 2 units/thread/array
    int ar = tid >> 2, ac = tid & 3;             // A: 1 unit/thread/array

    for (int kc = 0; kc < 256; kc += 32) {
        // W [128n][32k] hi/lo : 16B cp.async, 4/thread
#pragma unroll
        for (int u = 0; u < 2; u++) {
            int r = wr0, c = wc0 + u;
            cpa16(bWhi + r*80 + c*16, wHi + (size_t)r*HH + kc + c*8);
            cpa16(bWlo + r*80 + c*16, wLo + (size_t)r*HH + kc + c*8);
        }
        // A [64b][32k] hi/lo : 2/thread
        cpa16(bAhi + ar*80 + ac*16, aHi + (size_t)ar*HH + kc + ac*8);
        cpa16(bAlo + ar*80 + ac*16, aLo + (size_t)ar*HH + kc + ac*8);
        asm volatile("cp.async.commit_group;");
        asm volatile("cp.async.wait_group 0;");
        __syncthreads();

#pragma unroll
        for (int kq = 0; kq < 2; kq++) {
            unsigned wa_h[2][4], wa_l[2][4];
#pragma unroll
            for (int mt = 0; mt < 2; mt++) {
                unsigned off = (unsigned)((aRow + mt*16)*80 + kq*32 + aColHalf);
                ldsm4(wa_h[mt], bWhi + off);
                ldsm4(wa_l[mt], bWlo + off);
            }
            unsigned hb_h[4][2], hb_l[4][2];
#pragma unroll
            for (int j2 = 0; j2 < 2; j2++) {
                unsigned off = (unsigned)((bwarp*32 + j2*16 + bRowOff)*80 + kq*32 + bColHalf);
                unsigned q[4];
                ldsm4(q, bAhi + off);
                hb_h[2*j2][0] = q[0]; hb_h[2*j2][1] = q[1];
                hb_h[2*j2+1][0] = q[2]; hb_h[2*j2+1][1] = q[3];
                ldsm4(q, bAlo + off);
                hb_l[2*j2][0] = q[0]; hb_l[2*j2][1] = q[1];
                hb_l[2*j2+1][0] = q[2]; hb_l[2*j2+1][1] = q[3];
            }
#pragma unroll
            for (int mt = 0; mt < 2; mt++)
#pragma unroll
                for (int j = 0; j < 4; j++) {
                    mma_bf16(acc[mt][j], wa_h[mt], hb_h[j]);
                    mma_bf16(acc[mt][j], wa_h[mt], hb_l[j]);
                    mma_bf16(acc[mt][j], wa_l[mt], hb_h[j]);
                }
        }
        __syncthreads();
    }

    float* P = g_part + ((size_t)(l*4 + slice)*GG + nb)*BB;
    int g = lane >> 2, tg = lane & 3;
#pragma unroll
    for (int mt = 0; mt < 2; mt++) {
        int n = mwarp*32 + mt*16 + g;
#pragma unroll
        for (int j = 0; j < 4; j++) {
            int b = bwarp*32 + j*8 + 2*tg;
            float2 v0; v0.x = acc[mt][j][0]; v0.y = acc[mt][j][1];
            float2 v1; v1.x = acc[mt][j][2]; v1.y = acc[mt][j][3];
            *(float2*)&P[(size_t)n*BB + b]       = v0;
            *(float2*)&P[(size_t)(n + 8)*BB + b] = v1;
        }
    }
}

// ---------------- wavefront cell: LSTM + BN(train) + locked dropout ----------
__global__ void __launch_bounds__(256) k_cell_wave(int d,
    const float* __restrict__ b2, const float* __restrict__ b3,
    const float* __restrict__ gm0, const float* __restrict__ bt0, const float* __restrict__ mk0,
    const float* __restrict__ gm1, const float* __restrict__ bt1, const float* __restrict__ mk1,
    const float* __restrict__ gm2, const float* __restrict__ bt2, const float* __restrict__ mk2)
{
    int l = blockIdx.y;
    int t = d - l;
    if (t < 0 || t >= TS) return;
    int tid = threadIdx.x;
    int jl = tid >> 4, bq = tid & 15;
    int j = blockIdx.x * 16 + jl;
    int b0 = bq * 4;
    const float* biasP = (l == 1) ? b2 : b3;
    const float* gmP = (l == 0) ? gm0 : (l == 1) ? gm1 : gm2;
    const float* btP = (l == 0) ? bt0 : (l == 1) ? bt1 : bt2;
    const float* mkP = (l == 0) ? mk0 : (l == 1) ? mk1 : mk2;

    float ga[4][4];
#pragma unroll
    for (int g = 0; g < 4; g++) {
        int n = (g << 9) + j;
        float4 s;
        if (l == 0) {
            s = *(const float4*)&g_Xg1[(size_t)t*(GG*BB) + (size_t)n*BB + b0];
        } else {
            float bv = biasP[n];
            s = make_float4(bv, bv, bv, bv);
        }
        const float* pp = g_part + ((size_t)(l*4)*GG + n)*BB + b0;
        if (l == 0) {
#pragma unroll
            for (int sl = 0; sl < 2; sl++) {
                float4 v = *(const float4*)(pp + (size_t)sl*(GG*BB));
                s.x += v.x; s.y += v.y; s.z += v.z; s.w += v.w;
            }
        } else {
#pragma unroll
            for (int sl = 0; sl < 4; sl++) {
                float4 v = *(const float4*)(pp + (size_t)sl*(GG*BB));
                s.x += v.x; s.y += v.y; s.z += v.z; s.w += v.w;
            }
        }
        ga[g][0] = s.x; ga[g][1] = s.y; ga[g][2] = s.z; ga[g][3] = s.w;
    }

    float* cP = g_c + l*HH*BB + j*BB + b0;
    float4 cprev = *(const float4*)cP;
    float cpv[4] = {cprev.x, cprev.y, cprev.z, cprev.w};
    float hh[4], ccv[4];
#pragma unroll
    for (int e = 0; e < 4; e++) {
        float iv = 1.f / (1.f + expf(-ga[0][e]));
        float fv = 1.f / (1.f + expf(-ga[1][e]));
        float gv = tanhf(ga[2][e]);
        float ov = 1.f / (1.f + expf(-ga[3][e]));
        float cc = fv * cpv[e] + iv * gv;
        ccv[e] = cc;
        hh[e] = ov * tanhf(cc);
    }
    *(float4*)cP = make_float4(ccv[0], ccv[1], ccv[2], ccv[3]);

    // h -> bf16 hi/lo, [b][k] layout (Whh operand for next timestep)
    {
        __nv_bfloat16 hi, lo;
#pragma unroll
        for (int e = 0; e < 4; e++) {
            bsplit(hh[e], hi, lo);
            size_t o = (size_t)l*BB*HH + (size_t)(b0+e)*HH + j;
            g_hbfHi[o] = hi;
            g_hbfLo[o] = lo;
        }
    }

    float sum = hh[0] + hh[1] + hh[2] + hh[3];
    float sq  = hh[0]*hh[0] + hh[1]*hh[1] + hh[2]*hh[2] + hh[3]*hh[3];
#pragma unroll
    for (int o = 8; o; o >>= 1) {
        sum += __shfl_down_sync(0xffffffffu, sum, o, 16);
        sq  += __shfl_down_sync(0xffffffffu, sq,  o, 16);
    }
    sum = __shfl_sync(0xffffffffu, sum, 0, 16);
    sq  = __shfl_sync(0xffffffffu, sq,  0, 16);
    float mu  = sum * (1.f / BB);
    float var = sq  * (1.f / BB) - mu * mu;
    float rs  = rsqrtf(var + EPSN);
    float gmv = gmP[j], btv = btP[j];

    if (l < 2) {
        __nv_bfloat16 hi, lo;
#pragma unroll
        for (int e = 0; e < 4; e++) {
            float hd = (gmv * (hh[e] - mu) * rs + btv) * mkP[(b0+e)*HH + j];
            bsplit(hd, hi, lo);
            size_t o = (size_t)l*BB*HH + (size_t)(b0+e)*HH + j;
            g_hdbfHi[o] = hi;
            g_hdbfLo[o] = lo;
        }
    } else {
#pragma unroll
        for (int e = 0; e < 4; e++) {
            float hd = (gmv * (hh[e] - mu) * rs + btv) * mkP[(b0+e)*HH + j];
            g_Hout[((size_t)t*BB + b0 + e)*HH + j] = hd;
        }
    }
}

// ---------------- loss: mean NLL over 6400 rows of 8000 logits --------------
__global__ void k_loss(const int* __restrict__ x, float* out) {
    int r = blockIdx.x;
    int t = r >> 6, b = r & 63;
    const float* row = &g_logits[(size_t)r * VV];
    int tid = threadIdx.x;
    float m = -INFINITY, s = 0.f;
    for (int v = tid; v < VV; v += 256) {
        float xv = row[v];
        if (xv > m) { s = s * expf(m - xv) + 1.f; m = xv; }
        else s += expf(xv - m);
    }
    __shared__ float sm[256], ss[256];
    sm[tid] = m; ss[tid] = s;
    __syncthreads();
    for (int o = 128; o; o >>= 1) {
        if (tid < o) {
            float m2 = sm[tid + o], s2 = ss[tid + o];
            float mm = fmaxf(sm[tid], m2);
            ss[tid] = ss[tid] * expf(sm[tid] - mm) + s2 * expf(m2 - mm);
            sm[tid] = mm;
        }
        __syncthreads();
    }
    if (tid == 0) {
        int tgt = x[b*TT + t + 1];
        float lse = sm[0] + logf(ss[0]);
        atomicAdd(out, (lse - row[tgt]) * (1.f / MM));
    }
}

// ---------------- transpose [t*64+b][v] -> out[b][v][t] ---------------------
__global__ void k_transpose(float* __restrict__ outLogits) {
    int b = blockIdx.x;
    int v0 = blockIdx.y * 32;
    __shared__ float tile[32 * 101];
    int tid = threadIdx.x;
    for (int idx = tid; idx < 3200; idx += 256) {
        int t = idx >> 5, vi = idx & 31;
        tile[vi*101 + t] = g_logits[(size_t)(t*BB + b)*VV + v0 + vi];
    }
    __syncthreads();
    for (int idx = tid; idx < 3200; idx += 256) {
        int vi = idx / 100, t = idx - vi*100;
        outLogits[(size_t)b*VV*TS + (size_t)(v0 + vi)*TS + t] = tile[vi*101 + t];
    }
}

// ---------------- launch ------------------------------------------------------
extern "C" void kernel_launch(void* const* d_in, const int* in_sizes, int n_in,
                              void* d_out, int out_size) {
    const int*   x   = (const int*)d_in[0];
    const float* emb = (const float*)d_in[1];
    const float* Wd  = (const float*)d_in[2];
    const float* bd  = (const float*)d_in[3];
    const float* Wih[3] = {(const float*)d_in[4],  (const float*)d_in[10], (const float*)d_in[16]};
    const float* Whh[3] = {(const float*)d_in[5],  (const float*)d_in[11], (const float*)d_in[17]};
    const float* bl[3]  = {(const float*)d_in[6],  (const float*)d_in[12], (const float*)d_in[18]};
    const float* gm[3]  = {(const float*)d_in[7],  (const float*)d_in[13], (const float*)d_in[19]};
    const float* bt[3]  = {(const float*)d_in[8],  (const float*)d_in[14], (const float*)d_in[20]};
    const float* mk[3]  = {(const float*)d_in[9],  (const float*)d_in[15], (const float*)d_in[21]};

    float* out = (float*)d_out;
    int hasLoss = (out_size & 1) ? 1 : 0;
    float* outLogits = out + hasLoss;

    k_init<<<(3*HH*BB + 255)/256, 256>>>(out, hasLoss);
    k_wsplit<<<(5*GG*(HH/4) + 255)/256, 256>>>(Whh[0], Wih[1], Whh[1], Wih[2], Whh[2]);
    k_embed<<<(MM*(HH/4) + 255)/256, 256>>>(x, emb);
    k_gemm_xg1<<<dim3(GG/128, MM/128), 256>>>(Wih[0], bl[0]);

    for (int d = 0; d < TS + 2; d++) {
        k_gemm_wave_tc<<<dim3(16, 4, 3), 256>>>(d);
        k_cell_wave<<<dim3(32, 3), 256>>>(d, bl[1], bl[2],
                                          gm[0], bt[0], mk[0],
                                          gm[1], bt[1], mk[1],
                                          gm[2], bt[2], mk[2]);
    }

    k_dec_tc<<<dim3((VV + 127)/128, MM/128), 256>>>(Wd, bd);
    if (hasLoss) k_loss<<<MM, 256>>>(x, out);
    k_transpose<<<dim3(BB, VV/32), 256>>>(outLogits);
}

// round 11
// speedup vs baseline: 2.7298x; 1.2562x over previous
#include <cuda_runtime.h>
#include <cuda_bf16.h>
#include <math.h>

#define BB 64
#define TT 101
#define TS 100
#define VV 8000
#define HH 512
#define GG 2048
#define MM (TS*BB)   // 6400
#define EPSN 1e-5f

typedef unsigned long long ull;

// ---------------- device scratch (static; no runtime allocation) -------------
__device__ float g_Xg1[(size_t)GG*MM];           // [t][n][b] e@Wih1^T + b1
__device__ float g_Hout[MM*HH];                  // [m][h] layer-3 output
__device__ float g_logits[(size_t)MM*VV];        // [m][v]
__device__ float g_part[(size_t)3*4*GG*BB];      // [layer][slice][n][b]
__device__ float g_c[3*HH*BB];                   // [layer][j][b] cell state
// bf16 split weights: 0:Whh1 1:Wih2 2:Whh2 3:Wih3 4:Whh3 5:Wih1, [slot][n][k]
__device__ __align__(16) __nv_bfloat16 g_WspHi[(size_t)6*GG*HH];
__device__ __align__(16) __nv_bfloat16 g_WspLo[(size_t)6*GG*HH];
// bf16 split activations, [layer][b][k]
__device__ __align__(16) __nv_bfloat16 g_hbfHi[3*BB*HH];
__device__ __align__(16) __nv_bfloat16 g_hbfLo[3*BB*HH];
__device__ __align__(16) __nv_bfloat16 g_hdbfHi[2*BB*HH];
__device__ __align__(16) __nv_bfloat16 g_hdbfLo[2*BB*HH];
// bf16 split embeddings, [m][k]
__device__ __align__(16) __nv_bfloat16 g_ebfHi[(size_t)MM*HH];
__device__ __align__(16) __nv_bfloat16 g_ebfLo[(size_t)MM*HH];

// ---------------- helpers ------------------------------------------------------
__device__ __forceinline__ unsigned tf32c(float x) {
    unsigned u;
    asm("cvt.rna.tf32.f32 %0, %1;" : "=r"(u) : "f"(x));
    return u;
}
__device__ __forceinline__ void mma_tf32(float* c, const unsigned* a, const unsigned* b) {
    asm("mma.sync.aligned.m16n8k8.row.col.f32.tf32.tf32.f32 "
        "{%0,%1,%2,%3}, {%4,%5,%6,%7}, {%8,%9}, {%0,%1,%2,%3};"
        : "+f"(c[0]), "+f"(c[1]), "+f"(c[2]), "+f"(c[3])
        : "r"(a[0]), "r"(a[1]), "r"(a[2]), "r"(a[3]), "r"(b[0]), "r"(b[1]));
}
__device__ __forceinline__ void mma_bf16(float* c, const unsigned* a, const unsigned* b) {
    asm("mma.sync.aligned.m16n8k16.row.col.f32.bf16.bf16.f32 "
        "{%0,%1,%2,%3}, {%4,%5,%6,%7}, {%8,%9}, {%0,%1,%2,%3};"
        : "+f"(c[0]), "+f"(c[1]), "+f"(c[2]), "+f"(c[3])
        : "r"(a[0]), "r"(a[1]), "r"(a[2]), "r"(a[3]), "r"(b[0]), "r"(b[1]));
}
__device__ __forceinline__ void ldsm4(unsigned* r, unsigned addr) {
    asm volatile("ldmatrix.sync.aligned.m8n8.x4.shared.b16 {%0,%1,%2,%3}, [%4];"
                 : "=r"(r[0]), "=r"(r[1]), "=r"(r[2]), "=r"(r[3]) : "r"(addr));
}
__device__ __forceinline__ void bsplit(float x, __nv_bfloat16& hi, __nv_bfloat16& lo) {
    hi = __float2bfloat16(x);
    lo = __float2bfloat16(x - __bfloat162float(hi));
}
__device__ __forceinline__ void cpa16(unsigned dst, const void* src) {
    asm volatile("cp.async.ca.shared.global [%0], [%1], 16;" :: "r"(dst), "l"(src));
}

// ---------------- init: zero states + loss slot ------------------------------
__global__ void k_init(float* out, int hasLoss) {
    int i = blockIdx.x * blockDim.x + threadIdx.x;
    if (i < 3*HH*BB) {
        g_c[i] = 0.f;
        g_hbfHi[i] = __float2bfloat16(0.f);
        g_hbfLo[i] = __float2bfloat16(0.f);
    }
    if (i == 0 && hasLoss) out[0] = 0.f;
}

// ---------------- weight pre-split (once): 6 matrices [2048][512] ------------
__global__ void k_wsplit(const float* __restrict__ Whh1,
                         const float* __restrict__ Wih2, const float* __restrict__ Whh2,
                         const float* __restrict__ Wih3, const float* __restrict__ Whh3,
                         const float* __restrict__ Wih1) {
    int i = blockIdx.x * blockDim.x + threadIdx.x;   // float4 index
    const int PER = GG * (HH/4);
    if (i >= 6 * PER) return;
    int slot = i / PER, rem = i - slot * PER;
    const float* M = slot == 0 ? Whh1 : slot == 1 ? Wih2 : slot == 2 ? Whh2
                   : slot == 3 ? Wih3 : slot == 4 ? Whh3 : Wih1;
    float4 v = ((const float4*)M)[rem];
    __nv_bfloat16 h0,l0,h1,l1,h2,l2,h3,l3;
    bsplit(v.x, h0, l0); bsplit(v.y, h1, l1);
    bsplit(v.z, h2, l2); bsplit(v.w, h3, l3);
    size_t o = (size_t)slot*GG*HH + (size_t)rem*4;
    *(__nv_bfloat162*)&g_WspHi[o]   = __nv_bfloat162(h0, h1);
    *(__nv_bfloat162*)&g_WspHi[o+2] = __nv_bfloat162(h2, h3);
    *(__nv_bfloat162*)&g_WspLo[o]   = __nv_bfloat162(l0, l1);
    *(__nv_bfloat162*)&g_WspLo[o+2] = __nv_bfloat162(l2, l3);
}

// ---------------- embedding gather + bf16 split -------------------------------
__global__ void k_embed(const int* x, const float* emb) {
    int i = blockIdx.x * blockDim.x + threadIdx.x;
    if (i >= MM * (HH/4)) return;
    int m  = i / (HH/4);
    int hq = i % (HH/4);
    int t = m / BB, b = m % BB;
    int tok = x[b*TT + t];
    float4 v = ((const float4*)emb)[(size_t)tok*(HH/4) + hq];
    __nv_bfloat16 h0,l0,h1,l1,h2,l2,h3,l3;
    bsplit(v.x, h0, l0); bsplit(v.y, h1, l1);
    bsplit(v.z, h2, l2); bsplit(v.w, h3, l3);
    size_t o = (size_t)m*HH + (size_t)hq*4;
    *(__nv_bfloat162*)&g_ebfHi[o]   = __nv_bfloat162(h0, h1);
    *(__nv_bfloat162*)&g_ebfHi[o+2] = __nv_bfloat162(h2, h3);
    *(__nv_bfloat162*)&g_ebfLo[o]   = __nv_bfloat162(l0, l1);
    *(__nv_bfloat162*)&g_ebfLo[o+2] = __nv_bfloat162(l2, l3);
}

// ---------------- Xg1 GEMM: bf16 split-3 tensor cores -------------------------
// grid (16 n-tiles, 100 t), block 256. CTA tile 128n x 64b x 512k.
// g_Xg1[t][n][b] = e @ Wih1^T + b1.
__global__ void __launch_bounds__(256) k_xg1_tc(const float* __restrict__ bias) {
    int t = blockIdx.y;
    int nb = blockIdx.x * 128;
    const __nv_bfloat16* wHi = g_WspHi + ((size_t)5*GG + nb)*HH;
    const __nv_bfloat16* wLo = g_WspLo + ((size_t)5*GG + nb)*HH;
    const __nv_bfloat16* aHi = g_ebfHi + (size_t)t*BB*HH;
    const __nv_bfloat16* aLo = g_ebfLo + (size_t)t*BB*HH;

    int tid = threadIdx.x;
    int lane = tid & 31, warp = tid >> 5;
    int mwarp = warp >> 1, bwarp = warp & 1;

    __shared__ __align__(16) __nv_bfloat16 sWhi[128*40];
    __shared__ __align__(16) __nv_bfloat16 sWlo[128*40];
    __shared__ __align__(16) __nv_bfloat16 sAhi[64*40];
    __shared__ __align__(16) __nv_bfloat16 sAlo[64*40];
    unsigned bWhi = (unsigned)__cvta_generic_to_shared(sWhi);
    unsigned bWlo = (unsigned)__cvta_generic_to_shared(sWlo);
    unsigned bAhi = (unsigned)__cvta_generic_to_shared(sAhi);
    unsigned bAlo = (unsigned)__cvta_generic_to_shared(sAlo);

    float acc[2][4][4];
#pragma unroll
    for (int mt = 0; mt < 2; mt++)
#pragma unroll
        for (int j = 0; j < 4; j++)
#pragma unroll
            for (int e = 0; e < 4; e++) acc[mt][j][e] = 0.f;

    int aRow = mwarp*32 + (lane & 15);
    int aColHalf = (lane >> 4) * 16;
    int bSel = lane >> 3, bL = lane & 7;
    int bRowOff = (bSel >> 1) * 8 + bL;
    int bColHalf = (bSel & 1) * 16;

    int wr0 = tid >> 1, wc0 = (tid & 1) * 2;
    int ar = tid >> 2, ac = tid & 3;

    for (int kc = 0; kc < HH; kc += 32) {
#pragma unroll
        for (int u = 0; u < 2; u++) {
            int r = wr0, c = wc0 + u;
            cpa16(bWhi + r*80 + c*16, wHi + (size_t)r*HH + kc + c*8);
            cpa16(bWlo + r*80 + c*16, wLo + (size_t)r*HH + kc + c*8);
        }
        cpa16(bAhi + ar*80 + ac*16, aHi + (size_t)ar*HH + kc + ac*8);
        cpa16(bAlo + ar*80 + ac*16, aLo + (size_t)ar*HH + kc + ac*8);
        asm volatile("cp.async.commit_group;");
        asm volatile("cp.async.wait_group 0;");
        __syncthreads();

#pragma unroll
        for (int kq = 0; kq < 2; kq++) {
            unsigned wa_h[2][4], wa_l[2][4];
#pragma unroll
            for (int mt = 0; mt < 2; mt++) {
                unsigned off = (unsigned)((aRow + mt*16)*80 + kq*32 + aColHalf);
                ldsm4(wa_h[mt], bWhi + off);
                ldsm4(wa_l[mt], bWlo + off);
            }
            unsigned hb_h[4][2], hb_l[4][2];
#pragma unroll
            for (int j2 = 0; j2 < 2; j2++) {
                unsigned off = (unsigned)((bwarp*32 + j2*16 + bRowOff)*80 + kq*32 + bColHalf);
                unsigned q[4];
                ldsm4(q, bAhi + off);
                hb_h[2*j2][0] = q[0]; hb_h[2*j2][1] = q[1];
                hb_h[2*j2+1][0] = q[2]; hb_h[2*j2+1][1] = q[3];
                ldsm4(q, bAlo + off);
                hb_l[2*j2][0] = q[0]; hb_l[2*j2][1] = q[1];
                hb_l[2*j2+1][0] = q[2]; hb_l[2*j2+1][1] = q[3];
            }
#pragma unroll
            for (int mt = 0; mt < 2; mt++)
#pragma unroll
                for (int j = 0; j < 4; j++) {
                    mma_bf16(acc[mt][j], wa_h[mt], hb_h[j]);
                    mma_bf16(acc[mt][j], wa_h[mt], hb_l[j]);
                    mma_bf16(acc[mt][j], wa_l[mt], hb_h[j]);
                }
        }
        __syncthreads();
    }

    float* P = g_Xg1 + (size_t)t*(GG*BB) + (size_t)nb*BB;
    int g = lane >> 2, tg = lane & 3;
#pragma unroll
    for (int mt = 0; mt < 2; mt++) {
        int n = mwarp*32 + mt*16 + g;
        float bb0 = bias[nb + n], bb1 = bias[nb + n + 8];
#pragma unroll
        for (int j = 0; j < 4; j++) {
            int b = bwarp*32 + j*8 + 2*tg;
            float2 v0; v0.x = acc[mt][j][0] + bb0; v0.y = acc[mt][j][1] + bb0;
            float2 v1; v1.x = acc[mt][j][2] + bb1; v1.y = acc[mt][j][3] + bb1;
            *(float2*)&P[(size_t)n*BB + b]       = v0;
            *(float2*)&P[(size_t)(n + 8)*BB + b] = v1;
        }
    }
}

// ---------------- decoder GEMM: TF32 tensor cores -----------------------------
__global__ void __launch_bounds__(256) k_dec_tc(const float* __restrict__ Wd,
                                                const float* __restrict__ bd) {
    __shared__ unsigned Ast[32*136];
    __shared__ unsigned Bst[32*136];
    int tid = threadIdx.x;
    int warp = tid >> 5, lane = tid & 31;
    int gid = lane >> 2, tig = lane & 3;
    int mBase = blockIdx.y * 128, nBase = blockIdx.x * 128;
    int wm = (warp >> 2) * 64, wn = (warp & 3) * 32;

    float c[4][4][4];
#pragma unroll
    for (int i = 0; i < 4; i++)
#pragma unroll
        for (int j = 0; j < 4; j++)
#pragma unroll
            for (int e = 0; e < 4; e++) c[i][j][e] = 0.f;

    int srow = tid & 127;
    int half = tid >> 7;
    int nIdx = nBase + srow;
    bool nOk = nIdx < VV;
    const float* aRow = &g_Hout[(size_t)(mBase + srow)*HH];
    const float* bRow = &Wd[(size_t)(nOk ? nIdx : 0)*HH];

    for (int kc = 0; kc < HH; kc += 32) {
        float4 av[4], bv[4];
#pragma unroll
        for (int i = 0; i < 4; i++) {
            av[i] = *(const float4*)&aRow[kc + half*16 + i*4];
            float4 b = *(const float4*)&bRow[kc + half*16 + i*4];
            if (!nOk) b = make_float4(0.f, 0.f, 0.f, 0.f);
            bv[i] = b;
        }
        __syncthreads();
#pragma unroll
        for (int i = 0; i < 4; i++) {
            int k = half*16 + i*4;
            Ast[(k+0)*136 + srow] = tf32c(av[i].x);
            Ast[(k+1)*136 + srow] = tf32c(av[i].y);
            Ast[(k+2)*136 + srow] = tf32c(av[i].z);
            Ast[(k+3)*136 + srow] = tf32c(av[i].w);
            Bst[(k+0)*136 + srow] = tf32c(bv[i].x);
            Bst[(k+1)*136 + srow] = tf32c(bv[i].y);
            Bst[(k+2)*136 + srow] = tf32c(bv[i].z);
            Bst[(k+3)*136 + srow] = tf32c(bv[i].w);
        }
        __syncthreads();
#pragma unroll
        for (int ks = 0; ks < 32; ks += 8) {
            unsigned a[4][4], b[4][2];
            int r0 = (ks + tig)*136, r1 = (ks + tig + 4)*136;
#pragma unroll
            for (int i = 0; i < 4; i++) {
                int mo = wm + i*16 + gid;
                a[i][0] = Ast[r0 + mo]; a[i][1] = Ast[r0 + mo + 8];
                a[i][2] = Ast[r1 + mo]; a[i][3] = Ast[r1 + mo + 8];
            }
#pragma unroll
            for (int j = 0; j < 4; j++) {
                int no = wn + j*8 + gid;
                b[j][0] = Bst[r0 + no];
                b[j][1] = Bst[r1 + no];
            }
#pragma unroll
            for (int i = 0; i < 4; i++)
#pragma unroll
                for (int j = 0; j < 4; j++)
                    mma_tf32(c[i][j], a[i], b[j]);
        }
    }

#pragma unroll
    for (int i = 0; i < 4; i++) {
        int r0 = mBase + wm + i*16 + gid;
#pragma unroll
        for (int j = 0; j < 4; j++) {
            int n = nBase + wn + j*8 + 2*tig;
            if (n < VV) {
                float2 bb = *(const float2*)&bd[n];
                float2 v0; v0.x = c[i][j][0] + bb.x; v0.y = c[i][j][1] + bb.y;
                float2 v1; v1.x = c[i][j][2] + bb.x; v1.y = c[i][j][3] + bb.y;
                *(float2*)&g_logits[(size_t)r0*VV + n]       = v0;
                *(float2*)&g_logits[(size_t)(r0 + 8)*VV + n] = v1;
            }
        }
    }
}

// ---------------- wavefront GEMM: bf16 split-3 tensor cores -------------------
__global__ void __launch_bounds__(256) k_gemm_wave_tc(int d) {
    int l = blockIdx.z;
    int t = d - l;
    if (t < 0 || t >= TS) return;
    int slice = blockIdx.y;
    if (l == 0 && slice >= 2) return;

    int wslot, kOff;
    const __nv_bfloat16 *aHi, *aLo;
    if (l == 0) {
        wslot = 0; kOff = slice * 256;
        aHi = g_hbfHi;             aLo = g_hbfLo;
    } else if (slice < 2) {
        wslot = 2*l - 1; kOff = slice * 256;
        aHi = g_hdbfHi + (l-1)*BB*HH; aLo = g_hdbfLo + (l-1)*BB*HH;
    } else {
        wslot = 2*l; kOff = (slice - 2) * 256;
        aHi = g_hbfHi + l*BB*HH;   aLo = g_hbfLo + l*BB*HH;
    }
    int nb = blockIdx.x * 128;
    const __nv_bfloat16* wHi = g_WspHi + ((size_t)wslot*GG + nb)*HH + kOff;
    const __nv_bfloat16* wLo = g_WspLo + ((size_t)wslot*GG + nb)*HH + kOff;
    aHi += kOff; aLo += kOff;

    int tid = threadIdx.x;
    int lane = tid & 31, warp = tid >> 5;
    int mwarp = warp >> 1, bwarp = warp & 1;

    __shared__ __align__(16) __nv_bfloat16 sWhi[128*40];
    __shared__ __align__(16) __nv_bfloat16 sWlo[128*40];
    __shared__ __align__(16) __nv_bfloat16 sAhi[64*40];
    __shared__ __align__(16) __nv_bfloat16 sAlo[64*40];
    unsigned bWhi = (unsigned)__cvta_generic_to_shared(sWhi);
    unsigned bWlo = (unsigned)__cvta_generic_to_shared(sWlo);
    unsigned bAhi = (unsigned)__cvta_generic_to_shared(sAhi);
    unsigned bAlo = (unsigned)__cvta_generic_to_shared(sAlo);

    float acc[2][4][4];
#pragma unroll
    for (int mt = 0; mt < 2; mt++)
#pragma unroll
        for (int j = 0; j < 4; j++)
#pragma unroll
            for (int e = 0; e < 4; e++) acc[mt][j][e] = 0.f;

    int aRow = mwarp*32 + (lane & 15);
    int aColHalf = (lane >> 4) * 16;
    int bSel = lane >> 3, bL = lane & 7;
    int bRowOff = (bSel >> 1) * 8 + bL;
    int bColHalf = (bSel & 1) * 16;

    int wr0 = tid >> 1, wc0 = (tid & 1) * 2;
    int ar = tid >> 2, ac = tid & 3;

    for (int kc = 0; kc < 256; kc += 32) {
#pragma unroll
        for (int u = 0; u < 2; u++) {
            int r = wr0, c = wc0 + u;
            cpa16(bWhi + r*80 + c*16, wHi + (size_t)r*HH + kc + c*8);
            cpa16(bWlo + r*80 + c*16, wLo + (size_t)r*HH + kc + c*8);
        }
        cpa16(bAhi + ar*80 + ac*16, aHi + (size_t)ar*HH + kc + ac*8);
        cpa16(bAlo + ar*80 + ac*16, aLo + (size_t)ar*HH + kc + ac*8);
        asm volatile("cp.async.commit_group;");
        asm volatile("cp.async.wait_group 0;");
        __syncthreads();

#pragma unroll
        for (int kq = 0; kq < 2; kq++) {
            unsigned wa_h[2][4], wa_l[2][4];
#pragma unroll
            for (int mt = 0; mt < 2; mt++) {
                unsigned off = (unsigned)((aRow + mt*16)*80 + kq*32 + aColHalf);
                ldsm4(wa_h[mt], bWhi + off);
                ldsm4(wa_l[mt], bWlo + off);
            }
            unsigned hb_h[4][2], hb_l[4][2];
#pragma unroll
            for (int j2 = 0; j2 < 2; j2++) {
                unsigned off = (unsigned)((bwarp*32 + j2*16 + bRowOff)*80 + kq*32 + bColHalf);
                unsigned q[4];
                ldsm4(q, bAhi + off);
                hb_h[2*j2][0] = q[0]; hb_h[2*j2][1] = q[1];
                hb_h[2*j2+1][0] = q[2]; hb_h[2*j2+1][1] = q[3];
                ldsm4(q, bAlo + off);
                hb_l[2*j2][0] = q[0]; hb_l[2*j2][1] = q[1];
                hb_l[2*j2+1][0] = q[2]; hb_l[2*j2+1][1] = q[3];
            }
#pragma unroll
            for (int mt = 0; mt < 2; mt++)
#pragma unroll
                for (int j = 0; j < 4; j++) {
                    mma_bf16(acc[mt][j], wa_h[mt], hb_h[j]);
                    mma_bf16(acc[mt][j], wa_h[mt], hb_l[j]);
                    mma_bf16(acc[mt][j], wa_l[mt], hb_h[j]);
                }
        }
        __syncthreads();
    }

    float* P = g_part + ((size_t)(l*4 + slice)*GG + nb)*BB;
    int g = lane >> 2, tg = lane & 3;
#pragma unroll
    for (int mt = 0; mt < 2; mt++) {
        int n = mwarp*32 + mt*16 + g;
#pragma unroll
        for (int j = 0; j < 4; j++) {
            int b = bwarp*32 + j*8 + 2*tg;
            float2 v0; v0.x = acc[mt][j][0]; v0.y = acc[mt][j][1];
            float2 v1; v1.x = acc[mt][j][2]; v1.y = acc[mt][j][3];
            *(float2*)&P[(size_t)n*BB + b]       = v0;
            *(float2*)&P[(size_t)(n + 8)*BB + b] = v1;
        }
    }
}

// ---------------- wavefront cell: LSTM + BN(train) + locked dropout ----------
__global__ void __launch_bounds__(256) k_cell_wave(int d,
    const float* __restrict__ b2, const float* __restrict__ b3,
    const float* __restrict__ gm0, const float* __restrict__ bt0, const float* __restrict__ mk0,
    const float* __restrict__ gm1, const float* __restrict__ bt1, const float* __restrict__ mk1,
    const float* __restrict__ gm2, const float* __restrict__ bt2, const float* __restrict__ mk2)
{
    int l = blockIdx.y;
    int t = d - l;
    if (t < 0 || t >= TS) return;
    int tid = threadIdx.x;
    int jl = tid >> 4, bq = tid & 15;
    int j = blockIdx.x * 16 + jl;
    int b0 = bq * 4;
    const float* biasP = (l == 1) ? b2 : b3;
    const float* gmP = (l == 0) ? gm0 : (l == 1) ? gm1 : gm2;
    const float* btP = (l == 0) ? bt0 : (l == 1) ? bt1 : bt2;
    const float* mkP = (l == 0) ? mk0 : (l == 1) ? mk1 : mk2;

    float ga[4][4];
#pragma unroll
    for (int g = 0; g < 4; g++) {
        int n = (g << 9) + j;
        float4 s;
        if (l == 0) {
            s = *(const float4*)&g_Xg1[(size_t)t*(GG*BB) + (size_t)n*BB + b0];
        } else {
            float bv = biasP[n];
            s = make_float4(bv, bv, bv, bv);
        }
        const float* pp = g_part + ((size_t)(l*4)*GG + n)*BB + b0;
        if (l == 0) {
#pragma unroll
            for (int sl = 0; sl < 2; sl++) {
                float4 v = *(const float4*)(pp + (size_t)sl*(GG*BB));
                s.x += v.x; s.y += v.y; s.z += v.z; s.w += v.w;
            }
        } else {
#pragma unroll
            for (int sl = 0; sl < 4; sl++) {
                float4 v = *(const float4*)(pp + (size_t)sl*(GG*BB));
                s.x += v.x; s.y += v.y; s.z += v.z; s.w += v.w;
            }
        }
        ga[g][0] = s.x; ga[g][1] = s.y; ga[g][2] = s.z; ga[g][3] = s.w;
    }

    float* cP = g_c + l*HH*BB + j*BB + b0;
    float4 cprev = *(const float4*)cP;
    float cpv[4] = {cprev.x, cprev.y, cprev.z, cprev.w};
    float hh[4], ccv[4];
#pragma unroll
    for (int e = 0; e < 4; e++) {
        float iv = 1.f / (1.f + expf(-ga[0][e]));
        float fv = 1.f / (1.f + expf(-ga[1][e]));
        float gv = tanhf(ga[2][e]);
        float ov = 1.f / (1.f + expf(-ga[3][e]));
        float cc = fv * cpv[e] + iv * gv;
        ccv[e] = cc;
        hh[e] = ov * tanhf(cc);
    }
    *(float4*)cP = make_float4(ccv[0], ccv[1], ccv[2], ccv[3]);

    {
        __nv_bfloat16 hi, lo;
#pragma unroll
        for (int e = 0; e < 4; e++) {
            bsplit(hh[e], hi, lo);
            size_t o = (size_t)l*BB*HH + (size_t)(b0+e)*HH + j;
            g_hbfHi[o] = hi;
            g_hbfLo[o] = lo;
        }
    }

    float sum = hh[0] + hh[1] + hh[2] + hh[3];
    float sq  = hh[0]*hh[0] + hh[1]*hh[1] + hh[2]*hh[2] + hh[3]*hh[3];
#pragma unroll
    for (int o = 8; o; o >>= 1) {
        sum += __shfl_down_sync(0xffffffffu, sum, o, 16);
        sq  += __shfl_down_sync(0xffffffffu, sq,  o, 16);
    }
    sum = __shfl_sync(0xffffffffu, sum, 0, 16);
    sq  = __shfl_sync(0xffffffffu, sq,  0, 16);
    float mu  = sum * (1.f / BB);
    float var = sq  * (1.f / BB) - mu * mu;
    float rs  = rsqrtf(var + EPSN);
    float gmv = gmP[j], btv = btP[j];

    if (l < 2) {
        __nv_bfloat16 hi, lo;
#pragma unroll
        for (int e = 0; e < 4; e++) {
            float hd = (gmv * (hh[e] - mu) * rs + btv) * mkP[(b0+e)*HH + j];
            bsplit(hd, hi, lo);
            size_t o = (size_t)l*BB*HH + (size_t)(b0+e)*HH + j;
            g_hdbfHi[o] = hi;
            g_hdbfLo[o] = lo;
        }
    } else {
#pragma unroll
        for (int e = 0; e < 4; e++) {
            float hd = (gmv * (hh[e] - mu) * rs + btv) * mkP[(b0+e)*HH + j];
            g_Hout[((size_t)t*BB + b0 + e)*HH + j] = hd;
        }
    }
}

// ---------------- loss: mean NLL over 6400 rows of 8000 logits --------------
__global__ void k_loss(const int* __restrict__ x, float* out) {
    int r = blockIdx.x;
    int t = r >> 6, b = r & 63;
    const float* row = &g_logits[(size_t)r * VV];
    int tid = threadIdx.x;
    float m = -INFINITY, s = 0.f;
    for (int v = tid; v < VV; v += 256) {
        float xv = row[v];
        if (xv > m) { s = s * expf(m - xv) + 1.f; m = xv; }
        else s += expf(xv - m);
    }
    __shared__ float sm[256], ss[256];
    sm[tid] = m; ss[tid] = s;
    __syncthreads();
    for (int o = 128; o; o >>= 1) {
        if (tid < o) {
            float m2 = sm[tid + o], s2 = ss[tid + o];
            float mm = fmaxf(sm[tid], m2);
            ss[tid] = ss[tid] * expf(sm[tid] - mm) + s2 * expf(m2 - mm);
            sm[tid] = mm;
        }
        __syncthreads();
    }
    if (tid == 0) {
        int tgt = x[b*TT + t + 1];
        float lse = sm[0] + logf(ss[0]);
        atomicAdd(out, (lse - row[tgt]) * (1.f / MM));
    }
}

// ---------------- transpose [t*64+b][v] -> out[b][v][t] ---------------------
__global__ void k_transpose(float* __restrict__ outLogits) {
    int b = blockIdx.x;
    int v0 = blockIdx.y * 32;
    __shared__ float tile[32 * 101];
    int tid = threadIdx.x;
    for (int idx = tid; idx < 3200; idx += 256) {
        int t = idx >> 5, vi = idx & 31;
        tile[vi*101 + t] = g_logits[(size_t)(t*BB + b)*VV + v0 + vi];
    }
    __syncthreads();
    for (int idx = tid; idx < 3200; idx += 256) {
        int vi = idx / 100, t = idx - vi*100;
        outLogits[(size_t)b*VV*TS + (size_t)(v0 + vi)*TS + t] = tile[vi*101 + t];
    }
}

// ---------------- launch ------------------------------------------------------
extern "C" void kernel_launch(void* const* d_in, const int* in_sizes, int n_in,
                              void* d_out, int out_size) {
    const int*   x   = (const int*)d_in[0];
    const float* emb = (const float*)d_in[1];
    const float* Wd  = (const float*)d_in[2];
    const float* bd  = (const float*)d_in[3];
    const float* Wih[3] = {(const float*)d_in[4],  (const float*)d_in[10], (const float*)d_in[16]};
    const float* Whh[3] = {(const float*)d_in[5],  (const float*)d_in[11], (const float*)d_in[17]};
    const float* bl[3]  = {(const float*)d_in[6],  (const float*)d_in[12], (const float*)d_in[18]};
    const float* gm[3]  = {(const float*)d_in[7],  (const float*)d_in[13], (const float*)d_in[19]};
    const float* bt[3]  = {(const float*)d_in[8],  (const float*)d_in[14], (const float*)d_in[20]};
    const float* mk[3]  = {(const float*)d_in[9],  (const float*)d_in[15], (const float*)d_in[21]};

    float* out = (float*)d_out;
    int hasLoss = (out_size & 1) ? 1 : 0;
    float* outLogits = out + hasLoss;

    k_init<<<(3*HH*BB + 255)/256, 256>>>(out, hasLoss);
    k_wsplit<<<(6*GG*(HH/4) + 255)/256, 256>>>(Whh[0], Wih[1], Whh[1], Wih[2], Whh[2], Wih[0]);
    k_embed<<<(MM*(HH/4) + 255)/256, 256>>>(x, emb);
    k_xg1_tc<<<dim3(16, TS), 256>>>(bl[0]);

    for (int d = 0; d < TS + 2; d++) {
        k_gemm_wave_tc<<<dim3(16, 4, 3), 256>>>(d);
        k_cell_wave<<<dim3(32, 3), 256>>>(d, bl[1], bl[2],
                                          gm[0], bt[0], mk[0],
                                          gm[1], bt[1], mk[1],
                                          gm[2], bt[2], mk[2]);
    }

    k_dec_tc<<<dim3((VV + 127)/128, MM/128), 256>>>(Wd, bd);
    if (hasLoss) k_loss<<<MM, 256>>>(x, out);
    k_transpose<<<dim3(BB, VV/32), 256>>>(outLogits);
}

// round 12
// speedup vs baseline: 2.9523x; 1.0815x over previous
#include <cuda_runtime.h>
#include <cuda_bf16.h>
#include <math.h>

#define BB 64
#define TT 101
#define TS 100
#define VV 8000
#define HH 512
#define GG 2048
#define MM (TS*BB)   // 6400
#define EPSN 1e-5f

typedef unsigned long long ull;

// ---------------- device scratch (static; no runtime allocation) -------------
__device__ float g_Xg1[(size_t)GG*MM];           // [t][n][b] e@Wih1^T + b1
__device__ float g_Hout[MM*HH];                  // [m][h] layer-3 output
__device__ float g_logits[(size_t)MM*VV];        // [m][v]
__device__ float g_part[(size_t)3*4*GG*BB];      // [layer][slice][n][b]
__device__ float g_c[3*HH*BB];                   // [layer][j][b] cell state
__device__ unsigned g_cnt[3];                    // per-layer gemm-completion counters
// bf16 split weights: 0:Whh1 1:Wih2 2:Whh2 3:Wih3 4:Whh3 5:Wih1, [slot][n][k]
__device__ __align__(16) __nv_bfloat16 g_WspHi[(size_t)6*GG*HH];
__device__ __align__(16) __nv_bfloat16 g_WspLo[(size_t)6*GG*HH];
// bf16 split activations, [layer][b][k]
__device__ __align__(16) __nv_bfloat16 g_hbfHi[3*BB*HH];
__device__ __align__(16) __nv_bfloat16 g_hbfLo[3*BB*HH];
__device__ __align__(16) __nv_bfloat16 g_hdbfHi[2*BB*HH];
__device__ __align__(16) __nv_bfloat16 g_hdbfLo[2*BB*HH];
// bf16 split embeddings, [m][k]
__device__ __align__(16) __nv_bfloat16 g_ebfHi[(size_t)MM*HH];
__device__ __align__(16) __nv_bfloat16 g_ebfLo[(size_t)MM*HH];

// ---------------- helpers ------------------------------------------------------
__device__ __forceinline__ unsigned tf32c(float x) {
    unsigned u;
    asm("cvt.rna.tf32.f32 %0, %1;" : "=r"(u) : "f"(x));
    return u;
}
__device__ __forceinline__ void mma_tf32(float* c, const unsigned* a, const unsigned* b) {
    asm("mma.sync.aligned.m16n8k8.row.col.f32.tf32.tf32.f32 "
        "{%0,%1,%2,%3}, {%4,%5,%6,%7}, {%8,%9}, {%0,%1,%2,%3};"
        : "+f"(c[0]), "+f"(c[1]), "+f"(c[2]), "+f"(c[3])
        : "r"(a[0]), "r"(a[1]), "r"(a[2]), "r"(a[3]), "r"(b[0]), "r"(b[1]));
}
__device__ __forceinline__ void mma_bf16(float* c, const unsigned* a, const unsigned* b) {
    asm("mma.sync.aligned.m16n8k16.row.col.f32.bf16.bf16.f32 "
        "{%0,%1,%2,%3}, {%4,%5,%6,%7}, {%8,%9}, {%0,%1,%2,%3};"
        : "+f"(c[0]), "+f"(c[1]), "+f"(c[2]), "+f"(c[3])
        : "r"(a[0]), "r"(a[1]), "r"(a[2]), "r"(a[3]), "r"(b[0]), "r"(b[1]));
}
__device__ __forceinline__ void ldsm4(unsigned* r, unsigned addr) {
    asm volatile("ldmatrix.sync.aligned.m8n8.x4.shared.b16 {%0,%1,%2,%3}, [%4];"
                 : "=r"(r[0]), "=r"(r[1]), "=r"(r[2]), "=r"(r[3]) : "r"(addr));
}
__device__ __forceinline__ void bsplit(float x, __nv_bfloat16& hi, __nv_bfloat16& lo) {
    hi = __float2bfloat16(x);
    lo = __float2bfloat16(x - __bfloat162float(hi));
}
__device__ __forceinline__ void cpa16(unsigned dst, const void* src) {
    asm volatile("cp.async.ca.shared.global [%0], [%1], 16;" :: "r"(dst), "l"(src));
}

// ---------------- init: zero states + counters + loss slot --------------------
__global__ void k_init(float* out, int hasLoss) {
    int i = blockIdx.x * blockDim.x + threadIdx.x;
    if (i < 3*HH*BB) {
        g_c[i] = 0.f;
        g_hbfHi[i] = __float2bfloat16(0.f);
        g_hbfLo[i] = __float2bfloat16(0.f);
    }
    if (i < 3) g_cnt[i] = 0u;
    if (i == 0 && hasLoss) out[0] = 0.f;
}

// ---------------- weight pre-split (once): 6 matrices [2048][512] ------------
__global__ void k_wsplit(const float* __restrict__ Whh1,
                         const float* __restrict__ Wih2, const float* __restrict__ Whh2,
                         const float* __restrict__ Wih3, const float* __restrict__ Whh3,
                         const float* __restrict__ Wih1) {
    int i = blockIdx.x * blockDim.x + threadIdx.x;   // float4 index
    const int PER = GG * (HH/4);
    if (i >= 6 * PER) return;
    int slot = i / PER, rem = i - slot * PER;
    const float* M = slot == 0 ? Whh1 : slot == 1 ? Wih2 : slot == 2 ? Whh2
                   : slot == 3 ? Wih3 : slot == 4 ? Whh3 : Wih1;
    float4 v = ((const float4*)M)[rem];
    __nv_bfloat16 h0,l0,h1,l1,h2,l2,h3,l3;
    bsplit(v.x, h0, l0); bsplit(v.y, h1, l1);
    bsplit(v.z, h2, l2); bsplit(v.w, h3, l3);
    size_t o = (size_t)slot*GG*HH + (size_t)rem*4;
    *(__nv_bfloat162*)&g_WspHi[o]   = __nv_bfloat162(h0, h1);
    *(__nv_bfloat162*)&g_WspHi[o+2] = __nv_bfloat162(h2, h3);
    *(__nv_bfloat162*)&g_WspLo[o]   = __nv_bfloat162(l0, l1);
    *(__nv_bfloat162*)&g_WspLo[o+2] = __nv_bfloat162(l2, l3);
}

// ---------------- embedding gather + bf16 split -------------------------------
__global__ void k_embed(const int* x, const float* emb) {
    int i = blockIdx.x * blockDim.x + threadIdx.x;
    if (i >= MM * (HH/4)) return;
    int m  = i / (HH/4);
    int hq = i % (HH/4);
    int t = m / BB, b = m % BB;
    int tok = x[b*TT + t];
    float4 v = ((const float4*)emb)[(size_t)tok*(HH/4) + hq];
    __nv_bfloat16 h0,l0,h1,l1,h2,l2,h3,l3;
    bsplit(v.x, h0, l0); bsplit(v.y, h1, l1);
    bsplit(v.z, h2, l2); bsplit(v.w, h3, l3);
    size_t o = (size_t)m*HH + (size_t)hq*4;
    *(__nv_bfloat162*)&g_ebfHi[o]   = __nv_bfloat162(h0, h1);
    *(__nv_bfloat162*)&g_ebfHi[o+2] = __nv_bfloat162(h2, h3);
    *(__nv_bfloat162*)&g_ebfLo[o]   = __nv_bfloat162(l0, l1);
    *(__nv_bfloat162*)&g_ebfLo[o+2] = __nv_bfloat162(l2, l3);
}

// ---------------- Xg1 GEMM: bf16 split-3 tensor cores -------------------------
__global__ void __launch_bounds__(256) k_xg1_tc(const float* __restrict__ bias) {
    int t = blockIdx.y;
    int nb = blockIdx.x * 128;
    const __nv_bfloat16* wHi = g_WspHi + ((size_t)5*GG + nb)*HH;
    const __nv_bfloat16* wLo = g_WspLo + ((size_t)5*GG + nb)*HH;
    const __nv_bfloat16* aHi = g_ebfHi + (size_t)t*BB*HH;
    const __nv_bfloat16* aLo = g_ebfLo + (size_t)t*BB*HH;

    int tid = threadIdx.x;
    int lane = tid & 31, warp = tid >> 5;
    int mwarp = warp >> 1, bwarp = warp & 1;

    __shared__ __align__(16) __nv_bfloat16 sWhi[128*40];
    __shared__ __align__(16) __nv_bfloat16 sWlo[128*40];
    __shared__ __align__(16) __nv_bfloat16 sAhi[64*40];
    __shared__ __align__(16) __nv_bfloat16 sAlo[64*40];
    unsigned bWhi = (unsigned)__cvta_generic_to_shared(sWhi);
    unsigned bWlo = (unsigned)__cvta_generic_to_shared(sWlo);
    unsigned bAhi = (unsigned)__cvta_generic_to_shared(sAhi);
    unsigned bAlo = (unsigned)__cvta_generic_to_shared(sAlo);

    float acc[2][4][4];
#pragma unroll
    for (int mt = 0; mt < 2; mt++)
#pragma unroll
        for (int j = 0; j < 4; j++)
#pragma unroll
            for (int e = 0; e < 4; e++) acc[mt][j][e] = 0.f;

    int aRow = mwarp*32 + (lane & 15);
    int aColHalf = (lane >> 4) * 16;
    int bSel = lane >> 3, bL = lane & 7;
    int bRowOff = (bSel >> 1) * 8 + bL;
    int bColHalf = (bSel & 1) * 16;

    int wr0 = tid >> 1, wc0 = (tid & 1) * 2;
    int ar = tid >> 2, ac = tid & 3;

    for (int kc = 0; kc < HH; kc += 32) {
#pragma unroll
        for (int u = 0; u < 2; u++) {
            int r = wr0, c = wc0 + u;
            cpa16(bWhi + r*80 + c*16, wHi + (size_t)r*HH + kc + c*8);
            cpa16(bWlo + r*80 + c*16, wLo + (size_t)r*HH + kc + c*8);
        }
        cpa16(bAhi + ar*80 + ac*16, aHi + (size_t)ar*HH + kc + ac*8);
        cpa16(bAlo + ar*80 + ac*16, aLo + (size_t)ar*HH + kc + ac*8);
        asm volatile("cp.async.commit_group;");
        asm volatile("cp.async.wait_group 0;");
        __syncthreads();

#pragma unroll
        for (int kq = 0; kq < 2; kq++) {
            unsigned wa_h[2][4], wa_l[2][4];
#pragma unroll
            for (int mt = 0; mt < 2; mt++) {
                unsigned off = (unsigned)((aRow + mt*16)*80 + kq*32 + aColHalf);
                ldsm4(wa_h[mt], bWhi + off);
                ldsm4(wa_l[mt], bWlo + off);
            }
            unsigned hb_h[4][2], hb_l[4][2];
#pragma unroll
            for (int j2 = 0; j2 < 2; j2++) {
                unsigned off = (unsigned)((bwarp*32 + j2*16 + bRowOff)*80 + kq*32 + bColHalf);
                unsigned q[4];
                ldsm4(q, bAhi + off);
                hb_h[2*j2][0] = q[0]; hb_h[2*j2][1] = q[1];
                hb_h[2*j2+1][0] = q[2]; hb_h[2*j2+1][1] = q[3];
                ldsm4(q, bAlo + off);
                hb_l[2*j2][0] = q[0]; hb_l[2*j2][1] = q[1];
                hb_l[2*j2+1][0] = q[2]; hb_l[2*j2+1][1] = q[3];
            }
#pragma unroll
            for (int mt = 0; mt < 2; mt++)
#pragma unroll
                for (int j = 0; j < 4; j++) {
                    mma_bf16(acc[mt][j], wa_h[mt], hb_h[j]);
                    mma_bf16(acc[mt][j], wa_h[mt], hb_l[j]);
                    mma_bf16(acc[mt][j], wa_l[mt], hb_h[j]);
                }
        }
        __syncthreads();
    }

    float* P = g_Xg1 + (size_t)t*(GG*BB) + (size_t)nb*BB;
    int g = lane >> 2, tg = lane & 3;
#pragma unroll
    for (int mt = 0; mt < 2; mt++) {
        int n = mwarp*32 + mt*16 + g;
        float bb0 = bias[nb + n], bb1 = bias[nb + n + 8];
#pragma unroll
        for (int j = 0; j < 4; j++) {
            int b = bwarp*32 + j*8 + 2*tg;
            float2 v0; v0.x = acc[mt][j][0] + bb0; v0.y = acc[mt][j][1] + bb0;
            float2 v1; v1.x = acc[mt][j][2] + bb1; v1.y = acc[mt][j][3] + bb1;
            *(float2*)&P[(size_t)n*BB + b]       = v0;
            *(float2*)&P[(size_t)(n + 8)*BB + b] = v1;
        }
    }
}

// ---------------- decoder GEMM: TF32 tensor cores -----------------------------
__global__ void __launch_bounds__(256) k_dec_tc(const float* __restrict__ Wd,
                                                const float* __restrict__ bd) {
    __shared__ unsigned Ast[32*136];
    __shared__ unsigned Bst[32*136];
    int tid = threadIdx.x;
    int warp = tid >> 5, lane = tid & 31;
    int gid = lane >> 2, tig = lane & 3;
    int mBase = blockIdx.y * 128, nBase = blockIdx.x * 128;
    int wm = (warp >> 2) * 64, wn = (warp & 3) * 32;

    float c[4][4][4];
#pragma unroll
    for (int i = 0; i < 4; i++)
#pragma unroll
        for (int j = 0; j < 4; j++)
#pragma unroll
            for (int e = 0; e < 4; e++) c[i][j][e] = 0.f;

    int srow = tid & 127;
    int half = tid >> 7;
    int nIdx = nBase + srow;
    bool nOk = nIdx < VV;
    const float* aRow = &g_Hout[(size_t)(mBase + srow)*HH];
    const float* bRow = &Wd[(size_t)(nOk ? nIdx : 0)*HH];

    for (int kc = 0; kc < HH; kc += 32) {
        float4 av[4], bv[4];
#pragma unroll
        for (int i = 0; i < 4; i++) {
            av[i] = *(const float4*)&aRow[kc + half*16 + i*4];
            float4 b = *(const float4*)&bRow[kc + half*16 + i*4];
            if (!nOk) b = make_float4(0.f, 0.f, 0.f, 0.f);
            bv[i] = b;
        }
        __syncthreads();
#pragma unroll
        for (int i = 0; i < 4; i++) {
            int k = half*16 + i*4;
            Ast[(k+0)*136 + srow] = tf32c(av[i].x);
            Ast[(k+1)*136 + srow] = tf32c(av[i].y);
            Ast[(k+2)*136 + srow] = tf32c(av[i].z);
            Ast[(k+3)*136 + srow] = tf32c(av[i].w);
            Bst[(k+0)*136 + srow] = tf32c(bv[i].x);
            Bst[(k+1)*136 + srow] = tf32c(bv[i].y);
            Bst[(k+2)*136 + srow] = tf32c(bv[i].z);
            Bst[(k+3)*136 + srow] = tf32c(bv[i].w);
        }
        __syncthreads();
#pragma unroll
        for (int ks = 0; ks < 32; ks += 8) {
            unsigned a[4][4], b[4][2];
            int r0 = (ks + tig)*136, r1 = (ks + tig + 4)*136;
#pragma unroll
            for (int i = 0; i < 4; i++) {
                int mo = wm + i*16 + gid;
                a[i][0] = Ast[r0 + mo]; a[i][1] = Ast[r0 + mo + 8];
                a[i][2] = Ast[r1 + mo]; a[i][3] = Ast[r1 + mo + 8];
            }
#pragma unroll
            for (int j = 0; j < 4; j++) {
                int no = wn + j*8 + gid;
                b[j][0] = Bst[r0 + no];
                b[j][1] = Bst[r1 + no];
            }
#pragma unroll
            for (int i = 0; i < 4; i++)
#pragma unroll
                for (int j = 0; j < 4; j++)
                    mma_tf32(c[i][j], a[i], b[j]);
        }
    }

#pragma unroll
    for (int i = 0; i < 4; i++) {
        int r0 = mBase + wm + i*16 + gid;
#pragma unroll
        for (int j = 0; j < 4; j++) {
            int n = nBase + wn + j*8 + 2*tig;
            if (n < VV) {
                float2 bb = *(const float2*)&bd[n];
                float2 v0; v0.x = c[i][j][0] + bb.x; v0.y = c[i][j][1] + bb.y;
                float2 v1; v1.x = c[i][j][2] + bb.x; v1.y = c[i][j][3] + bb.y;
                *(float2*)&g_logits[(size_t)r0*VV + n]       = v0;
                *(float2*)&g_logits[(size_t)(r0 + 8)*VV + n] = v1;
            }
        }
    }
}

// ---------------- FUSED wavefront: gemm CTAs (0..159) + cell CTAs (160..255) --
// One launch per diagonal. Gemm CTAs run free (inputs from previous launch),
// bump g_cnt[l] on completion. Cell CTAs poll g_cnt[l] >= target, then do
// LSTM+BN+dropout. Occupancy >= 2 guaranteed => all 256 CTAs resident.
__global__ void __launch_bounds__(256, 2) k_fused_wave(int d,
    unsigned tgt0, unsigned tgt1, unsigned tgt2,
    const float* __restrict__ b2, const float* __restrict__ b3,
    const float* __restrict__ gm0, const float* __restrict__ bt0, const float* __restrict__ mk0,
    const float* __restrict__ gm1, const float* __restrict__ bt1, const float* __restrict__ mk1,
    const float* __restrict__ gm2, const float* __restrict__ bt2, const float* __restrict__ mk2)
{
    extern __shared__ __align__(16) __nv_bfloat16 smemRaw[];
    int bx = blockIdx.x;
    int tid = threadIdx.x;

    if (bx < 160) {
        // =================== GEMM role ===================
        int ntile = bx & 15;
        int si = bx >> 4;                 // 0..9
        int l, slice;
        if (si < 2)      { l = 0; slice = si; }
        else if (si < 6) { l = 1; slice = si - 2; }
        else             { l = 2; slice = si - 6; }
        int t = d - l;
        if (t < 0 || t >= TS) return;

        int wslot, kOff;
        const __nv_bfloat16 *aHi, *aLo;
        if (l == 0) {
            wslot = 0; kOff = slice * 256;
            aHi = g_hbfHi;                aLo = g_hbfLo;
        } else if (slice < 2) {
            wslot = 2*l - 1; kOff = slice * 256;
            aHi = g_hdbfHi + (l-1)*BB*HH; aLo = g_hdbfLo + (l-1)*BB*HH;
        } else {
            wslot = 2*l; kOff = (slice - 2) * 256;
            aHi = g_hbfHi + l*BB*HH;      aLo = g_hbfLo + l*BB*HH;
        }
        int nb = ntile * 128;
        const __nv_bfloat16* wHi = g_WspHi + ((size_t)wslot*GG + nb)*HH + kOff;
        const __nv_bfloat16* wLo = g_WspLo + ((size_t)wslot*GG + nb)*HH + kOff;
        aHi += kOff; aLo += kOff;

        // dynamic smem layout: W hi [2][5120], W lo [2][5120], A hi [2][2560], A lo [2][2560]
        __nv_bfloat16* sWhi = smemRaw;
        __nv_bfloat16* sWlo = smemRaw + 2*5120;
        __nv_bfloat16* sAhi = smemRaw + 4*5120;
        __nv_bfloat16* sAlo = smemRaw + 4*5120 + 2*2560;
        unsigned bWhi = (unsigned)__cvta_generic_to_shared(sWhi);
        unsigned bWlo = (unsigned)__cvta_generic_to_shared(sWlo);
        unsigned bAhi = (unsigned)__cvta_generic_to_shared(sAhi);
        unsigned bAlo = (unsigned)__cvta_generic_to_shared(sAlo);

        int lane = tid & 31, warp = tid >> 5;
        int mwarp = warp >> 1, bwarp = warp & 1;

        float acc[2][4][4];
#pragma unroll
        for (int mt = 0; mt < 2; mt++)
#pragma unroll
            for (int j = 0; j < 4; j++)
#pragma unroll
                for (int e = 0; e < 4; e++) acc[mt][j][e] = 0.f;

        int aRow = mwarp*32 + (lane & 15);
        int aColHalf = (lane >> 4) * 16;
        int bSel = lane >> 3, bL = lane & 7;
        int bRowOff = (bSel >> 1) * 8 + bL;
        int bColHalf = (bSel & 1) * 16;

        int wr0 = tid >> 1, wc0 = (tid & 1) * 2;
        int ar = tid >> 2, ac = tid & 3;

        // ---- prologue: stage chunk 0 ----
        {
            int kc = 0;
#pragma unroll
            for (int u = 0; u < 2; u++) {
                int c = wc0 + u;
                cpa16(bWhi + wr0*80 + c*16, wHi + (size_t)wr0*HH + kc + c*8);
                cpa16(bWlo + wr0*80 + c*16, wLo + (size_t)wr0*HH + kc + c*8);
            }
            cpa16(bAhi + ar*80 + ac*16, aHi + (size_t)ar*HH + kc + ac*8);
            cpa16(bAlo + ar*80 + ac*16, aLo + (size_t)ar*HH + kc + ac*8);
            asm volatile("cp.async.commit_group;");
        }

        for (int ch = 0; ch < 8; ch++) {
            if (ch + 1 < 8) {
                int kc = (ch + 1) * 32;
                int st = (ch + 1) & 1;
                unsigned oW = st * 10240u, oA = st * 5120u;
#pragma unroll
                for (int u = 0; u < 2; u++) {
                    int c = wc0 + u;
                    cpa16(bWhi + oW + wr0*80 + c*16, wHi + (size_t)wr0*HH + kc + c*8);
                    cpa16(bWlo + oW + wr0*80 + c*16, wLo + (size_t)wr0*HH + kc + c*8);
                }
                cpa16(bAhi + oA + ar*80 + ac*16, aHi + (size_t)ar*HH + kc + ac*8);
                cpa16(bAlo + oA + ar*80 + ac*16, aLo + (size_t)ar*HH + kc + ac*8);
                asm volatile("cp.async.commit_group;");
                asm volatile("cp.async.wait_group 1;");
            } else {
                asm volatile("cp.async.wait_group 0;");
            }
            __syncthreads();

            int st = ch & 1;
            unsigned oW = st * 10240u, oA = st * 5120u;
#pragma unroll
            for (int kq = 0; kq < 2; kq++) {
                unsigned wa_h[2][4], wa_l[2][4];
#pragma unroll
                for (int mt = 0; mt < 2; mt++) {
                    unsigned off = (unsigned)((aRow + mt*16)*80 + kq*32 + aColHalf);
                    ldsm4(wa_h[mt], bWhi + oW + off);
                    ldsm4(wa_l[mt], bWlo + oW + off);
                }
                unsigned hb_h[4][2], hb_l[4][2];
#pragma unroll
                for (int j2 = 0; j2 < 2; j2++) {
                    unsigned off = (unsigned)((bwarp*32 + j2*16 + bRowOff)*80 + kq*32 + bColHalf);
                    unsigned q[4];
                    ldsm4(q, bAhi + oA + off);
                    hb_h[2*j2][0] = q[0]; hb_h[2*j2][1] = q[1];
                    hb_h[2*j2+1][0] = q[2]; hb_h[2*j2+1][1] = q[3];
                    ldsm4(q, bAlo + oA + off);
                    hb_l[2*j2][0] = q[0]; hb_l[2*j2][1] = q[1];
                    hb_l[2*j2+1][0] = q[2]; hb_l[2*j2+1][1] = q[3];
                }
#pragma unroll
                for (int mt = 0; mt < 2; mt++)
#pragma unroll
                    for (int j = 0; j < 4; j++) {
                        mma_bf16(acc[mt][j], wa_h[mt], hb_h[j]);
                        mma_bf16(acc[mt][j], wa_h[mt], hb_l[j]);
                        mma_bf16(acc[mt][j], wa_l[mt], hb_h[j]);
                    }
            }
            __syncthreads();
        }

        float* P = g_part + ((size_t)(l*4 + slice)*GG + nb)*BB;
        int g = lane >> 2, tg = lane & 3;
#pragma unroll
        for (int mt = 0; mt < 2; mt++) {
            int n = mwarp*32 + mt*16 + g;
#pragma unroll
            for (int j = 0; j < 4; j++) {
                int b = bwarp*32 + j*8 + 2*tg;
                float2 v0; v0.x = acc[mt][j][0]; v0.y = acc[mt][j][1];
                float2 v1; v1.x = acc[mt][j][2]; v1.y = acc[mt][j][3];
                *(float2*)&P[(size_t)n*BB + b]       = v0;
                *(float2*)&P[(size_t)(n + 8)*BB + b] = v1;
            }
        }
        __syncthreads();
        if (tid == 0)
            asm volatile("red.release.gpu.add.u32 [%0], 1;"
                         :: "l"(&g_cnt[l]) : "memory");
        return;
    }

    // =================== CELL role ===================
    int idx = bx - 160;
    int l = idx >> 5, jt = idx & 31;
    int t = d - l;
    if (t < 0 || t >= TS) return;

    unsigned tgt = (l == 0) ? tgt0 : (l == 1) ? tgt1 : tgt2;
    if (tid == 0) {
        unsigned v;
        while (true) {
            asm volatile("ld.acquire.gpu.u32 %0, [%1];"
                         : "=r"(v) : "l"(&g_cnt[l]) : "memory");
            if (v >= tgt) break;
            __nanosleep(32);
        }
    }
    __syncthreads();

    int jl = tid >> 4, bq = tid & 15;
    int j = jt * 16 + jl;
    int b0 = bq * 4;
    const float* biasP = (l == 1) ? b2 : b3;
    const float* gmP = (l == 0) ? gm0 : (l == 1) ? gm1 : gm2;
    const float* btP = (l == 0) ? bt0 : (l == 1) ? bt1 : bt2;
    const float* mkP = (l == 0) ? mk0 : (l == 1) ? mk1 : mk2;

    float ga[4][4];
#pragma unroll
    for (int g = 0; g < 4; g++) {
        int n = (g << 9) + j;
        float4 s;
        if (l == 0) {
            s = *(const float4*)&g_Xg1[(size_t)t*(GG*BB) + (size_t)n*BB + b0];
        } else {
            float bv = biasP[n];
            s = make_float4(bv, bv, bv, bv);
        }
        const float* pp = g_part + ((size_t)(l*4)*GG + n)*BB + b0;
        if (l == 0) {
#pragma unroll
            for (int sl = 0; sl < 2; sl++) {
                float4 v = *(const float4*)(pp + (size_t)sl*(GG*BB));
                s.x += v.x; s.y += v.y; s.z += v.z; s.w += v.w;
            }
        } else {
#pragma unroll
            for (int sl = 0; sl < 4; sl++) {
                float4 v = *(const float4*)(pp + (size_t)sl*(GG*BB));
                s.x += v.x; s.y += v.y; s.z += v.z; s.w += v.w;
            }
        }
        ga[g][0] = s.x; ga[g][1] = s.y; ga[g][2] = s.z; ga[g][3] = s.w;
    }

    float* cP = g_c + l*HH*BB + j*BB + b0;
    float4 cprev = *(const float4*)cP;
    float cpv[4] = {cprev.x, cprev.y, cprev.z, cprev.w};
    float hh[4], ccv[4];
#pragma unroll
    for (int e = 0; e < 4; e++) {
        float iv = 1.f / (1.f + expf(-ga[0][e]));
        float fv = 1.f / (1.f + expf(-ga[1][e]));
        float gv = tanhf(ga[2][e]);
        float ov = 1.f / (1.f + expf(-ga[3][e]));
        float cc = fv * cpv[e] + iv * gv;
        ccv[e] = cc;
        hh[e] = ov * tanhf(cc);
    }
    *(float4*)cP = make_float4(ccv[0], ccv[1], ccv[2], ccv[3]);

    {
        __nv_bfloat16 hi, lo;
#pragma unroll
        for (int e = 0; e < 4; e++) {
            bsplit(hh[e], hi, lo);
            size_t o = (size_t)l*BB*HH + (size_t)(b0+e)*HH + j;
            g_hbfHi[o] = hi;
            g_hbfLo[o] = lo;
        }
    }

    float sum = hh[0] + hh[1] + hh[2] + hh[3];
    float sq  = hh[0]*hh[0] + hh[1]*hh[1] + hh[2]*hh[2] + hh[3]*hh[3];
#pragma unroll
    for (int o = 8; o; o >>= 1) {
        sum += __shfl_down_sync(0xffffffffu, sum, o, 16);
        sq  += __shfl_down_sync(0xffffffffu, sq,  o, 16);
    }
    sum = __shfl_sync(0xffffffffu, sum, 0, 16);
    sq  = __shfl_sync(0xffffffffu, sq,  0, 16);
    float mu  = sum * (1.f / BB);
    float var = sq  * (1.f / BB) - mu * mu;
    float rs  = rsqrtf(var + EPSN);
    float gmv = gmP[j], btv = btP[j];

    if (l < 2) {
        __nv_bfloat16 hi, lo;
#pragma unroll
        for (int e = 0; e < 4; e++) {
            float hd = (gmv * (hh[e] - mu) * rs + btv) * mkP[(b0+e)*HH + j];
            bsplit(hd, hi, lo);
            size_t o = (size_t)l*BB*HH + (size_t)(b0+e)*HH + j;
            g_hdbfHi[o] = hi;
            g_hdbfLo[o] = lo;
        }
    } else {
#pragma unroll
        for (int e = 0; e < 4; e++) {
            float hd = (gmv * (hh[e] - mu) * rs + btv) * mkP[(b0+e)*HH + j];
            g_Hout[((size_t)t*BB + b0 + e)*HH + j] = hd;
        }
    }
}

// ---------------- loss: mean NLL over 6400 rows of 8000 logits --------------
__global__ void k_loss(const int* __restrict__ x, float* out) {
    int r = blockIdx.x;
    int t = r >> 6, b = r & 63;
    const float* row = &g_logits[(size_t)r * VV];
    int tid = threadIdx.x;
    float m = -INFINITY, s = 0.f;
    for (int v = tid; v < VV; v += 256) {
        float xv = row[v];
        if (xv > m) { s = s * expf(m - xv) + 1.f; m = xv; }
        else s += expf(xv - m);
    }
    __shared__ float sm[256], ss[256];
    sm[tid] = m; ss[tid] = s;
    __syncthreads();
    for (int o = 128; o; o >>= 1) {
        if (tid < o) {
            float m2 = sm[tid + o], s2 = ss[tid + o];
            float mm = fmaxf(sm[tid], m2);
            ss[tid] = ss[tid] * expf(sm[tid] - mm) + s2 * expf(m2 - mm);
            sm[tid] = mm;
        }
        __syncthreads();
    }
    if (tid == 0) {
        int tgt = x[b*TT + t + 1];
        float lse = sm[0] + logf(ss[0]);
        atomicAdd(out, (lse - row[tgt]) * (1.f / MM));
    }
}

// ---------------- transpose [t*64+b][v] -> out[b][v][t] ---------------------
__global__ void k_transpose(float* __restrict__ outLogits) {
    int b = blockIdx.x;
    int v0 = blockIdx.y * 32;
    __shared__ float tile[32 * 101];
    int tid = threadIdx.x;
    for (int idx = tid; idx < 3200; idx += 256) {
        int t = idx >> 5, vi = idx & 31;
        tile[vi*101 + t] = g_logits[(size_t)(t*BB + b)*VV + v0 + vi];
    }
    __syncthreads();
    for (int idx = tid; idx < 3200; idx += 256) {
        int vi = idx / 100, t = idx - vi*100;
        outLogits[(size_t)b*VV*TS + (size_t)(v0 + vi)*TS + t] = tile[vi*101 + t];
    }
}

// ---------------- launch ------------------------------------------------------
extern "C" void kernel_launch(void* const* d_in, const int* in_sizes, int n_in,
                              void* d_out, int out_size) {
    const int*   x   = (const int*)d_in[0];
    const float* emb = (const float*)d_in[1];
    const float* Wd  = (const float*)d_in[2];
    const float* bd  = (const float*)d_in[3];
    const float* Wih[3] = {(const float*)d_in[4],  (const float*)d_in[10], (const float*)d_in[16]};
    const float* Whh[3] = {(const float*)d_in[5],  (const float*)d_in[11], (const float*)d_in[17]};
    const float* bl[3]  = {(const float*)d_in[6],  (const float*)d_in[12], (const float*)d_in[18]};
    const float* gm[3]  = {(const float*)d_in[7],  (const float*)d_in[13], (const float*)d_in[19]};
    const float* bt[3]  = {(const float*)d_in[8],  (const float*)d_in[14], (const float*)d_in[20]};
    const float* mk[3]  = {(const float*)d_in[9],  (const float*)d_in[15], (const float*)d_in[21]};

    float* out = (float*)d_out;
    int hasLoss = (out_size & 1) ? 1 : 0;
    float* outLogits = out + hasLoss;

    const int FUSED_SMEM = 61440;   // 2-stage W(hi/lo) + A(hi/lo)
    static int attrDone = 0;
    if (!attrDone) {
        cudaFuncSetAttribute(k_fused_wave, cudaFuncAttributeMaxDynamicSharedMemorySize,
                             FUSED_SMEM);
        attrDone = 1;
    }

    k_init<<<(3*HH*BB + 255)/256, 256>>>(out, hasLoss);
    k_wsplit<<<(6*GG*(HH/4) + 255)/256, 256>>>(Whh[0], Wih[1], Whh[1], Wih[2], Whh[2], Wih[0]);
    k_embed<<<(MM*(HH/4) + 255)/256, 256>>>(x, emb);
    k_xg1_tc<<<dim3(16, TS), 256>>>(bl[0]);

    for (int d = 0; d < TS + 2; d++) {
        int c0 = d + 1 < TS ? d + 1 : TS;                 // active diagonals layer 0
        int c1 = d >= 1 ? (d < TS ? d : TS) : 0;          // layer 1
        int c2 = d >= 2 ? (d - 1 < TS ? d - 1 : TS) : 0;  // layer 2
        unsigned tgt0 = 32u * (unsigned)c0;
        unsigned tgt1 = 64u * (unsigned)c1;
        unsigned tgt2 = 64u * (unsigned)c2;
        k_fused_wave<<<256, 256, FUSED_SMEM>>>(d, tgt0, tgt1, tgt2,
                                               bl[1], bl[2],
                                               gm[0], bt[0], mk[0],
                                               gm[1], bt[1], mk[1],
                                               gm[2], bt[2], mk[2]);
    }

    k_dec_tc<<<dim3((VV + 127)/128, MM/128), 256>>>(Wd, bd);
    if (hasLoss) k_loss<<<MM, 256>>>(x, out);
    k_transpose<<<dim3(BB, VV/32), 256>>>(outLogits);
}

// round 14
// speedup vs baseline: 3.2734x; 1.1087x over previous
#include <cuda_runtime.h>
#include <cuda_bf16.h>
#include <math.h>

#define BB 64
#define TT 101
#define TS 100
#define VV 8000
#define HH 512
#define GG 2048
#define MM (TS*BB)   // 6400
#define EPSN 1e-5f

typedef unsigned long long ull;

// ---------------- device scratch (static; no runtime allocation) -------------
__device__ float g_Xg1[(size_t)GG*MM];           // [t][n][b] e@Wih1^T + b1
__device__ float g_Hout[MM*HH];                  // [m][h] layer-3 output
__device__ float g_logits[(size_t)MM*VV];        // [m][v]
__device__ float g_part[(size_t)3*4*GG*BB];      // [layer][slice][n][b]
__device__ float g_c[3*HH*BB];                   // [layer][j][b] cell state
__device__ unsigned g_cnt[3];                    // cumulative gemm completions per layer
__device__ unsigned g_ccnt[3];                   // cumulative cell completions per layer
// bf16 split weights: 0:Whh1 1:Wih2 2:Whh2 3:Wih3 4:Whh3 5:Wih1, [slot][n][k]
__device__ __align__(16) __nv_bfloat16 g_WspHi[(size_t)6*GG*HH];
__device__ __align__(16) __nv_bfloat16 g_WspLo[(size_t)6*GG*HH];
// bf16 split activations, parity double-buffered: [parity][layer][b][k]
__device__ __align__(16) __nv_bfloat16 g_hbfHi[2*3*BB*HH];
__device__ __align__(16) __nv_bfloat16 g_hbfLo[2*3*BB*HH];
__device__ __align__(16) __nv_bfloat16 g_hdbfHi[2*2*BB*HH];
__device__ __align__(16) __nv_bfloat16 g_hdbfLo[2*2*BB*HH];
// bf16 split embeddings, [m][k]
__device__ __align__(16) __nv_bfloat16 g_ebfHi[(size_t)MM*HH];
__device__ __align__(16) __nv_bfloat16 g_ebfLo[(size_t)MM*HH];

// ---------------- helpers ------------------------------------------------------
__device__ __forceinline__ unsigned tf32c(float x) {
    unsigned u;
    asm("cvt.rna.tf32.f32 %0, %1;" : "=r"(u) : "f"(x));
    return u;
}
__device__ __forceinline__ void mma_tf32(float* c, const unsigned* a, const unsigned* b) {
    asm("mma.sync.aligned.m16n8k8.row.col.f32.tf32.tf32.f32 "
        "{%0,%1,%2,%3}, {%4,%5,%6,%7}, {%8,%9}, {%0,%1,%2,%3};"
        : "+f"(c[0]), "+f"(c[1]), "+f"(c[2]), "+f"(c[3])
        : "r"(a[0]), "r"(a[1]), "r"(a[2]), "r"(a[3]), "r"(b[0]), "r"(b[1]));
}
__device__ __forceinline__ void mma_bf16(float* c, const unsigned* a, const unsigned* b) {
    asm("mma.sync.aligned.m16n8k16.row.col.f32.bf16.bf16.f32 "
        "{%0,%1,%2,%3}, {%4,%5,%6,%7}, {%8,%9}, {%0,%1,%2,%3};"
        : "+f"(c[0]), "+f"(c[1]), "+f"(c[2]), "+f"(c[3])
        : "r"(a[0]), "r"(a[1]), "r"(a[2]), "r"(a[3]), "r"(b[0]), "r"(b[1]));
}
__device__ __forceinline__ void ldsm4(unsigned* r, unsigned addr) {
    asm volatile("ldmatrix.sync.aligned.m8n8.x4.shared.b16 {%0,%1,%2,%3}, [%4];"
                 : "=r"(r[0]), "=r"(r[1]), "=r"(r[2]), "=r"(r[3]) : "r"(addr));
}
__device__ __forceinline__ void bsplit(float x, __nv_bfloat16& hi, __nv_bfloat16& lo) {
    hi = __float2bfloat16(x);
    lo = __float2bfloat16(x - __bfloat162float(hi));
}
__device__ __forceinline__ void cpa16(unsigned dst, const void* src) {
    asm volatile("cp.async.ca.shared.global [%0], [%1], 16;" :: "r"(dst), "l"(src));
}
__device__ __forceinline__ void cpa16cg(unsigned dst, const void* src) {
    asm volatile("cp.async.cg.shared.global [%0], [%1], 16;" :: "r"(dst), "l"(src));
}
__device__ __forceinline__ void waitCnt(unsigned* addr, unsigned tgt) {
    unsigned v;
    while (true) {
        asm volatile("ld.acquire.gpu.u32 %0, [%1];" : "=r"(v) : "l"(addr) : "memory");
        if (v >= tgt) break;
        __nanosleep(32);
    }
}
__device__ __forceinline__ int iclamp(int x, int lo, int hi) {
    return x < lo ? lo : (x > hi ? hi : x);
}

// ---------------- init: zero states + counters + loss slot --------------------
__global__ void k_init(float* out, int hasLoss) {
    int i = blockIdx.x * blockDim.x + threadIdx.x;
    if (i < 3*HH*BB) g_c[i] = 0.f;
    if (i < 2*3*BB*HH) {
        g_hbfHi[i] = __float2bfloat16(0.f);
        g_hbfLo[i] = __float2bfloat16(0.f);
    }
    if (i < 3) { g_cnt[i] = 0u; g_ccnt[i] = 0u; }
    if (i == 0 && hasLoss) out[0] = 0.f;
}

// ---------------- weight pre-split (once): 6 matrices [2048][512] ------------
__global__ void k_wsplit(const float* __restrict__ Whh1,
                         const float* __restrict__ Wih2, const float* __restrict__ Whh2,
                         const float* __restrict__ Wih3, const float* __restrict__ Whh3,
                         const float* __restrict__ Wih1) {
    int i = blockIdx.x * blockDim.x + threadIdx.x;   // float4 index
    const int PER = GG * (HH/4);
    if (i >= 6 * PER) return;
    int slot = i / PER, rem = i - slot * PER;
    const float* M = slot == 0 ? Whh1 : slot == 1 ? Wih2 : slot == 2 ? Whh2
                   : slot == 3 ? Wih3 : slot == 4 ? Whh3 : Wih1;
    float4 v = ((const float4*)M)[rem];
    __nv_bfloat16 h0,l0,h1,l1,h2,l2,h3,l3;
    bsplit(v.x, h0, l0); bsplit(v.y, h1, l1);
    bsplit(v.z, h2, l2); bsplit(v.w, h3, l3);
    size_t o = (size_t)slot*GG*HH + (size_t)rem*4;
    *(__nv_bfloat162*)&g_WspHi[o]   = __nv_bfloat162(h0, h1);
    *(__nv_bfloat162*)&g_WspHi[o+2] = __nv_bfloat162(h2, h3);
    *(__nv_bfloat162*)&g_WspLo[o]   = __nv_bfloat162(l0, l1);
    *(__nv_bfloat162*)&g_WspLo[o+2] = __nv_bfloat162(l2, l3);
}

// ---------------- embedding gather + bf16 split -------------------------------
__global__ void k_embed(const int* x, const float* emb) {
    int i = blockIdx.x * blockDim.x + threadIdx.x;
    if (i >= MM * (HH/4)) return;
    int m  = i / (HH/4);
    int hq = i % (HH/4);
    int t = m / BB, b = m % BB;
    int tok = x[b*TT + t];
    float4 v = ((const float4*)emb)[(size_t)tok*(HH/4) + hq];
    __nv_bfloat16 h0,l0,h1,l1,h2,l2,h3,l3;
    bsplit(v.x, h0, l0); bsplit(v.y, h1, l1);
    bsplit(v.z, h2, l2); bsplit(v.w, h3, l3);
    size_t o = (size_t)m*HH + (size_t)hq*4;
    *(__nv_bfloat162*)&g_ebfHi[o]   = __nv_bfloat162(h0, h1);
    *(__nv_bfloat162*)&g_ebfHi[o+2] = __nv_bfloat162(h2, h3);
    *(__nv_bfloat162*)&g_ebfLo[o]   = __nv_bfloat162(l0, l1);
    *(__nv_bfloat162*)&g_ebfLo[o+2] = __nv_bfloat162(l2, l3);
}

// ---------------- Xg1 GEMM: bf16 split-3 tensor cores -------------------------
__global__ void __launch_bounds__(256) k_xg1_tc(const float* __restrict__ bias) {
    int t = blockIdx.y;
    int nb = blockIdx.x * 128;
    const __nv_bfloat16* wHi = g_WspHi + ((size_t)5*GG + nb)*HH;
    const __nv_bfloat16* wLo = g_WspLo + ((size_t)5*GG + nb)*HH;
    const __nv_bfloat16* aHi = g_ebfHi + (size_t)t*BB*HH;
    const __nv_bfloat16* aLo = g_ebfLo + (size_t)t*BB*HH;

    int tid = threadIdx.x;
    int lane = tid & 31, warp = tid >> 5;
    int mwarp = warp >> 1, bwarp = warp & 1;

    __shared__ __align__(16) __nv_bfloat16 sWhi[128*40];
    __shared__ __align__(16) __nv_bfloat16 sWlo[128*40];
    __shared__ __align__(16) __nv_bfloat16 sAhi[64*40];
    __shared__ __align__(16) __nv_bfloat16 sAlo[64*40];
    unsigned bWhi = (unsigned)__cvta_generic_to_shared(sWhi);
    unsigned bWlo = (unsigned)__cvta_generic_to_shared(sWlo);
    unsigned bAhi = (unsigned)__cvta_generic_to_shared(sAhi);
    unsigned bAlo = (unsigned)__cvta_generic_to_shared(sAlo);

    float acc[2][4][4];
#pragma unroll
    for (int mt = 0; mt < 2; mt++)
#pragma unroll
        for (int j = 0; j < 4; j++)
#pragma unroll
            for (int e = 0; e < 4; e++) acc[mt][j][e] = 0.f;

    int aRow = mwarp*32 + (lane & 15);
    int aColHalf = (lane >> 4) * 16;
    int bSel = lane >> 3, bL = lane & 7;
    int bRowOff = (bSel >> 1) * 8 + bL;
    int bColHalf = (bSel & 1) * 16;

    int wr0 = tid >> 1, wc0 = (tid & 1) * 2;
    int ar = tid >> 2, ac = tid & 3;

    for (int kc = 0; kc < HH; kc += 32) {
#pragma unroll
        for (int u = 0; u < 2; u++) {
            int r = wr0, c = wc0 + u;
            cpa16(bWhi + r*80 + c*16, wHi + (size_t)r*HH + kc + c*8);
            cpa16(bWlo + r*80 + c*16, wLo + (size_t)r*HH + kc + c*8);
        }
        cpa16(bAhi + ar*80 + ac*16, aHi + (size_t)ar*HH + kc + ac*8);
        cpa16(bAlo + ar*80 + ac*16, aLo + (size_t)ar*HH + kc + ac*8);
        asm volatile("cp.async.commit_group;");
        asm volatile("cp.async.wait_group 0;");
        __syncthreads();

#pragma unroll
        for (int kq = 0; kq < 2; kq++) {
            unsigned wa_h[2][4], wa_l[2][4];
#pragma unroll
            for (int mt = 0; mt < 2; mt++) {
                unsigned off = (unsigned)((aRow + mt*16)*80 + kq*32 + aColHalf);
                ldsm4(wa_h[mt], bWhi + off);
                ldsm4(wa_l[mt], bWlo + off);
            }
            unsigned hb_h[4][2], hb_l[4][2];
#pragma unroll
            for (int j2 = 0; j2 < 2; j2++) {
                unsigned off = (unsigned)((bwarp*32 + j2*16 + bRowOff)*80 + kq*32 + bColHalf);
                unsigned q[4];
                ldsm4(q, bAhi + off);
                hb_h[2*j2][0] = q[0]; hb_h[2*j2][1] = q[1];
                hb_h[2*j2+1][0] = q[2]; hb_h[2*j2+1][1] = q[3];
                ldsm4(q, bAlo + off);
                hb_l[2*j2][0] = q[0]; hb_l[2*j2][1] = q[1];
                hb_l[2*j2+1][0] = q[2]; hb_l[2*j2+1][1] = q[3];
            }
#pragma unroll
            for (int mt = 0; mt < 2; mt++)
#pragma unroll
                for (int j = 0; j < 4; j++) {
                    mma_bf16(acc[mt][j], wa_h[mt], hb_h[j]);
                    mma_bf16(acc[mt][j], wa_h[mt], hb_l[j]);
                    mma_bf16(acc[mt][j], wa_l[mt], hb_h[j]);
                }
        }
        __syncthreads();
    }

    float* P = g_Xg1 + (size_t)t*(GG*BB) + (size_t)nb*BB;
    int g = lane >> 2, tg = lane & 3;
#pragma unroll
    for (int mt = 0; mt < 2; mt++) {
        int n = mwarp*32 + mt*16 + g;
        float bb0 = bias[nb + n], bb1 = bias[nb + n + 8];
#pragma unroll
        for (int j = 0; j < 4; j++) {
            int b = bwarp*32 + j*8 + 2*tg;
            float2 v0; v0.x = acc[mt][j][0] + bb0; v0.y = acc[mt][j][1] + bb0;
            float2 v1; v1.x = acc[mt][j][2] + bb1; v1.y = acc[mt][j][3] + bb1;
            *(float2*)&P[(size_t)n*BB + b]       = v0;
            *(float2*)&P[(size_t)(n + 8)*BB + b] = v1;
        }
    }
}

// ---------------- decoder GEMM: TF32 tensor cores -----------------------------
__global__ void __launch_bounds__(256) k_dec_tc(const float* __restrict__ Wd,
                                                const float* __restrict__ bd) {
    __shared__ unsigned Ast[32*136];
    __shared__ unsigned Bst[32*136];
    int tid = threadIdx.x;
    int warp = tid >> 5, lane = tid & 31;
    int gid = lane >> 2, tig = lane & 3;
    int mBase = blockIdx.y * 128, nBase = blockIdx.x * 128;
    int wm = (warp >> 2) * 64, wn = (warp & 3) * 32;

    float c[4][4][4];
#pragma unroll
    for (int i = 0; i < 4; i++)
#pragma unroll
        for (int j = 0; j < 4; j++)
#pragma unroll
            for (int e = 0; e < 4; e++) c[i][j][e] = 0.f;

    int srow = tid & 127;
    int half = tid >> 7;
    int nIdx = nBase + srow;
    bool nOk = nIdx < VV;
    const float* aRow = &g_Hout[(size_t)(mBase + srow)*HH];
    const float* bRow = &Wd[(size_t)(nOk ? nIdx : 0)*HH];

    for (int kc = 0; kc < HH; kc += 32) {
        float4 av[4], bv[4];
#pragma unroll
        for (int i = 0; i < 4; i++) {
            av[i] = *(const float4*)&aRow[kc + half*16 + i*4];
            float4 b = *(const float4*)&bRow[kc + half*16 + i*4];
            if (!nOk) b = make_float4(0.f, 0.f, 0.f, 0.f);
            bv[i] = b;
        }
        __syncthreads();
#pragma unroll
        for (int i = 0; i < 4; i++) {
            int k = half*16 + i*4;
            Ast[(k+0)*136 + srow] = tf32c(av[i].x);
            Ast[(k+1)*136 + srow] = tf32c(av[i].y);
            Ast[(k+2)*136 + srow] = tf32c(av[i].z);
            Ast[(k+3)*136 + srow] = tf32c(av[i].w);
            Bst[(k+0)*136 + srow] = tf32c(bv[i].x);
            Bst[(k+1)*136 + srow] = tf32c(bv[i].y);
            Bst[(k+2)*136 + srow] = tf32c(bv[i].z);
            Bst[(k+3)*136 + srow] = tf32c(bv[i].w);
        }
        __syncthreads();
#pragma unroll
        for (int ks = 0; ks < 32; ks += 8) {
            unsigned a[4][4], b[4][2];
            int r0 = (ks + tig)*136, r1 = (ks + tig + 4)*136;
#pragma unroll
            for (int i = 0; i < 4; i++) {
                int mo = wm + i*16 + gid;
                a[i][0] = Ast[r0 + mo]; a[i][1] = Ast[r0 + mo + 8];
                a[i][2] = Ast[r1 + mo]; a[i][3] = Ast[r1 + mo + 8];
            }
#pragma unroll
            for (int j = 0; j < 4; j++) {
                int no = wn + j*8 + gid;
                b[j][0] = Bst[r0 + no];
                b[j][1] = Bst[r1 + no];
            }
#pragma unroll
            for (int i = 0; i < 4; i++)
#pragma unroll
                for (int j = 0; j < 4; j++)
                    mma_tf32(c[i][j], a[i], b[j]);
        }
    }

#pragma unroll
    for (int i = 0; i < 4; i++) {
        int r0 = mBase + wm + i*16 + gid;
#pragma unroll
        for (int j = 0; j < 4; j++) {
            int n = nBase + wn + j*8 + 2*tig;
            if (n < VV) {
                float2 bb = *(const float2*)&bd[n];
                float2 v0; v0.x = c[i][j][0] + bb.x; v0.y = c[i][j][1] + bb.y;
                float2 v1; v1.x = c[i][j][2] + bb.x; v1.y = c[i][j][3] + bb.y;
                *(float2*)&g_logits[(size_t)r0*VV + n]       = v0;
                *(float2*)&g_logits[(size_t)(r0 + 8)*VV + n] = v1;
            }
        }
    }
}

// ---------------- PERSISTENT wavefront: all 102 diagonals in ONE launch -------
// CTAs 0..159 = gemm role, 160..255 = cell role. Cross-diagonal ordering via
// cumulative release/acquire counters; activations parity double-buffered.
// RACE FIXES vs R13:
//  (1) Wih-slice gemm ALSO waits g_ccnt[l] (cell(d-1,l) must finish reading
//      g_part[l] before we overwrite it).
//  (2) cell of layers 0,1 ALSO waits g_cnt[l+1] (gemm(d-1,l+1) must finish
//      reading hd parity slot before we overwrite it).
__global__ void __launch_bounds__(256, 2) k_persist_wave(
    const float* __restrict__ b2, const float* __restrict__ b3,
    const float* __restrict__ gm0, const float* __restrict__ bt0, const float* __restrict__ mk0,
    const float* __restrict__ gm1, const float* __restrict__ bt1, const float* __restrict__ mk1,
    const float* __restrict__ gm2, const float* __restrict__ bt2, const float* __restrict__ mk2)
{
    extern __shared__ __align__(16) __nv_bfloat16 smemRaw[];
    int bx = blockIdx.x;
    int tid = threadIdx.x;

    if (bx < 160) {
        // =================== GEMM role ===================
        int ntile = bx & 15;
        int si = bx >> 4;
        int l, slice;
        if (si < 2)      { l = 0; slice = si; }
        else if (si < 6) { l = 1; slice = si - 2; }
        else             { l = 2; slice = si - 6; }

        int wslot, kOff;
        int useH;   // 1: reads g_hbf[l]; 0: reads g_hdbf[l-1]
        if (l == 0)          { wslot = 0;       kOff = slice * 256;       useH = 1; }
        else if (slice < 2)  { wslot = 2*l - 1; kOff = slice * 256;       useH = 0; }
        else                 { wslot = 2*l;     kOff = (slice - 2) * 256; useH = 1; }
        int nb = ntile * 128;
        const __nv_bfloat16* wHi = g_WspHi + ((size_t)wslot*GG + nb)*HH + kOff;
        const __nv_bfloat16* wLo = g_WspLo + ((size_t)wslot*GG + nb)*HH + kOff;

        __nv_bfloat16* sWhi = smemRaw;
        __nv_bfloat16* sWlo = smemRaw + 2*5120;
        __nv_bfloat16* sAhi = smemRaw + 4*5120;
        __nv_bfloat16* sAlo = smemRaw + 4*5120 + 2*2560;
        unsigned bWhi = (unsigned)__cvta_generic_to_shared(sWhi);
        unsigned bWlo = (unsigned)__cvta_generic_to_shared(sWlo);
        unsigned bAhi = (unsigned)__cvta_generic_to_shared(sAhi);
        unsigned bAlo = (unsigned)__cvta_generic_to_shared(sAlo);

        int lane = tid & 31, warp = tid >> 5;
        int mwarp = warp >> 1, bwarp = warp & 1;
        int aRow = mwarp*32 + (lane & 15);
        int aColHalf = (lane >> 4) * 16;
        int bSel = lane >> 3, bL = lane & 7;
        int bRowOff = (bSel >> 1) * 8 + bL;
        int bColHalf = (bSel & 1) * 16;
        int wr0 = tid >> 1, wc0 = (tid & 1) * 2;
        int ar = tid >> 2, ac = tid & 3;
        float* P = g_part + ((size_t)(l*4 + slice)*GG + nb)*BB;

        for (int d = l; d < l + TS; d++) {
            // ---- wait for producers of diagonal d-1 AND consumers of our g_part ----
            if (tid == 0) {
                if (useH) {
                    waitCnt(&g_ccnt[l],   32u * (unsigned)iclamp(d - l,     0, TS));
                } else {
                    waitCnt(&g_ccnt[l-1], 32u * (unsigned)iclamp(d - l + 1, 0, TS));
                    waitCnt(&g_ccnt[l],   32u * (unsigned)iclamp(d - l,     0, TS));
                }
            }
            __syncthreads();

            int pr = (d + 1) & 1;   // read parity = (d-1)&1
            const __nv_bfloat16 *aHi, *aLo;
            if (useH) {
                aHi = g_hbfHi + ((size_t)pr*3 + l)*BB*HH + kOff;
                aLo = g_hbfLo + ((size_t)pr*3 + l)*BB*HH + kOff;
            } else {
                aHi = g_hdbfHi + ((size_t)pr*2 + (l-1))*BB*HH + kOff;
                aLo = g_hdbfLo + ((size_t)pr*2 + (l-1))*BB*HH + kOff;
            }

            float acc[2][4][4];
#pragma unroll
            for (int mt = 0; mt < 2; mt++)
#pragma unroll
                for (int j = 0; j < 4; j++)
#pragma unroll
                    for (int e = 0; e < 4; e++) acc[mt][j][e] = 0.f;

            // prologue: stage chunk 0
            {
#pragma unroll
                for (int u = 0; u < 2; u++) {
                    int c = wc0 + u;
                    cpa16(bWhi + wr0*80 + c*16, wHi + (size_t)wr0*HH + c*8);
                    cpa16(bWlo + wr0*80 + c*16, wLo + (size_t)wr0*HH + c*8);
                }
                cpa16cg(bAhi + ar*80 + ac*16, aHi + (size_t)ar*HH + ac*8);
                cpa16cg(bAlo + ar*80 + ac*16, aLo + (size_t)ar*HH + ac*8);
                asm volatile("cp.async.commit_group;");
            }

            for (int ch = 0; ch < 8; ch++) {
                if (ch + 1 < 8) {
                    int kc = (ch + 1) * 32;
                    int st = (ch + 1) & 1;
                    unsigned oW = st * 10240u, oA = st * 5120u;
#pragma unroll
                    for (int u = 0; u < 2; u++) {
                        int c = wc0 + u;
                        cpa16(bWhi + oW + wr0*80 + c*16, wHi + (size_t)wr0*HH + kc + c*8);
                        cpa16(bWlo + oW + wr0*80 + c*16, wLo + (size_t)wr0*HH + kc + c*8);
                    }
                    cpa16cg(bAhi + oA + ar*80 + ac*16, aHi + (size_t)ar*HH + kc + ac*8);
                    cpa16cg(bAlo + oA + ar*80 + ac*16, aLo + (size_t)ar*HH + kc + ac*8);
                    asm volatile("cp.async.commit_group;");
                    asm volatile("cp.async.wait_group 1;");
                } else {
                    asm volatile("cp.async.wait_group 0;");
                }
                __syncthreads();

                int st = ch & 1;
                unsigned oW = st * 10240u, oA = st * 5120u;
#pragma unroll
                for (int kq = 0; kq < 2; kq++) {
                    unsigned wa_h[2][4], wa_l[2][4];
#pragma unroll
                    for (int mt = 0; mt < 2; mt++) {
                        unsigned off = (unsigned)((aRow + mt*16)*80 + kq*32 + aColHalf);
                        ldsm4(wa_h[mt], bWhi + oW + off);
                        ldsm4(wa_l[mt], bWlo + oW + off);
                    }
                    unsigned hb_h[4][2], hb_l[4][2];
#pragma unroll
                    for (int j2 = 0; j2 < 2; j2++) {
                        unsigned off = (unsigned)((bwarp*32 + j2*16 + bRowOff)*80 + kq*32 + bColHalf);
                        unsigned q[4];
                        ldsm4(q, bAhi + oA + off);
                        hb_h[2*j2][0] = q[0]; hb_h[2*j2][1] = q[1];
                        hb_h[2*j2+1][0] = q[2]; hb_h[2*j2+1][1] = q[3];
                        ldsm4(q, bAlo + oA + off);
                        hb_l[2*j2][0] = q[0]; hb_l[2*j2][1] = q[1];
                        hb_l[2*j2+1][0] = q[2]; hb_l[2*j2+1][1] = q[3];
                    }
#pragma unroll
                    for (int mt = 0; mt < 2; mt++)
#pragma unroll
                        for (int j = 0; j < 4; j++) {
                            mma_bf16(acc[mt][j], wa_h[mt], hb_h[j]);
                            mma_bf16(acc[mt][j], wa_h[mt], hb_l[j]);
                            mma_bf16(acc[mt][j], wa_l[mt], hb_h[j]);
                        }
                }
                __syncthreads();
            }

            int g = lane >> 2, tg = lane & 3;
#pragma unroll
            for (int mt = 0; mt < 2; mt++) {
                int n = mwarp*32 + mt*16 + g;
#pragma unroll
                for (int j = 0; j < 4; j++) {
                    int b = bwarp*32 + j*8 + 2*tg;
                    float2 v0; v0.x = acc[mt][j][0]; v0.y = acc[mt][j][1];
                    float2 v1; v1.x = acc[mt][j][2]; v1.y = acc[mt][j][3];
                    *(float2*)&P[(size_t)n*BB + b]       = v0;
                    *(float2*)&P[(size_t)(n + 8)*BB + b] = v1;
                }
            }
            __syncthreads();
            if (tid == 0)
                asm volatile("red.release.gpu.add.u32 [%0], 1;"
                             :: "l"(&g_cnt[l]) : "memory");
        }
        return;
    }

    // =================== CELL role ===================
    int idx = bx - 160;
    int l = idx >> 5, jt = idx & 31;
    int jl = tid >> 4, bq = tid & 15;
    int j = jt * 16 + jl;
    int b0 = bq * 4;
    const float* biasP = (l == 1) ? b2 : b3;
    const float* gmP = (l == 0) ? gm0 : (l == 1) ? gm1 : gm2;
    const float* btP = (l == 0) ? bt0 : (l == 1) ? bt1 : bt2;
    const float* mkP = (l == 0) ? mk0 : (l == 1) ? mk1 : mk2;
    unsigned per_l = (l == 0) ? 32u : 64u;
    float* cP = g_c + l*HH*BB + j*BB + b0;
    float mk4[4];
#pragma unroll
    for (int e = 0; e < 4; e++) mk4[e] = mkP[(b0+e)*HH + j];
    float gmv = gmP[j], btv = btP[j];

    for (int d = l; d < l + TS; d++) {
        int t = d - l;
        if (tid == 0) {
            waitCnt(&g_cnt[l], per_l * (unsigned)iclamp(d - l + 1, 0, TS));
            // hd overwrite guard: gemm(d-1, l+1) must have consumed this parity slot
            if (l < 2)
                waitCnt(&g_cnt[l+1], 64u * (unsigned)iclamp(d - l - 1, 0, TS));
        }
        __syncthreads();

        float ga[4][4];
#pragma unroll
        for (int g = 0; g < 4; g++) {
            int n = (g << 9) + j;
            float4 s;
            if (l == 0) {
                s = *(const float4*)&g_Xg1[(size_t)t*(GG*BB) + (size_t)n*BB + b0];
            } else {
                float bv = biasP[n];
                s = make_float4(bv, bv, bv, bv);
            }
            const float* pp = g_part + ((size_t)(l*4)*GG + n)*BB + b0;
            int nsl = (l == 0) ? 2 : 4;
            for (int sl = 0; sl < nsl; sl++) {
                float4 v = __ldcg((const float4*)(pp + (size_t)sl*(GG*BB)));
                s.x += v.x; s.y += v.y; s.z += v.z; s.w += v.w;
            }
            ga[g][0] = s.x; ga[g][1] = s.y; ga[g][2] = s.z; ga[g][3] = s.w;
        }

        float4 cprev = *(const float4*)cP;
        float cpv[4] = {cprev.x, cprev.y, cprev.z, cprev.w};
        float hh[4], ccv[4];
#pragma unroll
        for (int e = 0; e < 4; e++) {
            float iv = 1.f / (1.f + expf(-ga[0][e]));
            float fv = 1.f / (1.f + expf(-ga[1][e]));
            float gv = tanhf(ga[2][e]);
            float ov = 1.f / (1.f + expf(-ga[3][e]));
            float cc = fv * cpv[e] + iv * gv;
            ccv[e] = cc;
            hh[e] = ov * tanhf(cc);
        }
        *(float4*)cP = make_float4(ccv[0], ccv[1], ccv[2], ccv[3]);

        int pw = d & 1;
        {
            __nv_bfloat16 hi, lo;
#pragma unroll
            for (int e = 0; e < 4; e++) {
                bsplit(hh[e], hi, lo);
                size_t o = ((size_t)pw*3 + l)*BB*HH + (size_t)(b0+e)*HH + j;
                g_hbfHi[o] = hi;
                g_hbfLo[o] = lo;
            }
        }

        float sum = hh[0] + hh[1] + hh[2] + hh[3];
        float sq  = hh[0]*hh[0] + hh[1]*hh[1] + hh[2]*hh[2] + hh[3]*hh[3];
#pragma unroll
        for (int o = 8; o; o >>= 1) {
            sum += __shfl_down_sync(0xffffffffu, sum, o, 16);
            sq  += __shfl_down_sync(0xffffffffu, sq,  o, 16);
        }
        sum = __shfl_sync(0xffffffffu, sum, 0, 16);
        sq  = __shfl_sync(0xffffffffu, sq,  0, 16);
        float mu  = sum * (1.f / BB);
        float var = sq  * (1.f / BB) - mu * mu;
        float rs  = rsqrtf(var + EPSN);

        if (l < 2) {
            __nv_bfloat16 hi, lo;
#pragma unroll
            for (int e = 0; e < 4; e++) {
                float hd = (gmv * (hh[e] - mu) * rs + btv) * mk4[e];
                bsplit(hd, hi, lo);
                size_t o = ((size_t)pw*2 + l)*BB*HH + (size_t)(b0+e)*HH + j;
                g_hdbfHi[o] = hi;
                g_hdbfLo[o] = lo;
            }
        } else {
#pragma unroll
            for (int e = 0; e < 4; e++) {
                float hd = (gmv * (hh[e] - mu) * rs + btv) * mk4[e];
                g_Hout[((size_t)t*BB + b0 + e)*HH + j] = hd;
            }
        }
        __syncthreads();
        if (tid == 0)
            asm volatile("red.release.gpu.add.u32 [%0], 1;"
                         :: "l"(&g_ccnt[l]) : "memory");
    }
}

// ---------------- loss: mean NLL over 6400 rows of 8000 logits --------------
__global__ void k_loss(const int* __restrict__ x, float* out) {
    int r = blockIdx.x;
    int t = r >> 6, b = r & 63;
    const float* row = &g_logits[(size_t)r * VV];
    int tid = threadIdx.x;
    float m = -INFINITY, s = 0.f;
    for (int v = tid; v < VV; v += 256) {
        float xv = row[v];
        if (xv > m) { s = s * expf(m - xv) + 1.f; m = xv; }
        else s += expf(xv - m);
    }
    __shared__ float sm[256], ss[256];
    sm[tid] = m; ss[tid] = s;
    __syncthreads();
    for (int o = 128; o; o >>= 1) {
        if (tid < o) {
            float m2 = sm[tid + o], s2 = ss[tid + o];
            float mm = fmaxf(sm[tid], m2);
            ss[tid] = ss[tid] * expf(sm[tid] - mm) + s2 * expf(m2 - mm);
            sm[tid] = mm;
        }
        __syncthreads();
    }
    if (tid == 0) {
        int tgt = x[b*TT + t + 1];
        float lse = sm[0] + logf(ss[0]);
        atomicAdd(out, (lse - row[tgt]) * (1.f / MM));
    }
}

// ---------------- transpose [t*64+b][v] -> out[b][v][t] ---------------------
__global__ void k_transpose(float* __restrict__ outLogits) {
    int b = blockIdx.x;
    int v0 = blockIdx.y * 32;
    __shared__ float tile[32 * 101];
    int tid = threadIdx.x;
    for (int idx = tid; idx < 3200; idx += 256) {
        int t = idx >> 5, vi = idx & 31;
        tile[vi*101 + t] = g_logits[(size_t)(t*BB + b)*VV + v0 + vi];
    }
    __syncthreads();
    for (int idx = tid; idx < 3200; idx += 256) {
        int vi = idx / 100, t = idx - vi*100;
        outLogits[(size_t)b*VV*TS + (size_t)(v0 + vi)*TS + t] = tile[vi*101 + t];
    }
}

// ---------------- launch ------------------------------------------------------
extern "C" void kernel_launch(void* const* d_in, const int* in_sizes, int n_in,
                              void* d_out, int out_size) {
    const int*   x   = (const int*)d_in[0];
    const float* emb = (const float*)d_in[1];
    const float* Wd  = (const float*)d_in[2];
    const float* bd  = (const float*)d_in[3];
    const float* Wih[3] = {(const float*)d_in[4],  (const float*)d_in[10], (const float*)d_in[16]};
    const float* Whh[3] = {(const float*)d_in[5],  (const float*)d_in[11], (const float*)d_in[17]};
    const float* bl[3]  = {(const float*)d_in[6],  (const float*)d_in[12], (const float*)d_in[18]};
    const float* gm[3]  = {(const float*)d_in[7],  (const float*)d_in[13], (const float*)d_in[19]};
    const float* bt[3]  = {(const float*)d_in[8],  (const float*)d_in[14], (const float*)d_in[20]};
    const float* mk[3]  = {(const float*)d_in[9],  (const float*)d_in[15], (const float*)d_in[21]};

    float* out = (float*)d_out;
    int hasLoss = (out_size & 1) ? 1 : 0;
    float* outLogits = out + hasLoss;

    const int FUSED_SMEM = 61440;
    static int attrDone = 0;
    if (!attrDone) {
        cudaFuncSetAttribute(k_persist_wave, cudaFuncAttributeMaxDynamicSharedMemorySize,
                             FUSED_SMEM);
        attrDone = 1;
    }

    k_init<<<(2*3*HH*BB + 255)/256, 256>>>(out, hasLoss);
    k_wsplit<<<(6*GG*(HH/4) + 255)/256, 256>>>(Whh[0], Wih[1], Whh[1], Wih[2], Whh[2], Wih[0]);
    k_embed<<<(MM*(HH/4) + 255)/256, 256>>>(x, emb);
    k_xg1_tc<<<dim3(16, TS), 256>>>(bl[0]);

    k_persist_wave<<<256, 256, FUSED_SMEM>>>(bl[1], bl[2],
                                             gm[0], bt[0], mk[0],
                                             gm[1], bt[1], mk[1],
                                             gm[2], bt[2], mk[2]);

    k_dec_tc<<<dim3((VV + 127)/128, MM/128), 256>>>(Wd, bd);
    if (hasLoss) k_loss<<<MM, 256>>>(x, out);
    k_transpose<<<dim3(BB, VV/32), 256>>>(outLogits);
}

// round 16
// speedup vs baseline: 3.2977x; 1.0074x over previous
#include <cuda_runtime.h>
#include <cuda_bf16.h>
#include <math.h>

#define BB 64
#define TT 101
#define TS 100
#define VV 8000
#define HH 512
#define GG 2048
#define MM (TS*BB)   // 6400
#define EPSN 1e-5f

typedef unsigned long long ull;

// ---------------- device scratch (static; no runtime allocation) -------------
__device__ float g_Xg1[(size_t)GG*MM];           // [t][n][b] e@Wih1^T + b1
__device__ float g_Hout[MM*HH];                  // [m][h] layer-3 output
__device__ float g_logits[(size_t)MM*VV];        // [m][v]
__device__ float g_part[(size_t)2*3*4*GG*BB];    // [parity][layer][slice][n][b]
__device__ float g_c[3*HH*BB];                   // [layer][j][b] cell state
__device__ unsigned g_cnt[3];                    // cumulative gemm completions per layer
__device__ unsigned g_ccnt[3];                   // cumulative cell hd completions per layer
__device__ unsigned g_hcnt[3];                   // cumulative cell h completions (early)
// bf16 split weights: 0:Whh1 1:Wih2 2:Whh2 3:Wih3 4:Whh3 5:Wih1, [slot][n][k]
__device__ __align__(16) __nv_bfloat16 g_WspHi[(size_t)6*GG*HH];
__device__ __align__(16) __nv_bfloat16 g_WspLo[(size_t)6*GG*HH];
// bf16 split activations, parity double-buffered: [parity][layer][b][k]
__device__ __align__(16) __nv_bfloat16 g_hbfHi[2*3*BB*HH];
__device__ __align__(16) __nv_bfloat16 g_hbfLo[2*3*BB*HH];
__device__ __align__(16) __nv_bfloat16 g_hdbfHi[2*2*BB*HH];
__device__ __align__(16) __nv_bfloat16 g_hdbfLo[2*2*BB*HH];
// bf16 split embeddings, [m][k]
__device__ __align__(16) __nv_bfloat16 g_ebfHi[(size_t)MM*HH];
__device__ __align__(16) __nv_bfloat16 g_ebfLo[(size_t)MM*HH];

// ---------------- helpers ------------------------------------------------------
__device__ __forceinline__ unsigned tf32c(float x) {
    unsigned u;
    asm("cvt.rna.tf32.f32 %0, %1;" : "=r"(u) : "f"(x));
    return u;
}
__device__ __forceinline__ void mma_tf32(float* c, const unsigned* a, const unsigned* b) {
    asm("mma.sync.aligned.m16n8k8.row.col.f32.tf32.tf32.f32 "
        "{%0,%1,%2,%3}, {%4,%5,%6,%7}, {%8,%9}, {%0,%1,%2,%3};"
        : "+f"(c[0]), "+f"(c[1]), "+f"(c[2]), "+f"(c[3])
        : "r"(a[0]), "r"(a[1]), "r"(a[2]), "r"(a[3]), "r"(b[0]), "r"(b[1]));
}
__device__ __forceinline__ void mma_bf16(float* c, const unsigned* a, const unsigned* b) {
    asm("mma.sync.aligned.m16n8k16.row.col.f32.bf16.bf16.f32 "
        "{%0,%1,%2,%3}, {%4,%5,%6,%7}, {%8,%9}, {%0,%1,%2,%3};"
        : "+f"(c[0]), "+f"(c[1]), "+f"(c[2]), "+f"(c[3])
        : "r"(a[0]), "r"(a[1]), "r"(a[2]), "r"(a[3]), "r"(b[0]), "r"(b[1]));
}
__device__ __forceinline__ void ldsm4(unsigned* r, unsigned addr) {
    asm volatile("ldmatrix.sync.aligned.m8n8.x4.shared.b16 {%0,%1,%2,%3}, [%4];"
                 : "=r"(r[0]), "=r"(r[1]), "=r"(r[2]), "=r"(r[3]) : "r"(addr));
}
__device__ __forceinline__ void bsplit(float x, __nv_bfloat16& hi, __nv_bfloat16& lo) {
    hi = __float2bfloat16(x);
    lo = __float2bfloat16(x - __bfloat162float(hi));
}
__device__ __forceinline__ void cpa16(unsigned dst, const void* src) {
    asm volatile("cp.async.ca.shared.global [%0], [%1], 16;" :: "r"(dst), "l"(src));
}
__device__ __forceinline__ void cpa16cg(unsigned dst, const void* src) {
    asm volatile("cp.async.cg.shared.global [%0], [%1], 16;" :: "r"(dst), "l"(src));
}
__device__ __forceinline__ void waitCnt(unsigned* addr, unsigned tgt) {
    unsigned v;
    int spins = 0;
    while (true) {
        asm volatile("ld.acquire.gpu.u32 %0, [%1];" : "=r"(v) : "l"(addr) : "memory");
        if (v >= tgt) break;
        if (++spins > 64) __nanosleep(64);
    }
}
__device__ __forceinline__ int iclamp(int x, int lo, int hi) {
    return x < lo ? lo : (x > hi ? hi : x);
}
__device__ __forceinline__ float fsig(float x) {
    return 1.f / (1.f + __expf(-x));
}
__device__ __forceinline__ float ftanh(float x) {
    float xc = fminf(fmaxf(x, -15.f), 15.f);
    float e = __expf(2.f * xc);
    return __fdividef(e - 1.f, e + 1.f);
}

// ---------------- init: zero states + counters + loss slot --------------------
__global__ void k_init(float* out, int hasLoss) {
    int i = blockIdx.x * blockDim.x + threadIdx.x;
    if (i < 3*HH*BB) g_c[i] = 0.f;
    if (i < 2*3*BB*HH) {
        g_hbfHi[i] = __float2bfloat16(0.f);
        g_hbfLo[i] = __float2bfloat16(0.f);
    }
    if (i < 3) { g_cnt[i] = 0u; g_ccnt[i] = 0u; g_hcnt[i] = 0u; }
    if (i == 0 && hasLoss) out[0] = 0.f;
}

// ---------------- weight pre-split (once): 6 matrices [2048][512] ------------
__global__ void k_wsplit(const float* __restrict__ Whh1,
                         const float* __restrict__ Wih2, const float* __restrict__ Whh2,
                         const float* __restrict__ Wih3, const float* __restrict__ Whh3,
                         const float* __restrict__ Wih1) {
    int i = blockIdx.x * blockDim.x + threadIdx.x;   // float4 index
    const int PER = GG * (HH/4);
    if (i >= 6 * PER) return;
    int slot = i / PER, rem = i - slot * PER;
    const float* M = slot == 0 ? Whh1 : slot == 1 ? Wih2 : slot == 2 ? Whh2
                   : slot == 3 ? Wih3 : slot == 4 ? Whh3 : Wih1;
    float4 v = ((const float4*)M)[rem];
    __nv_bfloat16 h0,l0,h1,l1,h2,l2,h3,l3;
    bsplit(v.x, h0, l0); bsplit(v.y, h1, l1);
    bsplit(v.z, h2, l2); bsplit(v.w, h3, l3);
    size_t o = (size_t)slot*GG*HH + (size_t)rem*4;
    *(__nv_bfloat162*)&g_WspHi[o]   = __nv_bfloat162(h0, h1);
    *(__nv_bfloat162*)&g_WspHi[o+2] = __nv_bfloat162(h2, h3);
    *(__nv_bfloat162*)&g_WspLo[o]   = __nv_bfloat162(l0, l1);
    *(__nv_bfloat162*)&g_WspLo[o+2] = __nv_bfloat162(l2, l3);
}

// ---------------- embedding gather + bf16 split -------------------------------
__global__ void k_embed(const int* x, const float* emb) {
    int i = blockIdx.x * blockDim.x + threadIdx.x;
    if (i >= MM * (HH/4)) return;
    int m  = i / (HH/4);
    int hq = i % (HH/4);
    int t = m / BB, b = m % BB;
    int tok = x[b*TT + t];
    float4 v = ((const float4*)emb)[(size_t)tok*(HH/4) + hq];
    __nv_bfloat16 h0,l0,h1,l1,h2,l2,h3,l3;
    bsplit(v.x, h0, l0); bsplit(v.y, h1, l1);
    bsplit(v.z, h2, l2); bsplit(v.w, h3, l3);
    size_t o = (size_t)m*HH + (size_t)hq*4;
    *(__nv_bfloat162*)&g_ebfHi[o]   = __nv_bfloat162(h0, h1);
    *(__nv_bfloat162*)&g_ebfHi[o+2] = __nv_bfloat162(h2, h3);
    *(__nv_bfloat162*)&g_ebfLo[o]   = __nv_bfloat162(l0, l1);
    *(__nv_bfloat162*)&g_ebfLo[o+2] = __nv_bfloat162(l2, l3);
}

// ---------------- Xg1 GEMM: bf16 split-3 tensor cores -------------------------
__global__ void __launch_bounds__(256) k_xg1_tc(const float* __restrict__ bias) {
    int t = blockIdx.y;
    int nb = blockIdx.x * 128;
    const __nv_bfloat16* wHi = g_WspHi + ((size_t)5*GG + nb)*HH;
    const __nv_bfloat16* wLo = g_WspLo + ((size_t)5*GG + nb)*HH;
    const __nv_bfloat16* aHi = g_ebfHi + (size_t)t*BB*HH;
    const __nv_bfloat16* aLo = g_ebfLo + (size_t)t*BB*HH;

    int tid = threadIdx.x;
    int lane = tid & 31, warp = tid >> 5;
    int mwarp = warp >> 1, bwarp = warp & 1;

    __shared__ __align__(16) __nv_bfloat16 sWhi[128*40];
    __shared__ __align__(16) __nv_bfloat16 sWlo[128*40];
    __shared__ __align__(16) __nv_bfloat16 sAhi[64*40];
    __shared__ __align__(16) __nv_bfloat16 sAlo[64*40];
    unsigned bWhi = (unsigned)__cvta_generic_to_shared(sWhi);
    unsigned bWlo = (unsigned)__cvta_generic_to_shared(sWlo);
    unsigned bAhi = (unsigned)__cvta_generic_to_shared(sAhi);
    unsigned bAlo = (unsigned)__cvta_generic_to_shared(sAlo);

    float acc[2][4][4];
#pragma unroll
    for (int mt = 0; mt < 2; mt++)
#pragma unroll
        for (int j = 0; j < 4; j++)
#pragma unroll
            for (int e = 0; e < 4; e++) acc[mt][j][e] = 0.f;

    int aRow = mwarp*32 + (lane & 15);
    int aColHalf = (lane >> 4) * 16;
    int bSel = lane >> 3, bL = lane & 7;
    int bRowOff = (bSel >> 1) * 8 + bL;
    int bColHalf = (bSel & 1) * 16;

    int wr0 = tid >> 1, wc0 = (tid & 1) * 2;
    int ar = tid >> 2, ac = tid & 3;

    for (int kc = 0; kc < HH; kc += 32) {
#pragma unroll
        for (int u = 0; u < 2; u++) {
            int r = wr0, c = wc0 + u;
            cpa16(bWhi + r*80 + c*16, wHi + (size_t)r*HH + kc + c*8);
            cpa16(bWlo + r*80 + c*16, wLo + (size_t)r*HH + kc + c*8);
        }
        cpa16(bAhi + ar*80 + ac*16, aHi + (size_t)ar*HH + kc + ac*8);
        cpa16(bAlo + ar*80 + ac*16, aLo + (size_t)ar*HH + kc + ac*8);
        asm volatile("cp.async.commit_group;");
        asm volatile("cp.async.wait_group 0;");
        __syncthreads();

#pragma unroll
        for (int kq = 0; kq < 2; kq++) {
            unsigned wa_h[2][4], wa_l[2][4];
#pragma unroll
            for (int mt = 0; mt < 2; mt++) {
                unsigned off = (unsigned)((aRow + mt*16)*80 + kq*32 + aColHalf);
                ldsm4(wa_h[mt], bWhi + off);
                ldsm4(wa_l[mt], bWlo + off);
            }
            unsigned hb_h[4][2], hb_l[4][2];
#pragma unroll
            for (int j2 = 0; j2 < 2; j2++) {
                unsigned off = (unsigned)((bwarp*32 + j2*16 + bRowOff)*80 + kq*32 + bColHalf);
                unsigned q[4];
                ldsm4(q, bAhi + off);
                hb_h[2*j2][0] = q[0]; hb_h[2*j2][1] = q[1];
                hb_h[2*j2+1][0] = q[2]; hb_h[2*j2+1][1] = q[3];
                ldsm4(q, bAlo + off);
                hb_l[2*j2][0] = q[0]; hb_l[2*j2][1] = q[1];
                hb_l[2*j2+1][0] = q[2]; hb_l[2*j2+1][1] = q[3];
            }
#pragma unroll
            for (int mt = 0; mt < 2; mt++)
#pragma unroll
                for (int j = 0; j < 4; j++) {
                    mma_bf16(acc[mt][j], wa_h[mt], hb_h[j]);
                    mma_bf16(acc[mt][j], wa_h[mt], hb_l[j]);
                    mma_bf16(acc[mt][j], wa_l[mt], hb_h[j]);
                }
        }
        __syncthreads();
    }

    float* P = g_Xg1 + (size_t)t*(GG*BB) + (size_t)nb*BB;
    int g = lane >> 2, tg = lane & 3;
#pragma unroll
    for (int mt = 0; mt < 2; mt++) {
        int n = mwarp*32 + mt*16 + g;
        float bb0 = bias[nb + n], bb1 = bias[nb + n + 8];
#pragma unroll
        for (int j = 0; j < 4; j++) {
            int b = bwarp*32 + j*8 + 2*tg;
            float2 v0; v0.x = acc[mt][j][0] + bb0; v0.y = acc[mt][j][1] + bb0;
            float2 v1; v1.x = acc[mt][j][2] + bb1; v1.y = acc[mt][j][3] + bb1;
            *(float2*)&P[(size_t)n*BB + b]       = v0;
            *(float2*)&P[(size_t)(n + 8)*BB + b] = v1;
        }
    }
}

// ---------------- decoder GEMM: TF32 tensor cores -----------------------------
__global__ void __launch_bounds__(256) k_dec_tc(const float* __restrict__ Wd,
                                                const float* __restrict__ bd) {
    __shared__ unsigned Ast[32*136];
    __shared__ unsigned Bst[32*136];
    int tid = threadIdx.x;
    int warp = tid >> 5, lane = tid & 31;
    int gid = lane >> 2, tig = lane & 3;
    int mBase = blockIdx.y * 128, nBase = blockIdx.x * 128;
    int wm = (warp >> 2) * 64, wn = (warp & 3) * 32;

    float c[4][4][4];
#pragma unroll
    for (int i = 0; i < 4; i++)
#pragma unroll
        for (int j = 0; j < 4; j++)
#pragma unroll
            for (int e = 0; e < 4; e++) c[i][j][e] = 0.f;

    int srow = tid & 127;
    int half = tid >> 7;
    int nIdx = nBase + srow;
    bool nOk = nIdx < VV;
    const float* aRow = &g_Hout[(size_t)(mBase + srow)*HH];
    const float* bRow = &Wd[(size_t)(nOk ? nIdx : 0)*HH];

    for (int kc = 0; kc < HH; kc += 32) {
        float4 av[4], bv[4];
#pragma unroll
        for (int i = 0; i < 4; i++) {
            av[i] = *(const float4*)&aRow[kc + half*16 + i*4];
            float4 b = *(const float4*)&bRow[kc + half*16 + i*4];
            if (!nOk) b = make_float4(0.f, 0.f, 0.f, 0.f);
            bv[i] = b;
        }
        __syncthreads();
#pragma unroll
        for (int i = 0; i < 4; i++) {
            int k = half*16 + i*4;
            Ast[(k+0)*136 + srow] = tf32c(av[i].x);
            Ast[(k+1)*136 + srow] = tf32c(av[i].y);
            Ast[(k+2)*136 + srow] = tf32c(av[i].z);
            Ast[(k+3)*136 + srow] = tf32c(av[i].w);
            Bst[(k+0)*136 + srow] = tf32c(bv[i].x);
            Bst[(k+1)*136 + srow] = tf32c(bv[i].y);
            Bst[(k+2)*136 + srow] = tf32c(bv[i].z);
            Bst[(k+3)*136 + srow] = tf32c(bv[i].w);
        }
        __syncthreads();
#pragma unroll
        for (int ks = 0; ks < 32; ks += 8) {
            unsigned a[4][4], b[4][2];
            int r0 = (ks + tig)*136, r1 = (ks + tig + 4)*136;
#pragma unroll
            for (int i = 0; i < 4; i++) {
                int mo = wm + i*16 + gid;
                a[i][0] = Ast[r0 + mo]; a[i][1] = Ast[r0 + mo + 8];
                a[i][2] = Ast[r1 + mo]; a[i][3] = Ast[r1 + mo + 8];
            }
#pragma unroll
            for (int j = 0; j < 4; j++) {
                int no = wn + j*8 + gid;
                b[j][0] = Bst[r0 + no];
                b[j][1] = Bst[r1 + no];
            }
#pragma unroll
            for (int i = 0; i < 4; i++)
#pragma unroll
                for (int j = 0; j < 4; j++)
                    mma_tf32(c[i][j], a[i], b[j]);
        }
    }

#pragma unroll
    for (int i = 0; i < 4; i++) {
        int r0 = mBase + wm + i*16 + gid;
#pragma unroll
        for (int j = 0; j < 4; j++) {
            int n = nBase + wn + j*8 + 2*tig;
            if (n < VV) {
                float2 bb = *(const float2*)&bd[n];
                float2 v0; v0.x = c[i][j][0] + bb.x; v0.y = c[i][j][1] + bb.y;
                float2 v1; v1.x = c[i][j][2] + bb.x; v1.y = c[i][j][3] + bb.y;
                *(float2*)&g_logits[(size_t)r0*VV + n]       = v0;
                *(float2*)&g_logits[(size_t)(r0 + 8)*VV + n] = v1;
            }
        }
    }
}

// ---------------- PERSISTENT wavefront: all 102 diagonals in ONE launch -------
// CTAs 0..159 = gemm role, 160..255 = cell role.
// COUNTER-SKEW FIXES vs R15 (both restore the "no CTA > k ahead" invariant):
//  (1) Wih gemms use the SAME hcnt gate as Whh (hcnt[l] >= d-l), so all layer-l
//      gemm CTAs advance in lockstep and g_cnt[l]=64k <=> diagonal k complete.
//  (2) cell hd guard raised to g_cnt[l+1] >= 64*(d-l) (gemm(d-1,l+1) fully
//      done), so no cell can complete hd iter k+1 before ccnt's waiter at k.
__global__ void __launch_bounds__(256, 2) k_persist_wave(
    const float* __restrict__ b2, const float* __restrict__ b3,
    const float* __restrict__ gm0, const float* __restrict__ bt0, const float* __restrict__ mk0,
    const float* __restrict__ gm1, const float* __restrict__ bt1, const float* __restrict__ mk1,
    const float* __restrict__ gm2, const float* __restrict__ bt2, const float* __restrict__ mk2)
{
    extern __shared__ __align__(16) __nv_bfloat16 smemRaw[];
    int bx = blockIdx.x;
    int tid = threadIdx.x;

    if (bx < 160) {
        // =================== GEMM role ===================
        int ntile = bx & 15;
        int si = bx >> 4;
        int l, slice;
        if (si < 2)      { l = 0; slice = si; }
        else if (si < 6) { l = 1; slice = si - 2; }
        else             { l = 2; slice = si - 6; }

        int wslot, kOff;
        int useH;   // 1: reads g_hbf[l]; 0: reads g_hdbf[l-1]
        if (l == 0)          { wslot = 0;       kOff = slice * 256;       useH = 1; }
        else if (slice < 2)  { wslot = 2*l - 1; kOff = slice * 256;       useH = 0; }
        else                 { wslot = 2*l;     kOff = (slice - 2) * 256; useH = 1; }
        int nb = ntile * 128;
        const __nv_bfloat16* wHi = g_WspHi + ((size_t)wslot*GG + nb)*HH + kOff;
        const __nv_bfloat16* wLo = g_WspLo + ((size_t)wslot*GG + nb)*HH + kOff;

        __nv_bfloat16* sWhi = smemRaw;
        __nv_bfloat16* sWlo = smemRaw + 2*5120;
        __nv_bfloat16* sAhi = smemRaw + 4*5120;
        __nv_bfloat16* sAlo = smemRaw + 4*5120 + 2*2560;
        unsigned bWhi = (unsigned)__cvta_generic_to_shared(sWhi);
        unsigned bWlo = (unsigned)__cvta_generic_to_shared(sWlo);
        unsigned bAhi = (unsigned)__cvta_generic_to_shared(sAhi);
        unsigned bAlo = (unsigned)__cvta_generic_to_shared(sAlo);

        int lane = tid & 31, warp = tid >> 5;
        int mwarp = warp >> 1, bwarp = warp & 1;
        int aRow = mwarp*32 + (lane & 15);
        int aColHalf = (lane >> 4) * 16;
        int bSel = lane >> 3, bL = lane & 7;
        int bRowOff = (bSel >> 1) * 8 + bL;
        int bColHalf = (bSel & 1) * 16;
        int wr0 = tid >> 1, wc0 = (tid & 1) * 2;
        int ar = tid >> 2, ac = tid & 3;

        for (int d = l; d < l + TS; d++) {
            // ---- waits: activation producers + lockstep guard ----
            if (tid == 0) {
                if (useH) {
                    waitCnt(&g_hcnt[l], 32u * (unsigned)iclamp(d - l, 0, TS));
                } else {
                    waitCnt(&g_ccnt[l-1], 32u * (unsigned)iclamp(d - l + 1, 0, TS));
                    // FIXED: same gate as Whh -> layer-l gemm CTAs stay in lockstep
                    waitCnt(&g_hcnt[l],   32u * (unsigned)iclamp(d - l, 0, TS));
                }
            }
            __syncthreads();

            int pr = (d + 1) & 1;   // read parity = (d-1)&1
            const __nv_bfloat16 *aHi, *aLo;
            if (useH) {
                aHi = g_hbfHi + ((size_t)pr*3 + l)*BB*HH + kOff;
                aLo = g_hbfLo + ((size_t)pr*3 + l)*BB*HH + kOff;
            } else {
                aHi = g_hdbfHi + ((size_t)pr*2 + (l-1))*BB*HH + kOff;
                aLo = g_hdbfLo + ((size_t)pr*2 + (l-1))*BB*HH + kOff;
            }

            float acc[2][4][4];
#pragma unroll
            for (int mt = 0; mt < 2; mt++)
#pragma unroll
                for (int j = 0; j < 4; j++)
#pragma unroll
                    for (int e = 0; e < 4; e++) acc[mt][j][e] = 0.f;

            // prologue: stage chunk 0
            {
#pragma unroll
                for (int u = 0; u < 2; u++) {
                    int c = wc0 + u;
                    cpa16(bWhi + wr0*80 + c*16, wHi + (size_t)wr0*HH + c*8);
                    cpa16(bWlo + wr0*80 + c*16, wLo + (size_t)wr0*HH + c*8);
                }
                cpa16cg(bAhi + ar*80 + ac*16, aHi + (size_t)ar*HH + ac*8);
                cpa16cg(bAlo + ar*80 + ac*16, aLo + (size_t)ar*HH + ac*8);
                asm volatile("cp.async.commit_group;");
            }

            for (int ch = 0; ch < 8; ch++) {
                if (ch + 1 < 8) {
                    int kc = (ch + 1) * 32;
                    int st = (ch + 1) & 1;
                    unsigned oW = st * 10240u, oA = st * 5120u;
#pragma unroll
                    for (int u = 0; u < 2; u++) {
                        int c = wc0 + u;
                        cpa16(bWhi + oW + wr0*80 + c*16, wHi + (size_t)wr0*HH + kc + c*8);
                        cpa16(bWlo + oW + wr0*80 + c*16, wLo + (size_t)wr0*HH + kc + c*8);
                    }
                    cpa16cg(bAhi + oA + ar*80 + ac*16, aHi + (size_t)ar*HH + kc + ac*8);
                    cpa16cg(bAlo + oA + ar*80 + ac*16, aLo + (size_t)ar*HH + kc + ac*8);
                    asm volatile("cp.async.commit_group;");
                    asm volatile("cp.async.wait_group 1;");
                } else {
                    asm volatile("cp.async.wait_group 0;");
                }
                __syncthreads();

                int st = ch & 1;
                unsigned oW = st * 10240u, oA = st * 5120u;
#pragma unroll
                for (int kq = 0; kq < 2; kq++) {
                    unsigned wa_h[2][4], wa_l[2][4];
#pragma unroll
                    for (int mt = 0; mt < 2; mt++) {
                        unsigned off = (unsigned)((aRow + mt*16)*80 + kq*32 + aColHalf);
                        ldsm4(wa_h[mt], bWhi + oW + off);
                        ldsm4(wa_l[mt], bWlo + oW + off);
                    }
                    unsigned hb_h[4][2], hb_l[4][2];
#pragma unroll
                    for (int j2 = 0; j2 < 2; j2++) {
                        unsigned off = (unsigned)((bwarp*32 + j2*16 + bRowOff)*80 + kq*32 + bColHalf);
                        unsigned q[4];
                        ldsm4(q, bAhi + oA + off);
                        hb_h[2*j2][0] = q[0]; hb_h[2*j2][1] = q[1];
                        hb_h[2*j2+1][0] = q[2]; hb_h[2*j2+1][1] = q[3];
                        ldsm4(q, bAlo + oA + off);
                        hb_l[2*j2][0] = q[0]; hb_l[2*j2][1] = q[1];
                        hb_l[2*j2+1][0] = q[2]; hb_l[2*j2+1][1] = q[3];
                    }
#pragma unroll
                    for (int mt = 0; mt < 2; mt++)
#pragma unroll
                        for (int j = 0; j < 4; j++) {
                            mma_bf16(acc[mt][j], wa_h[mt], hb_h[j]);
                            mma_bf16(acc[mt][j], wa_h[mt], hb_l[j]);
                            mma_bf16(acc[mt][j], wa_l[mt], hb_h[j]);
                        }
                }
                __syncthreads();
            }

            // partial store: parity-buffered
            float* P = g_part + ((size_t)((d & 1)*12 + l*4 + slice)*GG + nb)*BB;
            int g = lane >> 2, tg = lane & 3;
#pragma unroll
            for (int mt = 0; mt < 2; mt++) {
                int n = mwarp*32 + mt*16 + g;
#pragma unroll
                for (int j = 0; j < 4; j++) {
                    int b = bwarp*32 + j*8 + 2*tg;
                    float2 v0; v0.x = acc[mt][j][0]; v0.y = acc[mt][j][1];
                    float2 v1; v1.x = acc[mt][j][2]; v1.y = acc[mt][j][3];
                    *(float2*)&P[(size_t)n*BB + b]       = v0;
                    *(float2*)&P[(size_t)(n + 8)*BB + b] = v1;
                }
            }
            __syncthreads();
            if (tid == 0)
                asm volatile("red.release.gpu.add.u32 [%0], 1;"
                             :: "l"(&g_cnt[l]) : "memory");
        }
        return;
    }

    // =================== CELL role ===================
    int idx = bx - 160;
    int l = idx >> 5, jt = idx & 31;
    int jl = tid >> 4, bq = tid & 15;
    int j = jt * 16 + jl;
    int b0 = bq * 4;
    const float* biasP = (l == 1) ? b2 : b3;
    const float* gmP = (l == 0) ? gm0 : (l == 1) ? gm1 : gm2;
    const float* btP = (l == 0) ? bt0 : (l == 1) ? bt1 : bt2;
    const float* mkP = (l == 0) ? mk0 : (l == 1) ? mk1 : mk2;
    unsigned per_l = (l == 0) ? 32u : 64u;
    float* cP = g_c + l*HH*BB + j*BB + b0;
    float mk4[4];
#pragma unroll
    for (int e = 0; e < 4; e++) mk4[e] = mkP[(b0+e)*HH + j];
    float gmv = gmP[j], btv = btP[j];
    float bias4[4];
#pragma unroll
    for (int g = 0; g < 4; g++) bias4[g] = (l == 0) ? 0.f : biasP[(g << 9) + j];

    for (int d = l; d < l + TS; d++) {
        int t = d - l;
        if (tid == 0)
            waitCnt(&g_cnt[l], per_l * (unsigned)iclamp(d - l + 1, 0, TS));
        __syncthreads();

        float ga[4][4];
#pragma unroll
        for (int g = 0; g < 4; g++) {
            int n = (g << 9) + j;
            float4 s;
            if (l == 0) {
                s = *(const float4*)&g_Xg1[(size_t)t*(GG*BB) + (size_t)n*BB + b0];
            } else {
                float bv = bias4[g];
                s = make_float4(bv, bv, bv, bv);
            }
            const float* pp = g_part + ((size_t)((d & 1)*12 + l*4)*GG + n)*BB + b0;
            int nsl = (l == 0) ? 2 : 4;
            for (int sl = 0; sl < nsl; sl++) {
                float4 v = __ldcg((const float4*)(pp + (size_t)sl*(GG*BB)));
                s.x += v.x; s.y += v.y; s.z += v.z; s.w += v.w;
            }
            ga[g][0] = s.x; ga[g][1] = s.y; ga[g][2] = s.z; ga[g][3] = s.w;
        }

        float4 cprev = *(const float4*)cP;
        float cpv[4] = {cprev.x, cprev.y, cprev.z, cprev.w};
        float hh[4], ccv[4];
#pragma unroll
        for (int e = 0; e < 4; e++) {
            float iv = fsig(ga[0][e]);
            float fv = fsig(ga[1][e]);
            float gv = ftanh(ga[2][e]);
            float ov = fsig(ga[3][e]);
            float cc = fv * cpv[e] + iv * gv;
            ccv[e] = cc;
            hh[e] = ov * ftanh(cc);
        }
        *(float4*)cP = make_float4(ccv[0], ccv[1], ccv[2], ccv[3]);

        int pw = d & 1;
        {
            __nv_bfloat16 hi, lo;
#pragma unroll
            for (int e = 0; e < 4; e++) {
                bsplit(hh[e], hi, lo);
                size_t o = ((size_t)pw*3 + l)*BB*HH + (size_t)(b0+e)*HH + j;
                g_hbfHi[o] = hi;
                g_hbfLo[o] = lo;
            }
        }
        // ---- EARLY h release: unblocks next diagonal's layer-l gemms ----
        __syncthreads();
        if (tid == 0)
            asm volatile("red.release.gpu.add.u32 [%0], 1;"
                         :: "l"(&g_hcnt[l]) : "memory");

        float sum = hh[0] + hh[1] + hh[2] + hh[3];
        float sq  = hh[0]*hh[0] + hh[1]*hh[1] + hh[2]*hh[2] + hh[3]*hh[3];
#pragma unroll
        for (int o = 8; o; o >>= 1) {
            sum += __shfl_down_sync(0xffffffffu, sum, o, 16);
            sq  += __shfl_down_sync(0xffffffffu, sq,  o, 16);
        }
        sum = __shfl_sync(0xffffffffu, sum, 0, 16);
        sq  = __shfl_sync(0xffffffffu, sq,  0, 16);
        float mu  = sum * (1.f / BB);
        float var = sq  * (1.f / BB) - mu * mu;
        float rs  = rsqrtf(var + EPSN);

        if (l < 2) {
            // FIXED: wait gemm(d-1, l+1) FULLY done (64*(d-l)) before hd write.
            // Keeps ccnt's bounded-ahead invariant AND guards the parity slot.
            if (tid == 0)
                waitCnt(&g_cnt[l+1], 64u * (unsigned)iclamp(d - l, 0, TS));
            __syncthreads();
            __nv_bfloat16 hi, lo;
#pragma unroll
            for (int e = 0; e < 4; e++) {
                float hd = (gmv * (hh[e] - mu) * rs + btv) * mk4[e];
                bsplit(hd, hi, lo);
                size_t o = ((size_t)pw*2 + l)*BB*HH + (size_t)(b0+e)*HH + j;
                g_hdbfHi[o] = hi;
                g_hdbfLo[o] = lo;
            }
            __syncthreads();
            if (tid == 0)
                asm volatile("red.release.gpu.add.u32 [%0], 1;"
                             :: "l"(&g_ccnt[l]) : "memory");
        } else {
#pragma unroll
            for (int e = 0; e < 4; e++) {
                float hd = (gmv * (hh[e] - mu) * rs + btv) * mk4[e];
                g_Hout[((size_t)t*BB + b0 + e)*HH + j] = hd;
            }
        }
    }
}

// ---------------- loss: mean NLL over 6400 rows of 8000 logits --------------
__global__ void k_loss(const int* __restrict__ x, float* out) {
    int r = blockIdx.x;
    int t = r >> 6, b = r & 63;
    const float* row = &g_logits[(size_t)r * VV];
    int tid = threadIdx.x;
    float m = -INFINITY, s = 0.f;
    for (int v = tid; v < VV; v += 256) {
        float xv = row[v];
        if (xv > m) { s = s * expf(m - xv) + 1.f; m = xv; }
        else s += expf(xv - m);
    }
    __shared__ float sm[256], ss[256];
    sm[tid] = m; ss[tid] = s;
    __syncthreads();
    for (int o = 128; o; o >>= 1) {
        if (tid < o) {
            float m2 = sm[tid + o], s2 = ss[tid + o];
            float mm = fmaxf(sm[tid], m2);
            ss[tid] = ss[tid] * expf(sm[tid] - mm) + s2 * expf(m2 - mm);
            sm[tid] = mm;
        }
        __syncthreads();
    }
    if (tid == 0) {
        int tgt = x[b*TT + t + 1];
        float lse = sm[0] + logf(ss[0]);
        atomicAdd(out, (lse - row[tgt]) * (1.f / MM));
    }
}

// ---------------- transpose [t*64+b][v] -> out[b][v][t] ---------------------
__global__ void k_transpose(float* __restrict__ outLogits) {
    int b = blockIdx.x;
    int v0 = blockIdx.y * 32;
    __shared__ float tile[32 * 101];
    int tid = threadIdx.x;
    for (int idx = tid; idx < 3200; idx += 256) {
        int t = idx >> 5, vi = idx & 31;
        tile[vi*101 + t] = g_logits[(size_t)(t*BB + b)*VV + v0 + vi];
    }
    __syncthreads();
    for (int idx = tid; idx < 3200; idx += 256) {
        int vi = idx / 100, t = idx - vi*100;
        outLogits[(size_t)b*VV*TS + (size_t)(v0 + vi)*TS + t] = tile[vi*101 + t];
    }
}

// ---------------- launch ------------------------------------------------------
extern "C" void kernel_launch(void* const* d_in, const int* in_sizes, int n_in,
                              void* d_out, int out_size) {
    const int*   x   = (const int*)d_in[0];
    const float* emb = (const float*)d_in[1];
    const float* Wd  = (const float*)d_in[2];
    const float* bd  = (const float*)d_in[3];
    const float* Wih[3] = {(const float*)d_in[4],  (const float*)d_in[10], (const float*)d_in[16]};
    const float* Whh[3] = {(const float*)d_in[5],  (const float*)d_in[11], (const float*)d_in[17]};
    const float* bl[3]  = {(const float*)d_in[6],  (const float*)d_in[12], (const float*)d_in[18]};
    const float* gm[3]  = {(const float*)d_in[7],  (const float*)d_in[13], (const float*)d_in[19]};
    const float* bt[3]  = {(const float*)d_in[8],  (const float*)d_in[14], (const float*)d_in[20]};
    const float* mk[3]  = {(const float*)d_in[9],  (const float*)d_in[15], (const float*)d_in[21]};

    float* out = (float*)d_out;
    int hasLoss = (out_size & 1) ? 1 : 0;
    float* outLogits = out + hasLoss;

    const int FUSED_SMEM = 61440;
    static int attrDone = 0;
    if (!attrDone) {
        cudaFuncSetAttribute(k_persist_wave, cudaFuncAttributeMaxDynamicSharedMemorySize,
                             FUSED_SMEM);
        attrDone = 1;
    }

    k_init<<<(2*3*HH*BB + 255)/256, 256>>>(out, hasLoss);
    k_wsplit<<<(6*GG*(HH/4) + 255)/256, 256>>>(Whh[0], Wih[1], Whh[1], Wih[2], Whh[2], Wih[0]);
    k_embed<<<(MM*(HH/4) + 255)/256, 256>>>(x, emb);
    k_xg1_tc<<<dim3(16, TS), 256>>>(bl[0]);

    k_persist_wave<<<256, 256, FUSED_SMEM>>>(bl[1], bl[2],
                                             gm[0], bt[0], mk[0],
                                             gm[1], bt[1], mk[1],
                                             gm[2], bt[2], mk[2]);

    k_dec_tc<<<dim3((VV + 127)/128, MM/128), 256>>>(Wd, bd);
    if (hasLoss) k_loss<<<MM, 256>>>(x, out);
    k_transpose<<<dim3(BB, VV/32), 256>>>(outLogits);
}